// round 7
// baseline (speedup 1.0000x reference)
#include <cuda_runtime.h>
#include <cuda_fp16.h>
#include <math.h>
#include <stdint.h>

// ---------------- problem constants ----------------
#define BB      16
#define PP      2048
#define DD      512
#define HH      8
#define CC      64
#define HD_     64
#define MM      (BB * PP)        // 32768
#define FFNIN   1024
#define FFNHID  4096

// ---------------- scratch (device globals; allocation-free) ----------------
__device__ __align__(256) float g_q[MM * DD];
__device__ __align__(256) float g_aff[BB * HH * CC * PP];
__device__ __align__(256) float g_p2c[BB * HH * CC * PP];
__device__ __align__(256) float g_vcore[BB * HH * CC * HD_];
__device__ __align__(256) float g_outp[MM * DD];

__device__ __align__(256) __half g_in_h[MM * DD];
__device__ __align__(256) __half g_ffn_h[MM * FFNIN];
__device__ __align__(256) __half g_hid_h[(size_t)MM * FFNHID];
// weights transposed to [N][K] fp16
__device__ __align__(256) __half g_wvT[DD * DD];
__device__ __align__(256) __half g_w1T[FFNHID * FFNIN];
__device__ __align__(256) __half g_w2T[DD * FFNHID];

// ---------------- PTX helpers (sm_80-era instructions only) ----------------
__device__ __forceinline__ uint32_t smem_u32(const void* p) {
    uint32_t a;
    asm("{ .reg .u64 t; cvta.to.shared.u64 t, %1; cvt.u32.u64 %0, t; }" : "=r"(a) : "l"(p));
    return a;
}
__device__ __forceinline__ void cp16(uint32_t s, const void* g) {
    asm volatile("cp.async.cg.shared.global [%0], [%1], 16;" :: "r"(s), "l"(g));
}
__device__ __forceinline__ void ldm_x4(uint32_t* r, uint32_t addr) {
    asm volatile("ldmatrix.sync.aligned.m8n8.x4.shared.b16 {%0,%1,%2,%3}, [%4];"
                 : "=r"(r[0]), "=r"(r[1]), "=r"(r[2]), "=r"(r[3]) : "r"(addr));
}
__device__ __forceinline__ void mma_f16(float* d, const uint32_t* a, const uint32_t* b) {
    asm volatile(
        "mma.sync.aligned.m16n8k16.row.col.f32.f16.f16.f32 "
        "{%0,%1,%2,%3}, {%4,%5,%6,%7}, {%8,%9}, {%0,%1,%2,%3};"
        : "+f"(d[0]), "+f"(d[1]), "+f"(d[2]), "+f"(d[3])
        : "r"(a[0]), "r"(a[1]), "r"(a[2]), "r"(a[3]), "r"(b[0]), "r"(b[1]));
}

__device__ __forceinline__ float gelu_exact(float x) {
    return 0.5f * x * (1.0f + erff(x * 0.7071067811865476f));
}

// ---------------- fp16 GEMM via mma.sync, BM=128 BN=256 BK=64, 3-stage ----------------
// C = Ah @ Bh^T  with fp32 accumulate
// EPI 0: Cf = D + bias                       (fp32 out)
// EPI 1: Ch = half(gelu(D + bias))           (fp16 out)
// EPI 2: Cf = D + bias + resid               (fp32 out)
#define BKK       64
#define RSTRIDE   72                          // fp16 elements per smem row (64 + 8 pad)
#define A_TILE_B  (128 * RSTRIDE * 2)         // 18432
#define B_TILE_B  (256 * RSTRIDE * 2)         // 36864
#define STAGE_B   (A_TILE_B + B_TILE_B)       // 55296
#define NSTAGE    3
#define GEMM_SMEM (NSTAGE * STAGE_B)          // 165888

template <int EPI>
__global__ void __launch_bounds__(256, 1) gemm_mma(
    const __half* __restrict__ Ah, const __half* __restrict__ Bh,
    const float* __restrict__ bias, const float* __restrict__ resid,
    float* __restrict__ Cf, __half* __restrict__ Ch,
    int N, int K)
{
    extern __shared__ __align__(256) char smem[];
    const uint32_t sb = smem_u32(smem);

    const int tid = threadIdx.x;
    const int wid = tid >> 5;
    const int lane = tid & 31;
    const int bm = blockIdx.y * 128;
    const int bn = blockIdx.x * 256;
    const int mOff = (wid & 1) * 64;      // 2 m-warps
    const int nOff = (wid >> 1) * 64;     // 4 n-warps

    // per-thread ldmatrix source row/col selectors
    const int aRow = lane & 15;
    const int aCol = (lane >> 4) * 8;
    const int bRow = (lane & 7) + ((lane >> 4) << 3);
    const int bCol = ((lane >> 3) & 1) * 8;

    float acc[4][8][4];
    #pragma unroll
    for (int i = 0; i < 4; ++i)
        #pragma unroll
        for (int j = 0; j < 8; ++j)
            #pragma unroll
            for (int k = 0; k < 4; ++k) acc[i][j][k] = 0.0f;

    const int nch = K / BKK;

    // stage loader: A = 4 chunks/thread, B = 8 chunks/thread (16B each)
    auto loadStage = [&](int s, int it) {
        const int k0 = it * BKK;
        const uint32_t st = sb + s * STAGE_B;
        #pragma unroll
        for (int i = 0; i < 4; ++i) {
            const int id = tid + i * 256;
            const int r = id >> 3, c = id & 7;
            cp16(st + (uint32_t)(r * (RSTRIDE * 2) + c * 16),
                 Ah + (size_t)(bm + r) * K + k0 + c * 8);
        }
        #pragma unroll
        for (int i = 0; i < 8; ++i) {
            const int id = tid + i * 256;
            const int r = id >> 3, c = id & 7;
            cp16(st + A_TILE_B + (uint32_t)(r * (RSTRIDE * 2) + c * 16),
                 Bh + (size_t)(bn + r) * K + k0 + c * 8);
        }
        asm volatile("cp.async.commit_group;" ::: "memory");
    };

    loadStage(0, 0);
    loadStage(1, 1);

    for (int it = 0; it < nch; ++it) {
        if (it + 1 < nch)
            asm volatile("cp.async.wait_group 1;" ::: "memory");
        else
            asm volatile("cp.async.wait_group 0;" ::: "memory");
        __syncthreads();

        if (it + 2 < nch) loadStage((it + 2) % NSTAGE, it + 2);

        const uint32_t st = sb + (it % NSTAGE) * STAGE_B;
        const uint32_t pA = st, pB = st + A_TILE_B;

        #pragma unroll
        for (int kk = 0; kk < 4; ++kk) {
            uint32_t ah[4][4], b[4][4];
            #pragma unroll
            for (int mf = 0; mf < 4; ++mf)
                ldm_x4(ah[mf], pA +
                    (uint32_t)(((mOff + mf * 16 + aRow) * RSTRIDE + kk * 16 + aCol) * 2));
            #pragma unroll
            for (int n2 = 0; n2 < 4; ++n2)
                ldm_x4(b[n2], pB +
                    (uint32_t)(((nOff + n2 * 16 + bRow) * RSTRIDE + kk * 16 + bCol) * 2));
            #pragma unroll
            for (int mf = 0; mf < 4; ++mf)
                #pragma unroll
                for (int nf = 0; nf < 8; ++nf)
                    mma_f16(acc[mf][nf], ah[mf], &b[nf >> 1][(nf & 1) * 2]);
        }
    }

    // ---- epilogue ----
    #pragma unroll
    for (int mf = 0; mf < 4; ++mf) {
        #pragma unroll
        for (int half_ = 0; half_ < 2; ++half_) {
            const int row = bm + mOff + mf * 16 + (lane >> 2) + half_ * 8;
            #pragma unroll
            for (int nf = 0; nf < 8; ++nf) {
                const int col = bn + nOff + nf * 8 + (lane & 3) * 2;
                float v0 = acc[mf][nf][half_ * 2 + 0] + bias[col];
                float v1 = acc[mf][nf][half_ * 2 + 1] + bias[col + 1];
                if (EPI == 1) {
                    v0 = gelu_exact(v0);
                    v1 = gelu_exact(v1);
                    __half h0 = __float2half_rn(v0);
                    __half h1 = __float2half_rn(v1);
                    uint32_t hp = (uint32_t)__half_as_ushort(h0) |
                                  ((uint32_t)__half_as_ushort(h1) << 16);
                    *reinterpret_cast<uint32_t*>(Ch + (size_t)row * N + col) = hp;
                } else {
                    if (EPI == 2) {
                        const float* rp = resid + (size_t)row * N + col;
                        v0 += rp[0];
                        v1 += rp[1];
                    }
                    *reinterpret_cast<float2*>(Cf + (size_t)row * N + col) = make_float2(v0, v1);
                }
            }
        }
    }
}

// ---------------- fp32 -> fp16 convert (elementwise) ----------------
__global__ void __launch_bounds__(256) cvt_kernel(
    const float* __restrict__ x, __half* __restrict__ h, int n4)
{
    int i = blockIdx.x * 256 + threadIdx.x;
    if (i >= n4) return;
    float4 v = reinterpret_cast<const float4*>(x)[i];
    __half hb[4] = {__float2half_rn(v.x), __float2half_rn(v.y),
                    __float2half_rn(v.z), __float2half_rn(v.w)};
    reinterpret_cast<uint2*>(h)[i] = *reinterpret_cast<const uint2*>(hb);
}

// ---------------- W[K][N] fp32 -> Wt[N][K] fp16 ----------------
__global__ void __launch_bounds__(256) transpose_h(
    const float* __restrict__ W, __half* __restrict__ Th, int K, int N)
{
    __shared__ float s[32][33];
    const int n0 = blockIdx.x * 32, k0 = blockIdx.y * 32;
    const int c = threadIdx.x & 31, r0 = threadIdx.x >> 5;
    #pragma unroll
    for (int r = r0; r < 32; r += 8)
        s[r][c] = W[(size_t)(k0 + r) * N + n0 + c];
    __syncthreads();
    #pragma unroll
    for (int r = r0; r < 32; r += 8)
        Th[(size_t)(n0 + r) * K + k0 + c] = __float2half_rn(s[c][r]);
}

// ---------------- block reduce helpers ----------------
__device__ __forceinline__ float blockReduceMax(float v) {
    __shared__ float sm[8];
    #pragma unroll
    for (int o = 16; o > 0; o >>= 1) v = fmaxf(v, __shfl_xor_sync(0xffffffffu, v, o));
    int wid = threadIdx.x >> 5, nw = blockDim.x >> 5;
    if ((threadIdx.x & 31) == 0) sm[wid] = v;
    __syncthreads();
    float r = -1e30f;
    for (int i = 0; i < nw; ++i) r = fmaxf(r, sm[i]);
    __syncthreads();
    return r;
}
__device__ __forceinline__ float blockReduceSum(float v) {
    __shared__ float sm[8];
    #pragma unroll
    for (int o = 16; o > 0; o >>= 1) v += __shfl_xor_sync(0xffffffffu, v, o);
    int wid = threadIdx.x >> 5, nw = blockDim.x >> 5;
    if ((threadIdx.x & 31) == 0) sm[wid] = v;
    __syncthreads();
    float r = 0.0f;
    for (int i = 0; i < nw; ++i) r += sm[i];
    __syncthreads();
    return r;
}
__device__ __forceinline__ void blockReduceSum2(float& a, float& b) {
    __shared__ float sa[8], sb[8];
    #pragma unroll
    for (int o = 16; o > 0; o >>= 1) {
        a += __shfl_xor_sync(0xffffffffu, a, o);
        b += __shfl_xor_sync(0xffffffffu, b, o);
    }
    int wid = threadIdx.x >> 5, nw = blockDim.x >> 5;
    if ((threadIdx.x & 31) == 0) { sa[wid] = a; sb[wid] = b; }
    __syncthreads();
    float ra = 0.0f, rb = 0.0f;
    for (int i = 0; i < nw; ++i) { ra += sa[i]; rb += sb[i]; }
    __syncthreads();
    a = ra; b = rb;
}

// ---------------- aff + fused softmax-over-cores ----------------
// aff[b,h,c,p] = (1/8) * sum_d cores[h,c,d] * q[b,p,h*64+d]
// Each 64x64 tile spans the FULL core dim (C=64): softmax over c is a
// 16-lane shfl reduction. Writes raw aff (for c2p) AND normalized p2c.
__global__ void __launch_bounds__(256) aff_kernel(
    const float* __restrict__ q, const float* __restrict__ cores,
    float* __restrict__ aff, float* __restrict__ p2c)
{
    __shared__ float cs[64][65];
    __shared__ float qs[64][65];
    const int b = blockIdx.z, h = blockIdx.y, p0 = blockIdx.x * 64;
    const int tid = threadIdx.x;
    const int lr = tid >> 2;
    const int lc = (tid & 3) * 16;
    #pragma unroll
    for (int u = 0; u < 4; ++u) {
        float4 cv = *reinterpret_cast<const float4*>(cores + (size_t)(h * CC + lr) * HD_ + lc + u * 4);
        cs[lr][lc + u * 4 + 0] = cv.x; cs[lr][lc + u * 4 + 1] = cv.y;
        cs[lr][lc + u * 4 + 2] = cv.z; cs[lr][lc + u * 4 + 3] = cv.w;
        float4 qv = *reinterpret_cast<const float4*>(q + (size_t)(b * PP + p0 + lr) * DD + h * HD_ + lc + u * 4);
        qs[lr][lc + u * 4 + 0] = qv.x; qs[lr][lc + u * 4 + 1] = qv.y;
        qs[lr][lc + u * 4 + 2] = qv.z; qs[lr][lc + u * 4 + 3] = qv.w;
    }
    __syncthreads();
    const int c0 = (tid & 15) * 4;      // c-group = lane & 15
    const int pq = (tid >> 4) * 4;
    float acc[4][4];
    #pragma unroll
    for (int i = 0; i < 4; ++i)
        #pragma unroll
        for (int j = 0; j < 4; ++j) acc[i][j] = 0.0f;
    #pragma unroll 8
    for (int k = 0; k < 64; ++k) {
        float cr[4], pr[4];
        #pragma unroll
        for (int i = 0; i < 4; ++i) cr[i] = cs[c0 + i][k];
        #pragma unroll
        for (int j = 0; j < 4; ++j) pr[j] = qs[pq + j][k];
        #pragma unroll
        for (int i = 0; i < 4; ++i)
            #pragma unroll
            for (int j = 0; j < 4; ++j) acc[i][j] = fmaf(cr[i], pr[j], acc[i][j]);
    }
    #pragma unroll
    for (int i = 0; i < 4; ++i)
        #pragma unroll
        for (int j = 0; j < 4; ++j) acc[i][j] *= 0.125f;

    // softmax over c (full 64): reduce across the 16 lanes sharing this p-group
    float e[4][4], inv[4];
    #pragma unroll
    for (int j = 0; j < 4; ++j) {
        float m = fmaxf(fmaxf(acc[0][j], acc[1][j]), fmaxf(acc[2][j], acc[3][j]));
        #pragma unroll
        for (int o = 1; o < 16; o <<= 1) m = fmaxf(m, __shfl_xor_sync(0xffffffffu, m, o));
        float s = 0.0f;
        #pragma unroll
        for (int i = 0; i < 4; ++i) { e[i][j] = __expf(acc[i][j] - m); s += e[i][j]; }
        #pragma unroll
        for (int o = 1; o < 16; o <<= 1) s += __shfl_xor_sync(0xffffffffu, s, o);
        inv[j] = 1.0f / s;
    }

    const size_t base = ((size_t)(b * HH + h) * CC) * PP;
    #pragma unroll
    for (int i = 0; i < 4; ++i) {
        const size_t off = base + (size_t)(c0 + i) * PP + p0 + pq;
        *reinterpret_cast<float4*>(aff + off) =
            make_float4(acc[i][0], acc[i][1], acc[i][2], acc[i][3]);
        *reinterpret_cast<float4*>(p2c + off) =
            make_float4(e[i][0] * inv[0], e[i][1] * inv[1], e[i][2] * inv[2], e[i][3] * inv[3]);
    }
}

// ---------------- softmax over patches (in-place) ----------------
__global__ void __launch_bounds__(256) c2p_softmax(float* __restrict__ a)
{
    float* row = a + (size_t)blockIdx.x * PP;
    const int t = threadIdx.x;
    float x[8];
    *reinterpret_cast<float4*>(x)     = *reinterpret_cast<const float4*>(row + t * 8);
    *reinterpret_cast<float4*>(x + 4) = *reinterpret_cast<const float4*>(row + t * 8 + 4);
    float m = -1e30f;
    #pragma unroll
    for (int i = 0; i < 8; ++i) m = fmaxf(m, x[i]);
    m = blockReduceMax(m);
    float s = 0.0f;
    #pragma unroll
    for (int i = 0; i < 8; ++i) { x[i] = __expf(x[i] - m); s += x[i]; }
    s = blockReduceSum(s);
    const float inv = 1.0f / s;
    #pragma unroll
    for (int i = 0; i < 8; ++i) x[i] *= inv;
    *reinterpret_cast<float4*>(row + t * 8)     = *reinterpret_cast<float4*>(x);
    *reinterpret_cast<float4*>(row + t * 8 + 4) = *reinterpret_cast<float4*>(x + 4);
}

// ---------------- v_core ----------------
__global__ void __launch_bounds__(256) vcore_kernel(
    const float* __restrict__ input, const float* __restrict__ c2p, float* __restrict__ vcore)
{
    __shared__ float asT[64][68];
    __shared__ float vs[64][68];
    const int h = blockIdx.x, b = blockIdx.y;
    const int bh = b * HH + h;
    const float* abase = c2p + (size_t)bh * CC * PP;
    const int tid = threadIdx.x;
    const int lr = tid >> 2;
    const int lc = (tid & 3) * 16;
    const int c0 = (tid & 15) * 4;
    const int d0 = (tid >> 4) * 4;
    float acc[4][4];
    #pragma unroll
    for (int i = 0; i < 4; ++i)
        #pragma unroll
        for (int j = 0; j < 4; ++j) acc[i][j] = 0.0f;

    for (int pt = 0; pt < PP; pt += 64) {
        #pragma unroll
        for (int u = 0; u < 4; ++u) {
            float4 av = *reinterpret_cast<const float4*>(abase + (size_t)lr * PP + pt + lc + u * 4);
            asT[lc + u * 4 + 0][lr] = av.x; asT[lc + u * 4 + 1][lr] = av.y;
            asT[lc + u * 4 + 2][lr] = av.z; asT[lc + u * 4 + 3][lr] = av.w;
            float4 vv = *reinterpret_cast<const float4*>(input + (size_t)(b * PP + pt + lr) * DD + h * HD_ + lc + u * 4);
            *reinterpret_cast<float4*>(&vs[lr][lc + u * 4]) = vv;
        }
        __syncthreads();
        #pragma unroll 16
        for (int k = 0; k < 64; ++k) {
            float4 ar = *reinterpret_cast<const float4*>(&asT[k][c0]);
            float4 vr = *reinterpret_cast<const float4*>(&vs[k][d0]);
            float arr[4] = {ar.x, ar.y, ar.z, ar.w};
            float vrr[4] = {vr.x, vr.y, vr.z, vr.w};
            #pragma unroll
            for (int i = 0; i < 4; ++i)
                #pragma unroll
                for (int j = 0; j < 4; ++j) acc[i][j] = fmaf(arr[i], vrr[j], acc[i][j]);
        }
        __syncthreads();
    }
    #pragma unroll
    for (int i = 0; i < 4; ++i) {
        float4 o = make_float4(acc[i][0], acc[i][1], acc[i][2], acc[i][3]);
        *reinterpret_cast<float4*>(vcore + (size_t)(bh * CC + c0 + i) * HD_ + d0) = o;
    }
}

// ---------------- v_patch + ffn_in concat (writes fp16) ----------------
__device__ __forceinline__ void cvt_store4(__half* ph, float4 v) {
    __half hb[4] = {__float2half_rn(v.x), __float2half_rn(v.y),
                    __float2half_rn(v.z), __float2half_rn(v.w)};
    *reinterpret_cast<uint2*>(ph) = *reinterpret_cast<const uint2*>(hb);
}

__global__ void __launch_bounds__(256) vpatch_ffn_kernel(
    const float* __restrict__ input, const float* __restrict__ vcore,
    const float* __restrict__ p2c, __half* __restrict__ fh)
{
    __shared__ float vc[64][65];
    __shared__ float ap[64][65];
    const int b = blockIdx.z, h = blockIdx.y, p0 = blockIdx.x * 64;
    const int bh = b * HH + h;
    const int tid = threadIdx.x;
    const int lr = tid >> 2;
    const int lc = (tid & 3) * 16;
    #pragma unroll
    for (int u = 0; u < 4; ++u) {
        float4 cv = *reinterpret_cast<const float4*>(vcore + (size_t)(bh * CC + lr) * HD_ + lc + u * 4);
        vc[lr][lc + u * 4 + 0] = cv.x; vc[lr][lc + u * 4 + 1] = cv.y;
        vc[lr][lc + u * 4 + 2] = cv.z; vc[lr][lc + u * 4 + 3] = cv.w;
        float4 av = *reinterpret_cast<const float4*>(p2c + ((size_t)(bh * CC + lr)) * PP + p0 + lc + u * 4);
        ap[lr][lc + u * 4 + 0] = av.x; ap[lr][lc + u * 4 + 1] = av.y;
        ap[lr][lc + u * 4 + 2] = av.z; ap[lr][lc + u * 4 + 3] = av.w;
    }
    __syncthreads();
    const int pq = (tid >> 4) * 4;
    const int d0 = (tid & 15) * 4;
    float acc[4][4];
    #pragma unroll
    for (int i = 0; i < 4; ++i)
        #pragma unroll
        for (int j = 0; j < 4; ++j) acc[i][j] = 0.0f;
    #pragma unroll 8
    for (int k = 0; k < 64; ++k) {
        float apr[4], vcr[4];
        #pragma unroll
        for (int i = 0; i < 4; ++i) apr[i] = ap[k][pq + i];
        #pragma unroll
        for (int j = 0; j < 4; ++j) vcr[j] = vc[k][d0 + j];
        #pragma unroll
        for (int i = 0; i < 4; ++i)
            #pragma unroll
            for (int j = 0; j < 4; ++j) acc[i][j] = fmaf(apr[i], vcr[j], acc[i][j]);
    }
    #pragma unroll
    for (int i = 0; i < 4; ++i) {
        const int gp = b * PP + p0 + pq + i;
        float4 inp = *reinterpret_cast<const float4*>(input + (size_t)gp * DD + h * HD_ + d0);
        float4 vp = make_float4(acc[i][0], acc[i][1], acc[i][2], acc[i][3]);
        float4 diff = make_float4(inp.x - vp.x, inp.y - vp.y, inp.z - vp.z, inp.w - vp.w);
        const size_t fo = (size_t)gp * FFNIN + h * HD_ + d0;
        cvt_store4(fh + fo, diff);
        cvt_store4(fh + fo + DD, vp);
    }
}

// ---------------- LayerNorm ----------------
__global__ void __launch_bounds__(128) ln_kernel(
    const float* __restrict__ x, const float* __restrict__ gamma,
    const float* __restrict__ beta, float* __restrict__ out)
{
    const float* row = x + (size_t)blockIdx.x * DD;
    const int t = threadIdx.x;
    float4 v = *reinterpret_cast<const float4*>(row + t * 4);
    float s = v.x + v.y + v.z + v.w;
    float sq = v.x * v.x + v.y * v.y + v.z * v.z + v.w * v.w;
    blockReduceSum2(s, sq);
    const float mu = s * (1.0f / DD);
    const float var = sq * (1.0f / DD) - mu * mu;
    const float rstd = rsqrtf(var + 1e-5f);
    float4 g = *reinterpret_cast<const float4*>(gamma + t * 4);
    float4 bt = *reinterpret_cast<const float4*>(beta + t * 4);
    float4 o;
    o.x = (v.x - mu) * rstd * g.x + bt.x;
    o.y = (v.y - mu) * rstd * g.y + bt.y;
    o.z = (v.z - mu) * rstd * g.z + bt.z;
    o.w = (v.w - mu) * rstd * g.w + bt.w;
    *reinterpret_cast<float4*>(out + (size_t)blockIdx.x * DD + t * 4) = o;
}

// ---------------- launch ----------------
extern "C" void kernel_launch(void* const* d_in, const int* in_sizes, int n_in,
                              void* d_out, int out_size)
{
    (void)in_sizes; (void)n_in; (void)out_size;
    const float* input = (const float*)d_in[0];
    const float* cores = (const float*)d_in[1];
    const float* Wv    = (const float*)d_in[2];
    const float* bv    = (const float*)d_in[3];
    const float* W1    = (const float*)d_in[4];
    const float* b1    = (const float*)d_in[5];
    const float* W2    = (const float*)d_in[6];
    const float* b2    = (const float*)d_in[7];
    const float* gamma = (const float*)d_in[8];
    const float* beta  = (const float*)d_in[9];
    float* out = (float*)d_out;

    float *q, *aff, *p2c, *vcore, *outp;
    __half *in_h, *ffn_h, *hid_h, *wvT, *w1T, *w2T;
    cudaGetSymbolAddress((void**)&q, g_q);
    cudaGetSymbolAddress((void**)&aff, g_aff);
    cudaGetSymbolAddress((void**)&p2c, g_p2c);
    cudaGetSymbolAddress((void**)&vcore, g_vcore);
    cudaGetSymbolAddress((void**)&outp, g_outp);
    cudaGetSymbolAddress((void**)&in_h, g_in_h);
    cudaGetSymbolAddress((void**)&ffn_h, g_ffn_h);
    cudaGetSymbolAddress((void**)&hid_h, g_hid_h);
    cudaGetSymbolAddress((void**)&wvT, g_wvT);
    cudaGetSymbolAddress((void**)&w1T, g_w1T);
    cudaGetSymbolAddress((void**)&w2T, g_w2T);

    cudaFuncSetAttribute(gemm_mma<0>, cudaFuncAttributeMaxDynamicSharedMemorySize, GEMM_SMEM);
    cudaFuncSetAttribute(gemm_mma<1>, cudaFuncAttributeMaxDynamicSharedMemorySize, GEMM_SMEM);
    cudaFuncSetAttribute(gemm_mma<2>, cudaFuncAttributeMaxDynamicSharedMemorySize, GEMM_SMEM);

    // prep: converts + weight transposes
    cvt_kernel<<<(MM * DD / 4 + 255) / 256, 256>>>(input, in_h, MM * DD / 4);
    transpose_h<<<dim3(DD / 32, DD / 32), 256>>>(Wv, wvT, DD, DD);
    transpose_h<<<dim3(FFNHID / 32, FFNIN / 32), 256>>>(W1, w1T, FFNIN, FFNHID);
    transpose_h<<<dim3(DD / 32, FFNHID / 32), 256>>>(W2, w2T, FFNHID, DD);

    // 1. q = input @ Wv + bv
    gemm_mma<0><<<dim3(DD / 256, MM / 128), 256, GEMM_SMEM>>>(
        in_h, wvT, bv, nullptr, q, nullptr, DD, DD);
    // 2-5. affinity (+fused p2c softmax) + c2p softmax + aggregate + redistribute
    aff_kernel<<<dim3(PP / 64, HH, BB), 256>>>(q, cores, aff, p2c);
    c2p_softmax<<<BB * HH * CC, 256>>>(aff);
    vcore_kernel<<<dim3(HH, BB), 256>>>(input, aff, vcore);
    vpatch_ffn_kernel<<<dim3(PP / 64, HH, BB), 256>>>(input, vcore, p2c, ffn_h);
    // 6. hid = gelu(ffn @ W1 + b1)   (fp16 out)
    gemm_mma<1><<<dim3(FFNHID / 256, MM / 128), 256, GEMM_SMEM>>>(
        ffn_h, w1T, b1, nullptr, nullptr, hid_h, FFNHID, FFNIN);
    // 7. outp = input + hid @ W2 + b2
    gemm_mma<2><<<dim3(DD / 256, MM / 128), 256, GEMM_SMEM>>>(
        hid_h, w2T, b2, input, outp, nullptr, DD, FFNHID);
    // 8. LayerNorm
    ln_kernel<<<MM, 128>>>(outp, gamma, beta, out);
}

// round 10
// speedup vs baseline: 1.0555x; 1.0555x over previous
#include <cuda_runtime.h>
#include <cuda_fp16.h>
#include <math.h>
#include <stdint.h>

// ---------------- problem constants ----------------
#define BB      16
#define PP      2048
#define DD      512
#define HH      8
#define CC      64
#define HD_     64
#define MM      (BB * PP)        // 32768
#define FFNIN   1024
#define FFNHID  4096

// ---------------- scratch (device globals; allocation-free) ----------------
__device__ __align__(256) float g_q[MM * DD];
__device__ __align__(256) float g_aff[BB * HH * CC * PP];
__device__ __align__(256) float g_p2c[BB * HH * CC * PP];
__device__ __align__(256) float g_vcore[BB * HH * CC * HD_];
__device__ __align__(256) float g_outp[MM * DD];

__device__ __align__(256) __half g_in_h[MM * DD];
__device__ __align__(256) __half g_ffn_h[MM * FFNIN];
__device__ __align__(256) __half g_hid_h[(size_t)MM * FFNHID];
// weights transposed to [N][K] fp16
__device__ __align__(256) __half g_wvT[DD * DD];
__device__ __align__(256) __half g_w1T[FFNHID * FFNIN];
__device__ __align__(256) __half g_w2T[DD * FFNHID];

// ---------------- PTX helpers (sm_80-era instructions only) ----------------
__device__ __forceinline__ uint32_t smem_u32(const void* p) {
    uint32_t a;
    asm("{ .reg .u64 t; cvta.to.shared.u64 t, %1; cvt.u32.u64 %0, t; }" : "=r"(a) : "l"(p));
    return a;
}
__device__ __forceinline__ void cp16(uint32_t s, const void* g) {
    asm volatile("cp.async.cg.shared.global [%0], [%1], 16;" :: "r"(s), "l"(g));
}
__device__ __forceinline__ void ldm_x4(uint32_t* r, uint32_t addr) {
    asm volatile("ldmatrix.sync.aligned.m8n8.x4.shared.b16 {%0,%1,%2,%3}, [%4];"
                 : "=r"(r[0]), "=r"(r[1]), "=r"(r[2]), "=r"(r[3]) : "r"(addr));
}
__device__ __forceinline__ void mma_f16(float* d, const uint32_t* a, const uint32_t* b) {
    asm volatile(
        "mma.sync.aligned.m16n8k16.row.col.f32.f16.f16.f32 "
        "{%0,%1,%2,%3}, {%4,%5,%6,%7}, {%8,%9}, {%0,%1,%2,%3};"
        : "+f"(d[0]), "+f"(d[1]), "+f"(d[2]), "+f"(d[3])
        : "r"(a[0]), "r"(a[1]), "r"(a[2]), "r"(a[3]), "r"(b[0]), "r"(b[1]));
}

__device__ __forceinline__ float gelu_exact(float x) {
    return 0.5f * x * (1.0f + erff(x * 0.7071067811865476f));
}

// ---------------- fp16 GEMM via mma.sync, BM=128 BN=128 BK=32, 3-stage ----------------
// C = Ah @ Bh^T  with fp32 accumulate
// EPI 0: Cf = D + bias                       (fp32 out)
// EPI 1: Ch = half(gelu(D + bias))           (fp16 out)
// EPI 2: Cf = D + bias + resid               (fp32 out)
#define BKK       32
#define RSTRIDE   40                        // fp16 elements per smem row (32 + 8 pad)
#define TILE_B    (128 * RSTRIDE * 2)       // 10240 bytes per matrix tile
#define STAGE_B   (2 * TILE_B)              // Ah, Bh = 20480
#define NSTAGE    3
#define GEMM_SMEM (NSTAGE * STAGE_B)        // 61440

template <int EPI>
__global__ void __launch_bounds__(256, 2) gemm_mma(
    const __half* __restrict__ Ah, const __half* __restrict__ Bh,
    const float* __restrict__ bias, const float* __restrict__ resid,
    float* __restrict__ Cf, __half* __restrict__ Ch,
    int N, int K)
{
    extern __shared__ __align__(256) char smem[];
    const uint32_t sb = smem_u32(smem);

    const int tid = threadIdx.x;
    const int wid = tid >> 5;
    const int lane = tid & 31;
    const int bm = blockIdx.y * 128;
    const int bn = blockIdx.x * 128;
    const int mOff = (wid & 3) * 32;
    const int nOff = (wid >> 2) * 64;

    // per-thread ldmatrix source row/col selectors
    const int aRow = lane & 15;
    const int aCol = (lane >> 4) * 8;
    const int bRow = (lane & 7) + ((lane >> 4) << 3);
    const int bCol = ((lane >> 3) & 1) * 8;

    float acc[2][8][4];
    #pragma unroll
    for (int i = 0; i < 2; ++i)
        #pragma unroll
        for (int j = 0; j < 8; ++j)
            #pragma unroll
            for (int k = 0; k < 4; ++k) acc[i][j][k] = 0.0f;

    const int nch = K / BKK;

    // stage loader: 2 chunks of 16B per thread per matrix (Ah, Bh)
    auto loadStage = [&](int s, int it) {
        const int k0 = it * BKK;
        const uint32_t st = sb + s * STAGE_B;
        #pragma unroll
        for (int i = 0; i < 2; ++i) {
            const int id = tid + i * 256;
            const int r = id >> 2, c = id & 3;
            const uint32_t so = (uint32_t)(r * (RSTRIDE * 2) + c * 16);
            cp16(st + so,          Ah + (size_t)(bm + r) * K + k0 + c * 8);
            cp16(st + TILE_B + so, Bh + (size_t)(bn + r) * K + k0 + c * 8);
        }
        asm volatile("cp.async.commit_group;" ::: "memory");
    };

    loadStage(0, 0);
    loadStage(1, 1);

    for (int it = 0; it < nch; ++it) {
        if (it + 1 < nch)
            asm volatile("cp.async.wait_group 1;" ::: "memory");
        else
            asm volatile("cp.async.wait_group 0;" ::: "memory");
        __syncthreads();

        // prefetch stage it+2 (distinct buffer from the one consumed now and the pending one)
        if (it + 2 < nch) loadStage((it + 2) % NSTAGE, it + 2);

        const uint32_t st = sb + (it % NSTAGE) * STAGE_B;
        const uint32_t pAh = st, pBh = st + TILE_B;

        #pragma unroll
        for (int kk = 0; kk < 2; ++kk) {
            uint32_t ah[2][4], b[4][4];
            #pragma unroll
            for (int mf = 0; mf < 2; ++mf)
                ldm_x4(ah[mf], pAh +
                    (uint32_t)(((mOff + mf * 16 + aRow) * RSTRIDE + kk * 16 + aCol) * 2));
            #pragma unroll
            for (int n2 = 0; n2 < 4; ++n2)
                ldm_x4(b[n2], pBh +
                    (uint32_t)(((nOff + n2 * 16 + bRow) * RSTRIDE + kk * 16 + bCol) * 2));
            #pragma unroll
            for (int mf = 0; mf < 2; ++mf)
                #pragma unroll
                for (int nf = 0; nf < 8; ++nf)
                    mma_f16(acc[mf][nf], ah[mf], &b[nf >> 1][(nf & 1) * 2]);
        }
    }

    // ---- epilogue ----
    #pragma unroll
    for (int mf = 0; mf < 2; ++mf) {
        #pragma unroll
        for (int half_ = 0; half_ < 2; ++half_) {
            const int row = bm + mOff + mf * 16 + (lane >> 2) + half_ * 8;
            #pragma unroll
            for (int nf = 0; nf < 8; ++nf) {
                const int col = bn + nOff + nf * 8 + (lane & 3) * 2;
                float v0 = acc[mf][nf][half_ * 2 + 0] + bias[col];
                float v1 = acc[mf][nf][half_ * 2 + 1] + bias[col + 1];
                if (EPI == 1) {
                    v0 = gelu_exact(v0);
                    v1 = gelu_exact(v1);
                    __half h0 = __float2half_rn(v0);
                    __half h1 = __float2half_rn(v1);
                    uint32_t hp = (uint32_t)__half_as_ushort(h0) |
                                  ((uint32_t)__half_as_ushort(h1) << 16);
                    *reinterpret_cast<uint32_t*>(Ch + (size_t)row * N + col) = hp;
                } else {
                    if (EPI == 2) {
                        const float* rp = resid + (size_t)row * N + col;
                        v0 += rp[0];
                        v1 += rp[1];
                    }
                    *reinterpret_cast<float2*>(Cf + (size_t)row * N + col) = make_float2(v0, v1);
                }
            }
        }
    }
}

// ---------------- fp32 -> fp16 convert (elementwise) ----------------
__global__ void __launch_bounds__(256) cvt_kernel(
    const float* __restrict__ x, __half* __restrict__ h, int n4)
{
    int i = blockIdx.x * 256 + threadIdx.x;
    if (i >= n4) return;
    float4 v = reinterpret_cast<const float4*>(x)[i];
    __half hb[4] = {__float2half_rn(v.x), __float2half_rn(v.y),
                    __float2half_rn(v.z), __float2half_rn(v.w)};
    reinterpret_cast<uint2*>(h)[i] = *reinterpret_cast<const uint2*>(hb);
}

// ---------------- W[K][N] fp32 -> Wt[N][K] fp16 ----------------
__global__ void __launch_bounds__(256) transpose_h(
    const float* __restrict__ W, __half* __restrict__ Th, int K, int N)
{
    __shared__ float s[32][33];
    const int n0 = blockIdx.x * 32, k0 = blockIdx.y * 32;
    const int c = threadIdx.x & 31, r0 = threadIdx.x >> 5;
    #pragma unroll
    for (int r = r0; r < 32; r += 8)
        s[r][c] = W[(size_t)(k0 + r) * N + n0 + c];
    __syncthreads();
    #pragma unroll
    for (int r = r0; r < 32; r += 8)
        Th[(size_t)(n0 + r) * K + k0 + c] = __float2half_rn(s[c][r]);
}

// ---------------- block reduce helpers ----------------
__device__ __forceinline__ float blockReduceMax(float v) {
    __shared__ float sm[8];
    #pragma unroll
    for (int o = 16; o > 0; o >>= 1) v = fmaxf(v, __shfl_xor_sync(0xffffffffu, v, o));
    int wid = threadIdx.x >> 5, nw = blockDim.x >> 5;
    if ((threadIdx.x & 31) == 0) sm[wid] = v;
    __syncthreads();
    float r = -1e30f;
    for (int i = 0; i < nw; ++i) r = fmaxf(r, sm[i]);
    __syncthreads();
    return r;
}
__device__ __forceinline__ float blockReduceSum(float v) {
    __shared__ float sm[8];
    #pragma unroll
    for (int o = 16; o > 0; o >>= 1) v += __shfl_xor_sync(0xffffffffu, v, o);
    int wid = threadIdx.x >> 5, nw = blockDim.x >> 5;
    if ((threadIdx.x & 31) == 0) sm[wid] = v;
    __syncthreads();
    float r = 0.0f;
    for (int i = 0; i < nw; ++i) r += sm[i];
    __syncthreads();
    return r;
}
__device__ __forceinline__ void blockReduceSum2(float& a, float& b) {
    __shared__ float sa[8], sb[8];
    #pragma unroll
    for (int o = 16; o > 0; o >>= 1) {
        a += __shfl_xor_sync(0xffffffffu, a, o);
        b += __shfl_xor_sync(0xffffffffu, b, o);
    }
    int wid = threadIdx.x >> 5, nw = blockDim.x >> 5;
    if ((threadIdx.x & 31) == 0) { sa[wid] = a; sb[wid] = b; }
    __syncthreads();
    float ra = 0.0f, rb = 0.0f;
    for (int i = 0; i < nw; ++i) { ra += sa[i]; rb += sb[i]; }
    __syncthreads();
    a = ra; b = rb;
}

// ---------------- aff + fused softmax-over-cores ----------------
// aff[b,h,c,p] = (1/8) * sum_d cores[h,c,d] * q[b,p,h*64+d]
// Each 64x64 tile spans the FULL core dim (C=64): softmax over c is a
// 16-lane shfl reduction. Writes raw aff (for c2p) AND normalized p2c.
__global__ void __launch_bounds__(256) aff_kernel(
    const float* __restrict__ q, const float* __restrict__ cores,
    float* __restrict__ aff, float* __restrict__ p2c)
{
    __shared__ float cs[64][65];
    __shared__ float qs[64][65];
    const int b = blockIdx.z, h = blockIdx.y, p0 = blockIdx.x * 64;
    const int tid = threadIdx.x;
    const int lr = tid >> 2;
    const int lc = (tid & 3) * 16;
    #pragma unroll
    for (int u = 0; u < 4; ++u) {
        float4 cv = *reinterpret_cast<const float4*>(cores + (size_t)(h * CC + lr) * HD_ + lc + u * 4);
        cs[lr][lc + u * 4 + 0] = cv.x; cs[lr][lc + u * 4 + 1] = cv.y;
        cs[lr][lc + u * 4 + 2] = cv.z; cs[lr][lc + u * 4 + 3] = cv.w;
        float4 qv = *reinterpret_cast<const float4*>(q + (size_t)(b * PP + p0 + lr) * DD + h * HD_ + lc + u * 4);
        qs[lr][lc + u * 4 + 0] = qv.x; qs[lr][lc + u * 4 + 1] = qv.y;
        qs[lr][lc + u * 4 + 2] = qv.z; qs[lr][lc + u * 4 + 3] = qv.w;
    }
    __syncthreads();
    const int c0 = (tid & 15) * 4;      // c-group = lane & 15
    const int pq = (tid >> 4) * 4;
    float acc[4][4];
    #pragma unroll
    for (int i = 0; i < 4; ++i)
        #pragma unroll
        for (int j = 0; j < 4; ++j) acc[i][j] = 0.0f;
    #pragma unroll 8
    for (int k = 0; k < 64; ++k) {
        float cr[4], pr[4];
        #pragma unroll
        for (int i = 0; i < 4; ++i) cr[i] = cs[c0 + i][k];
        #pragma unroll
        for (int j = 0; j < 4; ++j) pr[j] = qs[pq + j][k];
        #pragma unroll
        for (int i = 0; i < 4; ++i)
            #pragma unroll
            for (int j = 0; j < 4; ++j) acc[i][j] = fmaf(cr[i], pr[j], acc[i][j]);
    }
    #pragma unroll
    for (int i = 0; i < 4; ++i)
        #pragma unroll
        for (int j = 0; j < 4; ++j) acc[i][j] *= 0.125f;

    // softmax over c (full 64): reduce across the 16 lanes sharing this p-group
    float e[4][4], inv[4];
    #pragma unroll
    for (int j = 0; j < 4; ++j) {
        float m = fmaxf(fmaxf(acc[0][j], acc[1][j]), fmaxf(acc[2][j], acc[3][j]));
        #pragma unroll
        for (int o = 1; o < 16; o <<= 1) m = fmaxf(m, __shfl_xor_sync(0xffffffffu, m, o));
        float s = 0.0f;
        #pragma unroll
        for (int i = 0; i < 4; ++i) { e[i][j] = __expf(acc[i][j] - m); s += e[i][j]; }
        #pragma unroll
        for (int o = 1; o < 16; o <<= 1) s += __shfl_xor_sync(0xffffffffu, s, o);
        inv[j] = 1.0f / s;
    }

    const size_t base = ((size_t)(b * HH + h) * CC) * PP;
    #pragma unroll
    for (int i = 0; i < 4; ++i) {
        const size_t off = base + (size_t)(c0 + i) * PP + p0 + pq;
        *reinterpret_cast<float4*>(aff + off) =
            make_float4(acc[i][0], acc[i][1], acc[i][2], acc[i][3]);
        *reinterpret_cast<float4*>(p2c + off) =
            make_float4(e[i][0] * inv[0], e[i][1] * inv[1], e[i][2] * inv[2], e[i][3] * inv[3]);
    }
}

// ---------------- softmax over patches (in-place) ----------------
__global__ void __launch_bounds__(256) c2p_softmax(float* __restrict__ a)
{
    float* row = a + (size_t)blockIdx.x * PP;
    const int t = threadIdx.x;
    float x[8];
    *reinterpret_cast<float4*>(x)     = *reinterpret_cast<const float4*>(row + t * 8);
    *reinterpret_cast<float4*>(x + 4) = *reinterpret_cast<const float4*>(row + t * 8 + 4);
    float m = -1e30f;
    #pragma unroll
    for (int i = 0; i < 8; ++i) m = fmaxf(m, x[i]);
    m = blockReduceMax(m);
    float s = 0.0f;
    #pragma unroll
    for (int i = 0; i < 8; ++i) { x[i] = __expf(x[i] - m); s += x[i]; }
    s = blockReduceSum(s);
    const float inv = 1.0f / s;
    #pragma unroll
    for (int i = 0; i < 8; ++i) x[i] *= inv;
    *reinterpret_cast<float4*>(row + t * 8)     = *reinterpret_cast<float4*>(x);
    *reinterpret_cast<float4*>(row + t * 8 + 4) = *reinterpret_cast<float4*>(x + 4);
}

// ---------------- v_core ----------------
__global__ void __launch_bounds__(256) vcore_kernel(
    const float* __restrict__ input, const float* __restrict__ c2p, float* __restrict__ vcore)
{
    __shared__ float asT[64][68];
    __shared__ float vs[64][68];
    const int h = blockIdx.x, b = blockIdx.y;
    const int bh = b * HH + h;
    const float* abase = c2p + (size_t)bh * CC * PP;
    const int tid = threadIdx.x;
    const int lr = tid >> 2;
    const int lc = (tid & 3) * 16;
    const int c0 = (tid & 15) * 4;
    const int d0 = (tid >> 4) * 4;
    float acc[4][4];
    #pragma unroll
    for (int i = 0; i < 4; ++i)
        #pragma unroll
        for (int j = 0; j < 4; ++j) acc[i][j] = 0.0f;

    for (int pt = 0; pt < PP; pt += 64) {
        #pragma unroll
        for (int u = 0; u < 4; ++u) {
            float4 av = *reinterpret_cast<const float4*>(abase + (size_t)lr * PP + pt + lc + u * 4);
            asT[lc + u * 4 + 0][lr] = av.x; asT[lc + u * 4 + 1][lr] = av.y;
            asT[lc + u * 4 + 2][lr] = av.z; asT[lc + u * 4 + 3][lr] = av.w;
            float4 vv = *reinterpret_cast<const float4*>(input + (size_t)(b * PP + pt + lr) * DD + h * HD_ + lc + u * 4);
            *reinterpret_cast<float4*>(&vs[lr][lc + u * 4]) = vv;
        }
        __syncthreads();
        #pragma unroll 16
        for (int k = 0; k < 64; ++k) {
            float4 ar = *reinterpret_cast<const float4*>(&asT[k][c0]);
            float4 vr = *reinterpret_cast<const float4*>(&vs[k][d0]);
            float arr[4] = {ar.x, ar.y, ar.z, ar.w};
            float vrr[4] = {vr.x, vr.y, vr.z, vr.w};
            #pragma unroll
            for (int i = 0; i < 4; ++i)
                #pragma unroll
                for (int j = 0; j < 4; ++j) acc[i][j] = fmaf(arr[i], vrr[j], acc[i][j]);
        }
        __syncthreads();
    }
    #pragma unroll
    for (int i = 0; i < 4; ++i) {
        float4 o = make_float4(acc[i][0], acc[i][1], acc[i][2], acc[i][3]);
        *reinterpret_cast<float4*>(vcore + (size_t)(bh * CC + c0 + i) * HD_ + d0) = o;
    }
}

// ---------------- v_patch + ffn_in concat (writes fp16) ----------------
__device__ __forceinline__ void cvt_store4(__half* ph, float4 v) {
    __half hb[4] = {__float2half_rn(v.x), __float2half_rn(v.y),
                    __float2half_rn(v.z), __float2half_rn(v.w)};
    *reinterpret_cast<uint2*>(ph) = *reinterpret_cast<const uint2*>(hb);
}

__global__ void __launch_bounds__(256) vpatch_ffn_kernel(
    const float* __restrict__ input, const float* __restrict__ vcore,
    const float* __restrict__ p2c, __half* __restrict__ fh)
{
    __shared__ float vc[64][65];
    __shared__ float ap[64][65];
    const int b = blockIdx.z, h = blockIdx.y, p0 = blockIdx.x * 64;
    const int bh = b * HH + h;
    const int tid = threadIdx.x;
    const int lr = tid >> 2;
    const int lc = (tid & 3) * 16;
    #pragma unroll
    for (int u = 0; u < 4; ++u) {
        float4 cv = *reinterpret_cast<const float4*>(vcore + (size_t)(bh * CC + lr) * HD_ + lc + u * 4);
        vc[lr][lc + u * 4 + 0] = cv.x; vc[lr][lc + u * 4 + 1] = cv.y;
        vc[lr][lc + u * 4 + 2] = cv.z; vc[lr][lc + u * 4 + 3] = cv.w;
        float4 av = *reinterpret_cast<const float4*>(p2c + ((size_t)(bh * CC + lr)) * PP + p0 + lc + u * 4);
        ap[lr][lc + u * 4 + 0] = av.x; ap[lr][lc + u * 4 + 1] = av.y;
        ap[lr][lc + u * 4 + 2] = av.z; ap[lr][lc + u * 4 + 3] = av.w;
    }
    __syncthreads();
    const int pq = (tid >> 4) * 4;
    const int d0 = (tid & 15) * 4;
    float acc[4][4];
    #pragma unroll
    for (int i = 0; i < 4; ++i)
        #pragma unroll
        for (int j = 0; j < 4; ++j) acc[i][j] = 0.0f;
    #pragma unroll 8
    for (int k = 0; k < 64; ++k) {
        float apr[4], vcr[4];
        #pragma unroll
        for (int i = 0; i < 4; ++i) apr[i] = ap[k][pq + i];
        #pragma unroll
        for (int j = 0; j < 4; ++j) vcr[j] = vc[k][d0 + j];
        #pragma unroll
        for (int i = 0; i < 4; ++i)
            #pragma unroll
            for (int j = 0; j < 4; ++j) acc[i][j] = fmaf(apr[i], vcr[j], acc[i][j]);
    }
    #pragma unroll
    for (int i = 0; i < 4; ++i) {
        const int gp = b * PP + p0 + pq + i;
        float4 inp = *reinterpret_cast<const float4*>(input + (size_t)gp * DD + h * HD_ + d0);
        float4 vp = make_float4(acc[i][0], acc[i][1], acc[i][2], acc[i][3]);
        float4 diff = make_float4(inp.x - vp.x, inp.y - vp.y, inp.z - vp.z, inp.w - vp.w);
        const size_t fo = (size_t)gp * FFNIN + h * HD_ + d0;
        cvt_store4(fh + fo, diff);
        cvt_store4(fh + fo + DD, vp);
    }
}

// ---------------- LayerNorm ----------------
__global__ void __launch_bounds__(128) ln_kernel(
    const float* __restrict__ x, const float* __restrict__ gamma,
    const float* __restrict__ beta, float* __restrict__ out)
{
    const float* row = x + (size_t)blockIdx.x * DD;
    const int t = threadIdx.x;
    float4 v = *reinterpret_cast<const float4*>(row + t * 4);
    float s = v.x + v.y + v.z + v.w;
    float sq = v.x * v.x + v.y * v.y + v.z * v.z + v.w * v.w;
    blockReduceSum2(s, sq);
    const float mu = s * (1.0f / DD);
    const float var = sq * (1.0f / DD) - mu * mu;
    const float rstd = rsqrtf(var + 1e-5f);
    float4 g = *reinterpret_cast<const float4*>(gamma + t * 4);
    float4 bt = *reinterpret_cast<const float4*>(beta + t * 4);
    float4 o;
    o.x = (v.x - mu) * rstd * g.x + bt.x;
    o.y = (v.y - mu) * rstd * g.y + bt.y;
    o.z = (v.z - mu) * rstd * g.z + bt.z;
    o.w = (v.w - mu) * rstd * g.w + bt.w;
    *reinterpret_cast<float4*>(out + (size_t)blockIdx.x * DD + t * 4) = o;
}

// ---------------- launch ----------------
extern "C" void kernel_launch(void* const* d_in, const int* in_sizes, int n_in,
                              void* d_out, int out_size)
{
    (void)in_sizes; (void)n_in; (void)out_size;
    const float* input = (const float*)d_in[0];
    const float* cores = (const float*)d_in[1];
    const float* Wv    = (const float*)d_in[2];
    const float* bv    = (const float*)d_in[3];
    const float* W1    = (const float*)d_in[4];
    const float* b1    = (const float*)d_in[5];
    const float* W2    = (const float*)d_in[6];
    const float* b2    = (const float*)d_in[7];
    const float* gamma = (const float*)d_in[8];
    const float* beta  = (const float*)d_in[9];
    float* out = (float*)d_out;

    float *q, *aff, *p2c, *vcore, *outp;
    __half *in_h, *ffn_h, *hid_h, *wvT, *w1T, *w2T;
    cudaGetSymbolAddress((void**)&q, g_q);
    cudaGetSymbolAddress((void**)&aff, g_aff);
    cudaGetSymbolAddress((void**)&p2c, g_p2c);
    cudaGetSymbolAddress((void**)&vcore, g_vcore);
    cudaGetSymbolAddress((void**)&outp, g_outp);
    cudaGetSymbolAddress((void**)&in_h, g_in_h);
    cudaGetSymbolAddress((void**)&ffn_h, g_ffn_h);
    cudaGetSymbolAddress((void**)&hid_h, g_hid_h);
    cudaGetSymbolAddress((void**)&wvT, g_wvT);
    cudaGetSymbolAddress((void**)&w1T, g_w1T);
    cudaGetSymbolAddress((void**)&w2T, g_w2T);

    cudaFuncSetAttribute(gemm_mma<0>, cudaFuncAttributeMaxDynamicSharedMemorySize, GEMM_SMEM);
    cudaFuncSetAttribute(gemm_mma<1>, cudaFuncAttributeMaxDynamicSharedMemorySize, GEMM_SMEM);
    cudaFuncSetAttribute(gemm_mma<2>, cudaFuncAttributeMaxDynamicSharedMemorySize, GEMM_SMEM);

    // prep: converts + weight transposes
    cvt_kernel<<<(MM * DD / 4 + 255) / 256, 256>>>(input, in_h, MM * DD / 4);
    transpose_h<<<dim3(DD / 32, DD / 32), 256>>>(Wv, wvT, DD, DD);
    transpose_h<<<dim3(FFNHID / 32, FFNIN / 32), 256>>>(W1, w1T, FFNIN, FFNHID);
    transpose_h<<<dim3(DD / 32, FFNHID / 32), 256>>>(W2, w2T, FFNHID, DD);

    // 1. q = input @ Wv + bv
    gemm_mma<0><<<dim3(DD / 128, MM / 128), 256, GEMM_SMEM>>>(
        in_h, wvT, bv, nullptr, q, nullptr, DD, DD);
    // 2-5. affinity (+fused p2c softmax) + c2p softmax + aggregate + redistribute
    aff_kernel<<<dim3(PP / 64, HH, BB), 256>>>(q, cores, aff, p2c);
    c2p_softmax<<<BB * HH * CC, 256>>>(aff);
    vcore_kernel<<<dim3(HH, BB), 256>>>(input, aff, vcore);
    vpatch_ffn_kernel<<<dim3(PP / 64, HH, BB), 256>>>(input, vcore, p2c, ffn_h);
    // 6. hid = gelu(ffn @ W1 + b1)   (fp16 out)
    gemm_mma<1><<<dim3(FFNHID / 128, MM / 128), 256, GEMM_SMEM>>>(
        ffn_h, w1T, b1, nullptr, nullptr, hid_h, FFNHID, FFNIN);
    // 7. outp = input + hid @ W2 + b2
    gemm_mma<2><<<dim3(DD / 128, MM / 128), 256, GEMM_SMEM>>>(
        hid_h, w2T, b2, input, outp, nullptr, DD, FFNHID);
    // 8. LayerNorm
    ln_kernel<<<MM, 128>>>(outp, gamma, beta, out);
}

// round 11
// speedup vs baseline: 1.1318x; 1.0723x over previous
#include <cuda_runtime.h>
#include <cuda_fp16.h>
#include <math.h>
#include <stdint.h>

// ---------------- problem constants ----------------
#define BB      16
#define PP      2048
#define DD      512
#define HH      8
#define CC      64
#define HD_     64
#define MM      (BB * PP)        // 32768
#define FFNIN   1024
#define FFNHID  4096

// ---------------- scratch (device globals; allocation-free) ----------------
__device__ __align__(256) float g_q[MM * DD];
__device__ __align__(256) float g_aff[BB * HH * CC * PP];
__device__ __align__(256) float g_p2c[BB * HH * CC * PP];
__device__ __align__(256) float g_vcore[BB * HH * CC * HD_];
__device__ __align__(256) float g_outp[MM * DD];

__device__ __align__(256) __half g_in_h[MM * DD];
__device__ __align__(256) __half g_ffn_h[MM * FFNIN];
__device__ __align__(256) __half g_hid_h[(size_t)MM * FFNHID];
// weights transposed to [N][K] fp16
__device__ __align__(256) __half g_wvT[DD * DD];
__device__ __align__(256) __half g_w1T[FFNHID * FFNIN];
__device__ __align__(256) __half g_w2T[DD * FFNHID];

// ---------------- PTX helpers (sm_80-era instructions only) ----------------
__device__ __forceinline__ uint32_t smem_u32(const void* p) {
    uint32_t a;
    asm("{ .reg .u64 t; cvta.to.shared.u64 t, %1; cvt.u32.u64 %0, t; }" : "=r"(a) : "l"(p));
    return a;
}
__device__ __forceinline__ void cp16(uint32_t s, const void* g) {
    asm volatile("cp.async.cg.shared.global [%0], [%1], 16;" :: "r"(s), "l"(g));
}
__device__ __forceinline__ void ldm_x4(uint32_t* r, uint32_t addr) {
    asm volatile("ldmatrix.sync.aligned.m8n8.x4.shared.b16 {%0,%1,%2,%3}, [%4];"
                 : "=r"(r[0]), "=r"(r[1]), "=r"(r[2]), "=r"(r[3]) : "r"(addr));
}
__device__ __forceinline__ void mma_f16(float* d, const uint32_t* a, const uint32_t* b) {
    asm volatile(
        "mma.sync.aligned.m16n8k16.row.col.f32.f16.f16.f32 "
        "{%0,%1,%2,%3}, {%4,%5,%6,%7}, {%8,%9}, {%0,%1,%2,%3};"
        : "+f"(d[0]), "+f"(d[1]), "+f"(d[2]), "+f"(d[3])
        : "r"(a[0]), "r"(a[1]), "r"(a[2]), "r"(a[3]), "r"(b[0]), "r"(b[1]));
}

__device__ __forceinline__ float gelu_exact(float x) {
    return 0.5f * x * (1.0f + erff(x * 0.7071067811865476f));
}

// ---------------- fp16 GEMM via mma.sync, BM=128 BN=128 BK=64, 3-stage, 2 CTA/SM ----------------
// C = Ah @ Bh^T  with fp32 accumulate
// EPI 0: Cf = D + bias                       (fp32 out)
// EPI 1: Ch = half(gelu(D + bias))           (fp16 out)
// EPI 2: Cf = D + bias + resid               (fp32 out)
#define BKK       64
#define RSTRIDE   72                        // fp16 elements per smem row (64 + 8 pad)
#define TILE_B    (128 * RSTRIDE * 2)       // 18432 bytes per matrix tile
#define STAGE_B   (2 * TILE_B)              // Ah, Bh = 36864
#define NSTAGE    3
#define GEMM_SMEM (NSTAGE * STAGE_B)        // 110592 (x2 CTAs = 216 KB/SM)

template <int EPI>
__global__ void __launch_bounds__(256, 2) gemm_mma(
    const __half* __restrict__ Ah, const __half* __restrict__ Bh,
    const float* __restrict__ bias, const float* __restrict__ resid,
    float* __restrict__ Cf, __half* __restrict__ Ch,
    int N, int K)
{
    extern __shared__ __align__(256) char smem[];
    const uint32_t sb = smem_u32(smem);

    const int tid = threadIdx.x;
    const int wid = tid >> 5;
    const int lane = tid & 31;
    const int bm = blockIdx.y * 128;
    const int bn = blockIdx.x * 128;
    const int mOff = (wid & 3) * 32;
    const int nOff = (wid >> 2) * 64;

    // per-thread ldmatrix source row/col selectors
    const int aRow = lane & 15;
    const int aCol = (lane >> 4) * 8;
    const int bRow = (lane & 7) + ((lane >> 4) << 3);
    const int bCol = ((lane >> 3) & 1) * 8;

    float acc[2][8][4];
    #pragma unroll
    for (int i = 0; i < 2; ++i)
        #pragma unroll
        for (int j = 0; j < 8; ++j)
            #pragma unroll
            for (int k = 0; k < 4; ++k) acc[i][j][k] = 0.0f;

    const int nch = K / BKK;

    // stage loader: 4 chunks of 16B per thread per matrix (Ah, Bh)
    auto loadStage = [&](int s, int it) {
        const int k0 = it * BKK;
        const uint32_t st = sb + s * STAGE_B;
        #pragma unroll
        for (int i = 0; i < 4; ++i) {
            const int id = tid + i * 256;
            const int r = id >> 3, c = id & 7;
            const uint32_t so = (uint32_t)(r * (RSTRIDE * 2) + c * 16);
            cp16(st + so,          Ah + (size_t)(bm + r) * K + k0 + c * 8);
            cp16(st + TILE_B + so, Bh + (size_t)(bn + r) * K + k0 + c * 8);
        }
        asm volatile("cp.async.commit_group;" ::: "memory");
    };

    loadStage(0, 0);
    loadStage(1, 1);

    for (int it = 0; it < nch; ++it) {
        if (it + 1 < nch)
            asm volatile("cp.async.wait_group 1;" ::: "memory");
        else
            asm volatile("cp.async.wait_group 0;" ::: "memory");
        __syncthreads();

        // prefetch stage it+2 (distinct buffer from the one consumed now and the pending one)
        if (it + 2 < nch) loadStage((it + 2) % NSTAGE, it + 2);

        const uint32_t st = sb + (it % NSTAGE) * STAGE_B;
        const uint32_t pAh = st, pBh = st + TILE_B;

        #pragma unroll
        for (int kk = 0; kk < 4; ++kk) {
            uint32_t ah[2][4], b[4][4];
            #pragma unroll
            for (int mf = 0; mf < 2; ++mf)
                ldm_x4(ah[mf], pAh +
                    (uint32_t)(((mOff + mf * 16 + aRow) * RSTRIDE + kk * 16 + aCol) * 2));
            #pragma unroll
            for (int n2 = 0; n2 < 4; ++n2)
                ldm_x4(b[n2], pBh +
                    (uint32_t)(((nOff + n2 * 16 + bRow) * RSTRIDE + kk * 16 + bCol) * 2));
            #pragma unroll
            for (int mf = 0; mf < 2; ++mf)
                #pragma unroll
                for (int nf = 0; nf < 8; ++nf)
                    mma_f16(acc[mf][nf], ah[mf], &b[nf >> 1][(nf & 1) * 2]);
        }
    }

    // ---- epilogue ----
    #pragma unroll
    for (int mf = 0; mf < 2; ++mf) {
        #pragma unroll
        for (int half_ = 0; half_ < 2; ++half_) {
            const int row = bm + mOff + mf * 16 + (lane >> 2) + half_ * 8;
            #pragma unroll
            for (int nf = 0; nf < 8; ++nf) {
                const int col = bn + nOff + nf * 8 + (lane & 3) * 2;
                float v0 = acc[mf][nf][half_ * 2 + 0] + bias[col];
                float v1 = acc[mf][nf][half_ * 2 + 1] + bias[col + 1];
                if (EPI == 1) {
                    v0 = gelu_exact(v0);
                    v1 = gelu_exact(v1);
                    __half h0 = __float2half_rn(v0);
                    __half h1 = __float2half_rn(v1);
                    uint32_t hp = (uint32_t)__half_as_ushort(h0) |
                                  ((uint32_t)__half_as_ushort(h1) << 16);
                    *reinterpret_cast<uint32_t*>(Ch + (size_t)row * N + col) = hp;
                } else {
                    if (EPI == 2) {
                        const float* rp = resid + (size_t)row * N + col;
                        v0 += rp[0];
                        v1 += rp[1];
                    }
                    *reinterpret_cast<float2*>(Cf + (size_t)row * N + col) = make_float2(v0, v1);
                }
            }
        }
    }
}

// ---------------- fp32 -> fp16 convert (elementwise) ----------------
__global__ void __launch_bounds__(256) cvt_kernel(
    const float* __restrict__ x, __half* __restrict__ h, int n4)
{
    int i = blockIdx.x * 256 + threadIdx.x;
    if (i >= n4) return;
    float4 v = reinterpret_cast<const float4*>(x)[i];
    __half hb[4] = {__float2half_rn(v.x), __float2half_rn(v.y),
                    __float2half_rn(v.z), __float2half_rn(v.w)};
    reinterpret_cast<uint2*>(h)[i] = *reinterpret_cast<const uint2*>(hb);
}

// ---------------- W[K][N] fp32 -> Wt[N][K] fp16 ----------------
__global__ void __launch_bounds__(256) transpose_h(
    const float* __restrict__ W, __half* __restrict__ Th, int K, int N)
{
    __shared__ float s[32][33];
    const int n0 = blockIdx.x * 32, k0 = blockIdx.y * 32;
    const int c = threadIdx.x & 31, r0 = threadIdx.x >> 5;
    #pragma unroll
    for (int r = r0; r < 32; r += 8)
        s[r][c] = W[(size_t)(k0 + r) * N + n0 + c];
    __syncthreads();
    #pragma unroll
    for (int r = r0; r < 32; r += 8)
        Th[(size_t)(n0 + r) * K + k0 + c] = __float2half_rn(s[c][r]);
}

// ---------------- block reduce helpers ----------------
__device__ __forceinline__ float blockReduceMax(float v) {
    __shared__ float sm[8];
    #pragma unroll
    for (int o = 16; o > 0; o >>= 1) v = fmaxf(v, __shfl_xor_sync(0xffffffffu, v, o));
    int wid = threadIdx.x >> 5, nw = blockDim.x >> 5;
    if ((threadIdx.x & 31) == 0) sm[wid] = v;
    __syncthreads();
    float r = -1e30f;
    for (int i = 0; i < nw; ++i) r = fmaxf(r, sm[i]);
    __syncthreads();
    return r;
}
__device__ __forceinline__ float blockReduceSum(float v) {
    __shared__ float sm[8];
    #pragma unroll
    for (int o = 16; o > 0; o >>= 1) v += __shfl_xor_sync(0xffffffffu, v, o);
    int wid = threadIdx.x >> 5, nw = blockDim.x >> 5;
    if ((threadIdx.x & 31) == 0) sm[wid] = v;
    __syncthreads();
    float r = 0.0f;
    for (int i = 0; i < nw; ++i) r += sm[i];
    __syncthreads();
    return r;
}
__device__ __forceinline__ void blockReduceSum2(float& a, float& b) {
    __shared__ float sa[8], sb[8];
    #pragma unroll
    for (int o = 16; o > 0; o >>= 1) {
        a += __shfl_xor_sync(0xffffffffu, a, o);
        b += __shfl_xor_sync(0xffffffffu, b, o);
    }
    int wid = threadIdx.x >> 5, nw = blockDim.x >> 5;
    if ((threadIdx.x & 31) == 0) { sa[wid] = a; sb[wid] = b; }
    __syncthreads();
    float ra = 0.0f, rb = 0.0f;
    for (int i = 0; i < nw; ++i) { ra += sa[i]; rb += sb[i]; }
    __syncthreads();
    a = ra; b = rb;
}

// ---------------- aff + fused softmax-over-cores ----------------
// aff[b,h,c,p] = (1/8) * sum_d cores[h,c,d] * q[b,p,h*64+d]
// Each 64x64 tile spans the FULL core dim (C=64): softmax over c is a
// 16-lane shfl reduction. Writes raw aff (for c2p) AND normalized p2c.
__global__ void __launch_bounds__(256) aff_kernel(
    const float* __restrict__ q, const float* __restrict__ cores,
    float* __restrict__ aff, float* __restrict__ p2c)
{
    __shared__ float cs[64][65];
    __shared__ float qs[64][65];
    const int b = blockIdx.z, h = blockIdx.y, p0 = blockIdx.x * 64;
    const int tid = threadIdx.x;
    const int lr = tid >> 2;
    const int lc = (tid & 3) * 16;
    #pragma unroll
    for (int u = 0; u < 4; ++u) {
        float4 cv = *reinterpret_cast<const float4*>(cores + (size_t)(h * CC + lr) * HD_ + lc + u * 4);
        cs[lr][lc + u * 4 + 0] = cv.x; cs[lr][lc + u * 4 + 1] = cv.y;
        cs[lr][lc + u * 4 + 2] = cv.z; cs[lr][lc + u * 4 + 3] = cv.w;
        float4 qv = *reinterpret_cast<const float4*>(q + (size_t)(b * PP + p0 + lr) * DD + h * HD_ + lc + u * 4);
        qs[lr][lc + u * 4 + 0] = qv.x; qs[lr][lc + u * 4 + 1] = qv.y;
        qs[lr][lc + u * 4 + 2] = qv.z; qs[lr][lc + u * 4 + 3] = qv.w;
    }
    __syncthreads();
    const int c0 = (tid & 15) * 4;      // c-group = lane & 15
    const int pq = (tid >> 4) * 4;
    float acc[4][4];
    #pragma unroll
    for (int i = 0; i < 4; ++i)
        #pragma unroll
        for (int j = 0; j < 4; ++j) acc[i][j] = 0.0f;
    #pragma unroll 8
    for (int k = 0; k < 64; ++k) {
        float cr[4], pr[4];
        #pragma unroll
        for (int i = 0; i < 4; ++i) cr[i] = cs[c0 + i][k];
        #pragma unroll
        for (int j = 0; j < 4; ++j) pr[j] = qs[pq + j][k];
        #pragma unroll
        for (int i = 0; i < 4; ++i)
            #pragma unroll
            for (int j = 0; j < 4; ++j) acc[i][j] = fmaf(cr[i], pr[j], acc[i][j]);
    }
    #pragma unroll
    for (int i = 0; i < 4; ++i)
        #pragma unroll
        for (int j = 0; j < 4; ++j) acc[i][j] *= 0.125f;

    // softmax over c (full 64): reduce across the 16 lanes sharing this p-group
    float e[4][4], inv[4];
    #pragma unroll
    for (int j = 0; j < 4; ++j) {
        float m = fmaxf(fmaxf(acc[0][j], acc[1][j]), fmaxf(acc[2][j], acc[3][j]));
        #pragma unroll
        for (int o = 1; o < 16; o <<= 1) m = fmaxf(m, __shfl_xor_sync(0xffffffffu, m, o));
        float s = 0.0f;
        #pragma unroll
        for (int i = 0; i < 4; ++i) { e[i][j] = __expf(acc[i][j] - m); s += e[i][j]; }
        #pragma unroll
        for (int o = 1; o < 16; o <<= 1) s += __shfl_xor_sync(0xffffffffu, s, o);
        inv[j] = 1.0f / s;
    }

    const size_t base = ((size_t)(b * HH + h) * CC) * PP;
    #pragma unroll
    for (int i = 0; i < 4; ++i) {
        const size_t off = base + (size_t)(c0 + i) * PP + p0 + pq;
        *reinterpret_cast<float4*>(aff + off) =
            make_float4(acc[i][0], acc[i][1], acc[i][2], acc[i][3]);
        *reinterpret_cast<float4*>(p2c + off) =
            make_float4(e[i][0] * inv[0], e[i][1] * inv[1], e[i][2] * inv[2], e[i][3] * inv[3]);
    }
}

// ---------------- softmax over patches (in-place) ----------------
__global__ void __launch_bounds__(256) c2p_softmax(float* __restrict__ a)
{
    float* row = a + (size_t)blockIdx.x * PP;
    const int t = threadIdx.x;
    float x[8];
    *reinterpret_cast<float4*>(x)     = *reinterpret_cast<const float4*>(row + t * 8);
    *reinterpret_cast<float4*>(x + 4) = *reinterpret_cast<const float4*>(row + t * 8 + 4);
    float m = -1e30f;
    #pragma unroll
    for (int i = 0; i < 8; ++i) m = fmaxf(m, x[i]);
    m = blockReduceMax(m);
    float s = 0.0f;
    #pragma unroll
    for (int i = 0; i < 8; ++i) { x[i] = __expf(x[i] - m); s += x[i]; }
    s = blockReduceSum(s);
    const float inv = 1.0f / s;
    #pragma unroll
    for (int i = 0; i < 8; ++i) x[i] *= inv;
    *reinterpret_cast<float4*>(row + t * 8)     = *reinterpret_cast<float4*>(x);
    *reinterpret_cast<float4*>(row + t * 8 + 4) = *reinterpret_cast<float4*>(x + 4);
}

// ---------------- v_core ----------------
__global__ void __launch_bounds__(256) vcore_kernel(
    const float* __restrict__ input, const float* __restrict__ c2p, float* __restrict__ vcore)
{
    __shared__ float asT[64][68];
    __shared__ float vs[64][68];
    const int h = blockIdx.x, b = blockIdx.y;
    const int bh = b * HH + h;
    const float* abase = c2p + (size_t)bh * CC * PP;
    const int tid = threadIdx.x;
    const int lr = tid >> 2;
    const int lc = (tid & 3) * 16;
    const int c0 = (tid & 15) * 4;
    const int d0 = (tid >> 4) * 4;
    float acc[4][4];
    #pragma unroll
    for (int i = 0; i < 4; ++i)
        #pragma unroll
        for (int j = 0; j < 4; ++j) acc[i][j] = 0.0f;

    for (int pt = 0; pt < PP; pt += 64) {
        #pragma unroll
        for (int u = 0; u < 4; ++u) {
            float4 av = *reinterpret_cast<const float4*>(abase + (size_t)lr * PP + pt + lc + u * 4);
            asT[lc + u * 4 + 0][lr] = av.x; asT[lc + u * 4 + 1][lr] = av.y;
            asT[lc + u * 4 + 2][lr] = av.z; asT[lc + u * 4 + 3][lr] = av.w;
            float4 vv = *reinterpret_cast<const float4*>(input + (size_t)(b * PP + pt + lr) * DD + h * HD_ + lc + u * 4);
            *reinterpret_cast<float4*>(&vs[lr][lc + u * 4]) = vv;
        }
        __syncthreads();
        #pragma unroll 16
        for (int k = 0; k < 64; ++k) {
            float4 ar = *reinterpret_cast<const float4*>(&asT[k][c0]);
            float4 vr = *reinterpret_cast<const float4*>(&vs[k][d0]);
            float arr[4] = {ar.x, ar.y, ar.z, ar.w};
            float vrr[4] = {vr.x, vr.y, vr.z, vr.w};
            #pragma unroll
            for (int i = 0; i < 4; ++i)
                #pragma unroll
                for (int j = 0; j < 4; ++j) acc[i][j] = fmaf(arr[i], vrr[j], acc[i][j]);
        }
        __syncthreads();
    }
    #pragma unroll
    for (int i = 0; i < 4; ++i) {
        float4 o = make_float4(acc[i][0], acc[i][1], acc[i][2], acc[i][3]);
        *reinterpret_cast<float4*>(vcore + (size_t)(bh * CC + c0 + i) * HD_ + d0) = o;
    }
}

// ---------------- v_patch + ffn_in concat (writes fp16) ----------------
__device__ __forceinline__ void cvt_store4(__half* ph, float4 v) {
    __half hb[4] = {__float2half_rn(v.x), __float2half_rn(v.y),
                    __float2half_rn(v.z), __float2half_rn(v.w)};
    *reinterpret_cast<uint2*>(ph) = *reinterpret_cast<const uint2*>(hb);
}

__global__ void __launch_bounds__(256) vpatch_ffn_kernel(
    const float* __restrict__ input, const float* __restrict__ vcore,
    const float* __restrict__ p2c, __half* __restrict__ fh)
{
    __shared__ float vc[64][65];
    __shared__ float ap[64][65];
    const int b = blockIdx.z, h = blockIdx.y, p0 = blockIdx.x * 64;
    const int bh = b * HH + h;
    const int tid = threadIdx.x;
    const int lr = tid >> 2;
    const int lc = (tid & 3) * 16;
    #pragma unroll
    for (int u = 0; u < 4; ++u) {
        float4 cv = *reinterpret_cast<const float4*>(vcore + (size_t)(bh * CC + lr) * HD_ + lc + u * 4);
        vc[lr][lc + u * 4 + 0] = cv.x; vc[lr][lc + u * 4 + 1] = cv.y;
        vc[lr][lc + u * 4 + 2] = cv.z; vc[lr][lc + u * 4 + 3] = cv.w;
        float4 av = *reinterpret_cast<const float4*>(p2c + ((size_t)(bh * CC + lr)) * PP + p0 + lc + u * 4);
        ap[lr][lc + u * 4 + 0] = av.x; ap[lr][lc + u * 4 + 1] = av.y;
        ap[lr][lc + u * 4 + 2] = av.z; ap[lr][lc + u * 4 + 3] = av.w;
    }
    __syncthreads();
    const int pq = (tid >> 4) * 4;
    const int d0 = (tid & 15) * 4;
    float acc[4][4];
    #pragma unroll
    for (int i = 0; i < 4; ++i)
        #pragma unroll
        for (int j = 0; j < 4; ++j) acc[i][j] = 0.0f;
    #pragma unroll 8
    for (int k = 0; k < 64; ++k) {
        float apr[4], vcr[4];
        #pragma unroll
        for (int i = 0; i < 4; ++i) apr[i] = ap[k][pq + i];
        #pragma unroll
        for (int j = 0; j < 4; ++j) vcr[j] = vc[k][d0 + j];
        #pragma unroll
        for (int i = 0; i < 4; ++i)
            #pragma unroll
            for (int j = 0; j < 4; ++j) acc[i][j] = fmaf(apr[i], vcr[j], acc[i][j]);
    }
    #pragma unroll
    for (int i = 0; i < 4; ++i) {
        const int gp = b * PP + p0 + pq + i;
        float4 inp = *reinterpret_cast<const float4*>(input + (size_t)gp * DD + h * HD_ + d0);
        float4 vp = make_float4(acc[i][0], acc[i][1], acc[i][2], acc[i][3]);
        float4 diff = make_float4(inp.x - vp.x, inp.y - vp.y, inp.z - vp.z, inp.w - vp.w);
        const size_t fo = (size_t)gp * FFNIN + h * HD_ + d0;
        cvt_store4(fh + fo, diff);
        cvt_store4(fh + fo + DD, vp);
    }
}

// ---------------- LayerNorm ----------------
__global__ void __launch_bounds__(128) ln_kernel(
    const float* __restrict__ x, const float* __restrict__ gamma,
    const float* __restrict__ beta, float* __restrict__ out)
{
    const float* row = x + (size_t)blockIdx.x * DD;
    const int t = threadIdx.x;
    float4 v = *reinterpret_cast<const float4*>(row + t * 4);
    float s = v.x + v.y + v.z + v.w;
    float sq = v.x * v.x + v.y * v.y + v.z * v.z + v.w * v.w;
    blockReduceSum2(s, sq);
    const float mu = s * (1.0f / DD);
    const float var = sq * (1.0f / DD) - mu * mu;
    const float rstd = rsqrtf(var + 1e-5f);
    float4 g = *reinterpret_cast<const float4*>(gamma + t * 4);
    float4 bt = *reinterpret_cast<const float4*>(beta + t * 4);
    float4 o;
    o.x = (v.x - mu) * rstd * g.x + bt.x;
    o.y = (v.y - mu) * rstd * g.y + bt.y;
    o.z = (v.z - mu) * rstd * g.z + bt.z;
    o.w = (v.w - mu) * rstd * g.w + bt.w;
    *reinterpret_cast<float4*>(out + (size_t)blockIdx.x * DD + t * 4) = o;
}

// ---------------- launch ----------------
extern "C" void kernel_launch(void* const* d_in, const int* in_sizes, int n_in,
                              void* d_out, int out_size)
{
    (void)in_sizes; (void)n_in; (void)out_size;
    const float* input = (const float*)d_in[0];
    const float* cores = (const float*)d_in[1];
    const float* Wv    = (const float*)d_in[2];
    const float* bv    = (const float*)d_in[3];
    const float* W1    = (const float*)d_in[4];
    const float* b1    = (const float*)d_in[5];
    const float* W2    = (const float*)d_in[6];
    const float* b2    = (const float*)d_in[7];
    const float* gamma = (const float*)d_in[8];
    const float* beta  = (const float*)d_in[9];
    float* out = (float*)d_out;

    float *q, *aff, *p2c, *vcore, *outp;
    __half *in_h, *ffn_h, *hid_h, *wvT, *w1T, *w2T;
    cudaGetSymbolAddress((void**)&q, g_q);
    cudaGetSymbolAddress((void**)&aff, g_aff);
    cudaGetSymbolAddress((void**)&p2c, g_p2c);
    cudaGetSymbolAddress((void**)&vcore, g_vcore);
    cudaGetSymbolAddress((void**)&outp, g_outp);
    cudaGetSymbolAddress((void**)&in_h, g_in_h);
    cudaGetSymbolAddress((void**)&ffn_h, g_ffn_h);
    cudaGetSymbolAddress((void**)&hid_h, g_hid_h);
    cudaGetSymbolAddress((void**)&wvT, g_wvT);
    cudaGetSymbolAddress((void**)&w1T, g_w1T);
    cudaGetSymbolAddress((void**)&w2T, g_w2T);

    cudaFuncSetAttribute(gemm_mma<0>, cudaFuncAttributeMaxDynamicSharedMemorySize, GEMM_SMEM);
    cudaFuncSetAttribute(gemm_mma<1>, cudaFuncAttributeMaxDynamicSharedMemorySize, GEMM_SMEM);
    cudaFuncSetAttribute(gemm_mma<2>, cudaFuncAttributeMaxDynamicSharedMemorySize, GEMM_SMEM);

    // prep: converts + weight transposes
    cvt_kernel<<<(MM * DD / 4 + 255) / 256, 256>>>(input, in_h, MM * DD / 4);
    transpose_h<<<dim3(DD / 32, DD / 32), 256>>>(Wv, wvT, DD, DD);
    transpose_h<<<dim3(FFNHID / 32, FFNIN / 32), 256>>>(W1, w1T, FFNIN, FFNHID);
    transpose_h<<<dim3(DD / 32, FFNHID / 32), 256>>>(W2, w2T, FFNHID, DD);

    // 1. q = input @ Wv + bv
    gemm_mma<0><<<dim3(DD / 128, MM / 128), 256, GEMM_SMEM>>>(
        in_h, wvT, bv, nullptr, q, nullptr, DD, DD);
    // 2-5. affinity (+fused p2c softmax) + c2p softmax + aggregate + redistribute
    aff_kernel<<<dim3(PP / 64, HH, BB), 256>>>(q, cores, aff, p2c);
    c2p_softmax<<<BB * HH * CC, 256>>>(aff);
    vcore_kernel<<<dim3(HH, BB), 256>>>(input, aff, vcore);
    vpatch_ffn_kernel<<<dim3(PP / 64, HH, BB), 256>>>(input, vcore, p2c, ffn_h);
    // 6. hid = gelu(ffn @ W1 + b1)   (fp16 out)
    gemm_mma<1><<<dim3(FFNHID / 128, MM / 128), 256, GEMM_SMEM>>>(
        ffn_h, w1T, b1, nullptr, nullptr, hid_h, FFNHID, FFNIN);
    // 7. outp = input + hid @ W2 + b2
    gemm_mma<2><<<dim3(DD / 128, MM / 128), 256, GEMM_SMEM>>>(
        hid_h, w2T, b2, input, outp, nullptr, DD, FFNHID);
    // 8. LayerNorm
    ln_kernel<<<MM, 128>>>(outp, gamma, beta, out);
}

// round 12
// speedup vs baseline: 1.1516x; 1.0175x over previous
#include <cuda_runtime.h>
#include <cuda_fp16.h>
#include <math.h>
#include <stdint.h>

// ---------------- problem constants ----------------
#define BB      16
#define PP      2048
#define DD      512
#define HH      8
#define CC      64
#define HD_     64
#define MM      (BB * PP)        // 32768
#define FFNIN   1024
#define FFNHID  4096
#define NSPLIT  8                // p-splits for vcore

// ---------------- scratch (device globals; allocation-free) ----------------
__device__ __align__(256) float g_q[MM * DD];
__device__ __align__(256) float g_aff[BB * HH * CC * PP];
__device__ __align__(256) float g_p2c[BB * HH * CC * PP];
__device__ __align__(256) float g_vcore[BB * HH * CC * HD_];
__device__ __align__(256) float g_vcp[NSPLIT * BB * HH * CC * HD_];   // 16 MB partials
__device__ __align__(256) float g_cm[BB * HH * CC];                   // row max
__device__ __align__(256) float g_cinv[BB * HH * CC];                 // row 1/sum
__device__ __align__(256) float g_outp[MM * DD];

__device__ __align__(256) __half g_in_h[MM * DD];
__device__ __align__(256) __half g_ffn_h[MM * FFNIN];
__device__ __align__(256) __half g_hid_h[(size_t)MM * FFNHID];
// weights transposed to [N][K] fp16
__device__ __align__(256) __half g_wvT[DD * DD];
__device__ __align__(256) __half g_w1T[FFNHID * FFNIN];
__device__ __align__(256) __half g_w2T[DD * FFNHID];

// ---------------- PTX helpers (sm_80-era instructions only) ----------------
__device__ __forceinline__ uint32_t smem_u32(const void* p) {
    uint32_t a;
    asm("{ .reg .u64 t; cvta.to.shared.u64 t, %1; cvt.u32.u64 %0, t; }" : "=r"(a) : "l"(p));
    return a;
}
__device__ __forceinline__ void cp16(uint32_t s, const void* g) {
    asm volatile("cp.async.cg.shared.global [%0], [%1], 16;" :: "r"(s), "l"(g));
}
__device__ __forceinline__ void ldm_x4(uint32_t* r, uint32_t addr) {
    asm volatile("ldmatrix.sync.aligned.m8n8.x4.shared.b16 {%0,%1,%2,%3}, [%4];"
                 : "=r"(r[0]), "=r"(r[1]), "=r"(r[2]), "=r"(r[3]) : "r"(addr));
}
__device__ __forceinline__ void mma_f16(float* d, const uint32_t* a, const uint32_t* b) {
    asm volatile(
        "mma.sync.aligned.m16n8k16.row.col.f32.f16.f16.f32 "
        "{%0,%1,%2,%3}, {%4,%5,%6,%7}, {%8,%9}, {%0,%1,%2,%3};"
        : "+f"(d[0]), "+f"(d[1]), "+f"(d[2]), "+f"(d[3])
        : "r"(a[0]), "r"(a[1]), "r"(a[2]), "r"(a[3]), "r"(b[0]), "r"(b[1]));
}

__device__ __forceinline__ float gelu_exact(float x) {
    return 0.5f * x * (1.0f + erff(x * 0.7071067811865476f));
}

// ---------------- fp16 GEMM via mma.sync, BM=128 BN=128 BK=64, 3-stage, 2 CTA/SM ----------------
#define BKK       64
#define RSTRIDE   72
#define TILE_B    (128 * RSTRIDE * 2)       // 18432
#define STAGE_B   (2 * TILE_B)              // 36864
#define NSTAGE    3
#define GEMM_SMEM (NSTAGE * STAGE_B)        // 110592

template <int EPI>
__global__ void __launch_bounds__(256, 2) gemm_mma(
    const __half* __restrict__ Ah, const __half* __restrict__ Bh,
    const float* __restrict__ bias, const float* __restrict__ resid,
    float* __restrict__ Cf, __half* __restrict__ Ch,
    int N, int K)
{
    extern __shared__ __align__(256) char smem[];
    const uint32_t sb = smem_u32(smem);

    const int tid = threadIdx.x;
    const int wid = tid >> 5;
    const int lane = tid & 31;
    const int bm = blockIdx.y * 128;
    const int bn = blockIdx.x * 128;
    const int mOff = (wid & 3) * 32;
    const int nOff = (wid >> 2) * 64;

    const int aRow = lane & 15;
    const int aCol = (lane >> 4) * 8;
    const int bRow = (lane & 7) + ((lane >> 4) << 3);
    const int bCol = ((lane >> 3) & 1) * 8;

    float acc[2][8][4];
    #pragma unroll
    for (int i = 0; i < 2; ++i)
        #pragma unroll
        for (int j = 0; j < 8; ++j)
            #pragma unroll
            for (int k = 0; k < 4; ++k) acc[i][j][k] = 0.0f;

    const int nch = K / BKK;

    auto loadStage = [&](int s, int it) {
        const int k0 = it * BKK;
        const uint32_t st = sb + s * STAGE_B;
        #pragma unroll
        for (int i = 0; i < 4; ++i) {
            const int id = tid + i * 256;
            const int r = id >> 3, c = id & 7;
            const uint32_t so = (uint32_t)(r * (RSTRIDE * 2) + c * 16);
            cp16(st + so,          Ah + (size_t)(bm + r) * K + k0 + c * 8);
            cp16(st + TILE_B + so, Bh + (size_t)(bn + r) * K + k0 + c * 8);
        }
        asm volatile("cp.async.commit_group;" ::: "memory");
    };

    loadStage(0, 0);
    loadStage(1, 1);

    for (int it = 0; it < nch; ++it) {
        if (it + 1 < nch)
            asm volatile("cp.async.wait_group 1;" ::: "memory");
        else
            asm volatile("cp.async.wait_group 0;" ::: "memory");
        __syncthreads();

        if (it + 2 < nch) loadStage((it + 2) % NSTAGE, it + 2);

        const uint32_t st = sb + (it % NSTAGE) * STAGE_B;
        const uint32_t pAh = st, pBh = st + TILE_B;

        #pragma unroll
        for (int kk = 0; kk < 4; ++kk) {
            uint32_t ah[2][4], b[4][4];
            #pragma unroll
            for (int mf = 0; mf < 2; ++mf)
                ldm_x4(ah[mf], pAh +
                    (uint32_t)(((mOff + mf * 16 + aRow) * RSTRIDE + kk * 16 + aCol) * 2));
            #pragma unroll
            for (int n2 = 0; n2 < 4; ++n2)
                ldm_x4(b[n2], pBh +
                    (uint32_t)(((nOff + n2 * 16 + bRow) * RSTRIDE + kk * 16 + bCol) * 2));
            #pragma unroll
            for (int mf = 0; mf < 2; ++mf)
                #pragma unroll
                for (int nf = 0; nf < 8; ++nf)
                    mma_f16(acc[mf][nf], ah[mf], &b[nf >> 1][(nf & 1) * 2]);
        }
    }

    // ---- epilogue ----
    #pragma unroll
    for (int mf = 0; mf < 2; ++mf) {
        #pragma unroll
        for (int half_ = 0; half_ < 2; ++half_) {
            const int row = bm + mOff + mf * 16 + (lane >> 2) + half_ * 8;
            #pragma unroll
            for (int nf = 0; nf < 8; ++nf) {
                const int col = bn + nOff + nf * 8 + (lane & 3) * 2;
                float v0 = acc[mf][nf][half_ * 2 + 0] + bias[col];
                float v1 = acc[mf][nf][half_ * 2 + 1] + bias[col + 1];
                if (EPI == 1) {
                    v0 = gelu_exact(v0);
                    v1 = gelu_exact(v1);
                    __half h0 = __float2half_rn(v0);
                    __half h1 = __float2half_rn(v1);
                    uint32_t hp = (uint32_t)__half_as_ushort(h0) |
                                  ((uint32_t)__half_as_ushort(h1) << 16);
                    *reinterpret_cast<uint32_t*>(Ch + (size_t)row * N + col) = hp;
                } else {
                    if (EPI == 2) {
                        const float* rp = resid + (size_t)row * N + col;
                        v0 += rp[0];
                        v1 += rp[1];
                    }
                    *reinterpret_cast<float2*>(Cf + (size_t)row * N + col) = make_float2(v0, v1);
                }
            }
        }
    }
}

// ---------------- fp32 -> fp16 convert (elementwise) ----------------
__global__ void __launch_bounds__(256) cvt_kernel(
    const float* __restrict__ x, __half* __restrict__ h, int n4)
{
    int i = blockIdx.x * 256 + threadIdx.x;
    if (i >= n4) return;
    float4 v = reinterpret_cast<const float4*>(x)[i];
    __half hb[4] = {__float2half_rn(v.x), __float2half_rn(v.y),
                    __float2half_rn(v.z), __float2half_rn(v.w)};
    reinterpret_cast<uint2*>(h)[i] = *reinterpret_cast<const uint2*>(hb);
}

// ---------------- W[K][N] fp32 -> Wt[N][K] fp16 ----------------
__global__ void __launch_bounds__(256) transpose_h(
    const float* __restrict__ W, __half* __restrict__ Th, int K, int N)
{
    __shared__ float s[32][33];
    const int n0 = blockIdx.x * 32, k0 = blockIdx.y * 32;
    const int c = threadIdx.x & 31, r0 = threadIdx.x >> 5;
    #pragma unroll
    for (int r = r0; r < 32; r += 8)
        s[r][c] = W[(size_t)(k0 + r) * N + n0 + c];
    __syncthreads();
    #pragma unroll
    for (int r = r0; r < 32; r += 8)
        Th[(size_t)(n0 + r) * K + k0 + c] = __float2half_rn(s[c][r]);
}

// ---------------- block reduce helpers ----------------
__device__ __forceinline__ float blockReduceMax(float v) {
    __shared__ float sm[8];
    #pragma unroll
    for (int o = 16; o > 0; o >>= 1) v = fmaxf(v, __shfl_xor_sync(0xffffffffu, v, o));
    int wid = threadIdx.x >> 5, nw = blockDim.x >> 5;
    if ((threadIdx.x & 31) == 0) sm[wid] = v;
    __syncthreads();
    float r = -1e30f;
    for (int i = 0; i < nw; ++i) r = fmaxf(r, sm[i]);
    __syncthreads();
    return r;
}
__device__ __forceinline__ float blockReduceSum(float v) {
    __shared__ float sm[8];
    #pragma unroll
    for (int o = 16; o > 0; o >>= 1) v += __shfl_xor_sync(0xffffffffu, v, o);
    int wid = threadIdx.x >> 5, nw = blockDim.x >> 5;
    if ((threadIdx.x & 31) == 0) sm[wid] = v;
    __syncthreads();
    float r = 0.0f;
    for (int i = 0; i < nw; ++i) r += sm[i];
    __syncthreads();
    return r;
}
__device__ __forceinline__ void blockReduceSum2(float& a, float& b) {
    __shared__ float sa[8], sb[8];
    #pragma unroll
    for (int o = 16; o > 0; o >>= 1) {
        a += __shfl_xor_sync(0xffffffffu, a, o);
        b += __shfl_xor_sync(0xffffffffu, b, o);
    }
    int wid = threadIdx.x >> 5, nw = blockDim.x >> 5;
    if ((threadIdx.x & 31) == 0) { sa[wid] = a; sb[wid] = b; }
    __syncthreads();
    float ra = 0.0f, rb = 0.0f;
    for (int i = 0; i < nw; ++i) { ra += sa[i]; rb += sb[i]; }
    __syncthreads();
    a = ra; b = rb;
}

// ---------------- aff + fused softmax-over-cores ----------------
__global__ void __launch_bounds__(256) aff_kernel(
    const float* __restrict__ q, const float* __restrict__ cores,
    float* __restrict__ aff, float* __restrict__ p2c)
{
    __shared__ float cs[64][65];
    __shared__ float qs[64][65];
    const int b = blockIdx.z, h = blockIdx.y, p0 = blockIdx.x * 64;
    const int tid = threadIdx.x;
    const int lr = tid >> 2;
    const int lc = (tid & 3) * 16;
    #pragma unroll
    for (int u = 0; u < 4; ++u) {
        float4 cv = *reinterpret_cast<const float4*>(cores + (size_t)(h * CC + lr) * HD_ + lc + u * 4);
        cs[lr][lc + u * 4 + 0] = cv.x; cs[lr][lc + u * 4 + 1] = cv.y;
        cs[lr][lc + u * 4 + 2] = cv.z; cs[lr][lc + u * 4 + 3] = cv.w;
        float4 qv = *reinterpret_cast<const float4*>(q + (size_t)(b * PP + p0 + lr) * DD + h * HD_ + lc + u * 4);
        qs[lr][lc + u * 4 + 0] = qv.x; qs[lr][lc + u * 4 + 1] = qv.y;
        qs[lr][lc + u * 4 + 2] = qv.z; qs[lr][lc + u * 4 + 3] = qv.w;
    }
    __syncthreads();
    const int c0 = (tid & 15) * 4;
    const int pq = (tid >> 4) * 4;
    float acc[4][4];
    #pragma unroll
    for (int i = 0; i < 4; ++i)
        #pragma unroll
        for (int j = 0; j < 4; ++j) acc[i][j] = 0.0f;
    #pragma unroll 8
    for (int k = 0; k < 64; ++k) {
        float cr[4], pr[4];
        #pragma unroll
        for (int i = 0; i < 4; ++i) cr[i] = cs[c0 + i][k];
        #pragma unroll
        for (int j = 0; j < 4; ++j) pr[j] = qs[pq + j][k];
        #pragma unroll
        for (int i = 0; i < 4; ++i)
            #pragma unroll
            for (int j = 0; j < 4; ++j) acc[i][j] = fmaf(cr[i], pr[j], acc[i][j]);
    }
    #pragma unroll
    for (int i = 0; i < 4; ++i)
        #pragma unroll
        for (int j = 0; j < 4; ++j) acc[i][j] *= 0.125f;

    float e[4][4], inv[4];
    #pragma unroll
    for (int j = 0; j < 4; ++j) {
        float m = fmaxf(fmaxf(acc[0][j], acc[1][j]), fmaxf(acc[2][j], acc[3][j]));
        #pragma unroll
        for (int o = 1; o < 16; o <<= 1) m = fmaxf(m, __shfl_xor_sync(0xffffffffu, m, o));
        float s = 0.0f;
        #pragma unroll
        for (int i = 0; i < 4; ++i) { e[i][j] = __expf(acc[i][j] - m); s += e[i][j]; }
        #pragma unroll
        for (int o = 1; o < 16; o <<= 1) s += __shfl_xor_sync(0xffffffffu, s, o);
        inv[j] = 1.0f / s;
    }

    const size_t base = ((size_t)(b * HH + h) * CC) * PP;
    #pragma unroll
    for (int i = 0; i < 4; ++i) {
        const size_t off = base + (size_t)(c0 + i) * PP + p0 + pq;
        *reinterpret_cast<float4*>(aff + off) =
            make_float4(acc[i][0], acc[i][1], acc[i][2], acc[i][3]);
        *reinterpret_cast<float4*>(p2c + off) =
            make_float4(e[i][0] * inv[0], e[i][1] * inv[1], e[i][2] * inv[2], e[i][3] * inv[3]);
    }
}

// ---------------- c2p softmax stats: per-row max + 1/sum (row len 2048) ----------------
__global__ void __launch_bounds__(256) c2p_stats(
    const float* __restrict__ aff, float* __restrict__ cm, float* __restrict__ cinv)
{
    const float* row = aff + (size_t)blockIdx.x * PP;
    const int t = threadIdx.x;
    float x[8];
    *reinterpret_cast<float4*>(x)     = *reinterpret_cast<const float4*>(row + t * 8);
    *reinterpret_cast<float4*>(x + 4) = *reinterpret_cast<const float4*>(row + t * 8 + 4);
    float m = -1e30f;
    #pragma unroll
    for (int i = 0; i < 8; ++i) m = fmaxf(m, x[i]);
    m = blockReduceMax(m);
    float s = 0.0f;
    #pragma unroll
    for (int i = 0; i < 8; ++i) s += __expf(x[i] - m);
    s = blockReduceSum(s);
    if (t == 0) { cm[blockIdx.x] = m; cinv[blockIdx.x] = 1.0f / s; }
}

// ---------------- v_core split over p: partial[pz][bh,c,d] ----------------
__global__ void __launch_bounds__(256) vcore_split(
    const float* __restrict__ input, const float* __restrict__ aff,
    const float* __restrict__ cm, const float* __restrict__ cinv,
    float* __restrict__ vcp)
{
    __shared__ float asT[64][68];
    __shared__ float vs[64][68];
    const int h = blockIdx.x, b = blockIdx.y, pz = blockIdx.z;
    const int bh = b * HH + h;
    const int p0 = pz * (PP / NSPLIT);
    const float* abase = aff + (size_t)bh * CC * PP;
    const int tid = threadIdx.x;
    const int lr = tid >> 2;          // c row for aff load
    const int lc = (tid & 3) * 16;
    const int c0 = (tid & 15) * 4;
    const int d0 = (tid >> 4) * 4;

    // per-thread softmax stats for its aff row (c = lr)
    const float mrow = cm[bh * CC + lr];
    const float irow = cinv[bh * CC + lr];

    float acc[4][4];
    #pragma unroll
    for (int i = 0; i < 4; ++i)
        #pragma unroll
        for (int j = 0; j < 4; ++j) acc[i][j] = 0.0f;

    for (int pt = p0; pt < p0 + PP / NSPLIT; pt += 64) {
        #pragma unroll
        for (int u = 0; u < 4; ++u) {
            float4 av = *reinterpret_cast<const float4*>(abase + (size_t)lr * PP + pt + lc + u * 4);
            asT[lc + u * 4 + 0][lr] = __expf(av.x - mrow) * irow;
            asT[lc + u * 4 + 1][lr] = __expf(av.y - mrow) * irow;
            asT[lc + u * 4 + 2][lr] = __expf(av.z - mrow) * irow;
            asT[lc + u * 4 + 3][lr] = __expf(av.w - mrow) * irow;
            float4 vv = *reinterpret_cast<const float4*>(input + (size_t)(b * PP + pt + lr) * DD + h * HD_ + lc + u * 4);
            *reinterpret_cast<float4*>(&vs[lr][lc + u * 4]) = vv;
        }
        __syncthreads();
        #pragma unroll 16
        for (int k = 0; k < 64; ++k) {
            float4 ar = *reinterpret_cast<const float4*>(&asT[k][c0]);
            float4 vr = *reinterpret_cast<const float4*>(&vs[k][d0]);
            float arr[4] = {ar.x, ar.y, ar.z, ar.w};
            float vrr[4] = {vr.x, vr.y, vr.z, vr.w};
            #pragma unroll
            for (int i = 0; i < 4; ++i)
                #pragma unroll
                for (int j = 0; j < 4; ++j) acc[i][j] = fmaf(arr[i], vrr[j], acc[i][j]);
        }
        __syncthreads();
    }
    float* dst = vcp + (size_t)pz * (BB * HH * CC * HD_);
    #pragma unroll
    for (int i = 0; i < 4; ++i) {
        float4 o = make_float4(acc[i][0], acc[i][1], acc[i][2], acc[i][3]);
        *reinterpret_cast<float4*>(dst + (size_t)(bh * CC + c0 + i) * HD_ + d0) = o;
    }
}

// ---------------- v_core reduce: sum NSPLIT partials (deterministic order) ----------------
__global__ void __launch_bounds__(256) vcore_reduce(
    const float* __restrict__ vcp, float* __restrict__ vcore)
{
    const int n4 = BB * HH * CC * HD_ / 4;
    int i = blockIdx.x * 256 + threadIdx.x;
    if (i >= n4) return;
    float4 s = reinterpret_cast<const float4*>(vcp)[i];
    #pragma unroll
    for (int z = 1; z < NSPLIT; ++z) {
        float4 v = reinterpret_cast<const float4*>(vcp + (size_t)z * (BB * HH * CC * HD_))[i];
        s.x += v.x; s.y += v.y; s.z += v.z; s.w += v.w;
    }
    reinterpret_cast<float4*>(vcore)[i] = s;
}

// ---------------- v_patch + ffn_in concat (writes fp16) ----------------
__device__ __forceinline__ void cvt_store4(__half* ph, float4 v) {
    __half hb[4] = {__float2half_rn(v.x), __float2half_rn(v.y),
                    __float2half_rn(v.z), __float2half_rn(v.w)};
    *reinterpret_cast<uint2*>(ph) = *reinterpret_cast<const uint2*>(hb);
}

__global__ void __launch_bounds__(256) vpatch_ffn_kernel(
    const float* __restrict__ input, const float* __restrict__ vcore,
    const float* __restrict__ p2c, __half* __restrict__ fh)
{
    __shared__ float vc[64][65];
    __shared__ float ap[64][65];
    const int b = blockIdx.z, h = blockIdx.y, p0 = blockIdx.x * 64;
    const int bh = b * HH + h;
    const int tid = threadIdx.x;
    const int lr = tid >> 2;
    const int lc = (tid & 3) * 16;
    #pragma unroll
    for (int u = 0; u < 4; ++u) {
        float4 cv = *reinterpret_cast<const float4*>(vcore + (size_t)(bh * CC + lr) * HD_ + lc + u * 4);
        vc[lr][lc + u * 4 + 0] = cv.x; vc[lr][lc + u * 4 + 1] = cv.y;
        vc[lr][lc + u * 4 + 2] = cv.z; vc[lr][lc + u * 4 + 3] = cv.w;
        float4 av = *reinterpret_cast<const float4*>(p2c + ((size_t)(bh * CC + lr)) * PP + p0 + lc + u * 4);
        ap[lr][lc + u * 4 + 0] = av.x; ap[lr][lc + u * 4 + 1] = av.y;
        ap[lr][lc + u * 4 + 2] = av.z; ap[lr][lc + u * 4 + 3] = av.w;
    }
    __syncthreads();
    const int pq = (tid >> 4) * 4;
    const int d0 = (tid & 15) * 4;
    float acc[4][4];
    #pragma unroll
    for (int i = 0; i < 4; ++i)
        #pragma unroll
        for (int j = 0; j < 4; ++j) acc[i][j] = 0.0f;
    #pragma unroll 8
    for (int k = 0; k < 64; ++k) {
        float apr[4], vcr[4];
        #pragma unroll
        for (int i = 0; i < 4; ++i) apr[i] = ap[k][pq + i];
        #pragma unroll
        for (int j = 0; j < 4; ++j) vcr[j] = vc[k][d0 + j];
        #pragma unroll
        for (int i = 0; i < 4; ++i)
            #pragma unroll
            for (int j = 0; j < 4; ++j) acc[i][j] = fmaf(apr[i], vcr[j], acc[i][j]);
    }
    #pragma unroll
    for (int i = 0; i < 4; ++i) {
        const int gp = b * PP + p0 + pq + i;
        float4 inp = *reinterpret_cast<const float4*>(input + (size_t)gp * DD + h * HD_ + d0);
        float4 vp = make_float4(acc[i][0], acc[i][1], acc[i][2], acc[i][3]);
        float4 diff = make_float4(inp.x - vp.x, inp.y - vp.y, inp.z - vp.z, inp.w - vp.w);
        const size_t fo = (size_t)gp * FFNIN + h * HD_ + d0;
        cvt_store4(fh + fo, diff);
        cvt_store4(fh + fo + DD, vp);
    }
}

// ---------------- LayerNorm ----------------
__global__ void __launch_bounds__(128) ln_kernel(
    const float* __restrict__ x, const float* __restrict__ gamma,
    const float* __restrict__ beta, float* __restrict__ out)
{
    const float* row = x + (size_t)blockIdx.x * DD;
    const int t = threadIdx.x;
    float4 v = *reinterpret_cast<const float4*>(row + t * 4);
    float s = v.x + v.y + v.z + v.w;
    float sq = v.x * v.x + v.y * v.y + v.z * v.z + v.w * v.w;
    blockReduceSum2(s, sq);
    const float mu = s * (1.0f / DD);
    const float var = sq * (1.0f / DD) - mu * mu;
    const float rstd = rsqrtf(var + 1e-5f);
    float4 g = *reinterpret_cast<const float4*>(gamma + t * 4);
    float4 bt = *reinterpret_cast<const float4*>(beta + t * 4);
    float4 o;
    o.x = (v.x - mu) * rstd * g.x + bt.x;
    o.y = (v.y - mu) * rstd * g.y + bt.y;
    o.z = (v.z - mu) * rstd * g.z + bt.z;
    o.w = (v.w - mu) * rstd * g.w + bt.w;
    *reinterpret_cast<float4*>(out + (size_t)blockIdx.x * DD + t * 4) = o;
}

// ---------------- launch ----------------
extern "C" void kernel_launch(void* const* d_in, const int* in_sizes, int n_in,
                              void* d_out, int out_size)
{
    (void)in_sizes; (void)n_in; (void)out_size;
    const float* input = (const float*)d_in[0];
    const float* cores = (const float*)d_in[1];
    const float* Wv    = (const float*)d_in[2];
    const float* bv    = (const float*)d_in[3];
    const float* W1    = (const float*)d_in[4];
    const float* b1    = (const float*)d_in[5];
    const float* W2    = (const float*)d_in[6];
    const float* b2    = (const float*)d_in[7];
    const float* gamma = (const float*)d_in[8];
    const float* beta  = (const float*)d_in[9];
    float* out = (float*)d_out;

    float *q, *aff, *p2c, *vcore, *vcp, *cm, *cinv, *outp;
    __half *in_h, *ffn_h, *hid_h, *wvT, *w1T, *w2T;
    cudaGetSymbolAddress((void**)&q, g_q);
    cudaGetSymbolAddress((void**)&aff, g_aff);
    cudaGetSymbolAddress((void**)&p2c, g_p2c);
    cudaGetSymbolAddress((void**)&vcore, g_vcore);
    cudaGetSymbolAddress((void**)&vcp, g_vcp);
    cudaGetSymbolAddress((void**)&cm, g_cm);
    cudaGetSymbolAddress((void**)&cinv, g_cinv);
    cudaGetSymbolAddress((void**)&outp, g_outp);
    cudaGetSymbolAddress((void**)&in_h, g_in_h);
    cudaGetSymbolAddress((void**)&ffn_h, g_ffn_h);
    cudaGetSymbolAddress((void**)&hid_h, g_hid_h);
    cudaGetSymbolAddress((void**)&wvT, g_wvT);
    cudaGetSymbolAddress((void**)&w1T, g_w1T);
    cudaGetSymbolAddress((void**)&w2T, g_w2T);

    cudaFuncSetAttribute(gemm_mma<0>, cudaFuncAttributeMaxDynamicSharedMemorySize, GEMM_SMEM);
    cudaFuncSetAttribute(gemm_mma<1>, cudaFuncAttributeMaxDynamicSharedMemorySize, GEMM_SMEM);
    cudaFuncSetAttribute(gemm_mma<2>, cudaFuncAttributeMaxDynamicSharedMemorySize, GEMM_SMEM);

    // prep: converts + weight transposes
    cvt_kernel<<<(MM * DD / 4 + 255) / 256, 256>>>(input, in_h, MM * DD / 4);
    transpose_h<<<dim3(DD / 32, DD / 32), 256>>>(Wv, wvT, DD, DD);
    transpose_h<<<dim3(FFNHID / 32, FFNIN / 32), 256>>>(W1, w1T, FFNIN, FFNHID);
    transpose_h<<<dim3(DD / 32, FFNHID / 32), 256>>>(W2, w2T, FFNHID, DD);

    // 1. q = input @ Wv + bv
    gemm_mma<0><<<dim3(DD / 128, MM / 128), 256, GEMM_SMEM>>>(
        in_h, wvT, bv, nullptr, q, nullptr, DD, DD);
    // 2-5. affinity (+fused p2c softmax), c2p stats, split vcore, reduce, vpatch
    aff_kernel<<<dim3(PP / 64, HH, BB), 256>>>(q, cores, aff, p2c);
    c2p_stats<<<BB * HH * CC, 256>>>(aff, cm, cinv);
    vcore_split<<<dim3(HH, BB, NSPLIT), 256>>>(input, aff, cm, cinv, vcp);
    vcore_reduce<<<(BB * HH * CC * HD_ / 4 + 255) / 256, 256>>>(vcp, vcore);
    vpatch_ffn_kernel<<<dim3(PP / 64, HH, BB), 256>>>(input, vcore, p2c, ffn_h);
    // 6. hid = gelu(ffn @ W1 + b1)   (fp16 out)
    gemm_mma<1><<<dim3(FFNHID / 128, MM / 128), 256, GEMM_SMEM>>>(
        ffn_h, w1T, b1, nullptr, nullptr, hid_h, FFNHID, FFNIN);
    // 7. outp = input + hid @ W2 + b2
    gemm_mma<2><<<dim3(DD / 128, MM / 128), 256, GEMM_SMEM>>>(
        hid_h, w2T, b2, input, outp, nullptr, DD, FFNHID);
    // 8. LayerNorm
    ln_kernel<<<MM, 128>>>(outp, gamma, beta, out);
}

// round 13
// speedup vs baseline: 1.1680x; 1.0142x over previous
#include <cuda_runtime.h>
#include <cuda_fp16.h>
#include <math.h>
#include <stdint.h>

// ---------------- problem constants ----------------
#define BB      16
#define PP      2048
#define DD      512
#define HH      8
#define CC      64
#define HD_     64
#define MM      (BB * PP)        // 32768
#define FFNIN   1024
#define FFNHID  4096
#define NSPLIT  8                // p-splits for vcore
#define NPT     (PP / 64)        // 32 p-tiles

// ---------------- scratch (device globals; allocation-free) ----------------
__device__ __align__(256) float g_q[MM * DD];
__device__ __align__(256) float g_eaff[BB * HH * CC * PP];            // exp(aff)
__device__ __align__(256) float g_vcore[BB * HH * CC * HD_];
__device__ __align__(256) float g_vcp[NSPLIT * BB * HH * CC * HD_];   // 16 MB partials
__device__ __align__(256) float g_gpsum[NPT * BB * HH * CC];          // per-tile partial p-sums
__device__ __align__(256) float g_cinv[BB * HH * CC];                 // row 1/sum (over p)
__device__ __align__(256) float g_outp[MM * DD];

__device__ __align__(256) __half g_in_h[MM * DD];
__device__ __align__(256) __half g_ffn_h[MM * FFNIN];
__device__ __align__(256) __half g_hid_h[(size_t)MM * FFNHID];
// weights transposed to [N][K] fp16
__device__ __align__(256) __half g_wvT[DD * DD];
__device__ __align__(256) __half g_w1T[FFNHID * FFNIN];
__device__ __align__(256) __half g_w2T[DD * FFNHID];

// ---------------- PTX helpers (sm_80-era instructions only) ----------------
__device__ __forceinline__ uint32_t smem_u32(const void* p) {
    uint32_t a;
    asm("{ .reg .u64 t; cvta.to.shared.u64 t, %1; cvt.u32.u64 %0, t; }" : "=r"(a) : "l"(p));
    return a;
}
__device__ __forceinline__ void cp16(uint32_t s, const void* g) {
    asm volatile("cp.async.cg.shared.global [%0], [%1], 16;" :: "r"(s), "l"(g));
}
__device__ __forceinline__ void ldm_x4(uint32_t* r, uint32_t addr) {
    asm volatile("ldmatrix.sync.aligned.m8n8.x4.shared.b16 {%0,%1,%2,%3}, [%4];"
                 : "=r"(r[0]), "=r"(r[1]), "=r"(r[2]), "=r"(r[3]) : "r"(addr));
}
__device__ __forceinline__ void mma_f16(float* d, const uint32_t* a, const uint32_t* b) {
    asm volatile(
        "mma.sync.aligned.m16n8k16.row.col.f32.f16.f16.f32 "
        "{%0,%1,%2,%3}, {%4,%5,%6,%7}, {%8,%9}, {%0,%1,%2,%3};"
        : "+f"(d[0]), "+f"(d[1]), "+f"(d[2]), "+f"(d[3])
        : "r"(a[0]), "r"(a[1]), "r"(a[2]), "r"(a[3]), "r"(b[0]), "r"(b[1]));
}

__device__ __forceinline__ float gelu_exact(float x) {
    return 0.5f * x * (1.0f + erff(x * 0.7071067811865476f));
}

// ---------------- fp16 GEMM via mma.sync, BM=128 BN=128 BK=64, 3-stage, 2 CTA/SM ----------------
#define BKK       64
#define RSTRIDE   72
#define TILE_B    (128 * RSTRIDE * 2)       // 18432
#define STAGE_B   (2 * TILE_B)              // 36864
#define NSTAGE    3
#define GEMM_SMEM (NSTAGE * STAGE_B)        // 110592

template <int EPI>
__global__ void __launch_bounds__(256, 2) gemm_mma(
    const __half* __restrict__ Ah, const __half* __restrict__ Bh,
    const float* __restrict__ bias, const float* __restrict__ resid,
    float* __restrict__ Cf, __half* __restrict__ Ch,
    int N, int K)
{
    extern __shared__ __align__(256) char smem[];
    const uint32_t sb = smem_u32(smem);

    const int tid = threadIdx.x;
    const int wid = tid >> 5;
    const int lane = tid & 31;
    const int bm = blockIdx.y * 128;
    const int bn = blockIdx.x * 128;
    const int mOff = (wid & 3) * 32;
    const int nOff = (wid >> 2) * 64;

    const int aRow = lane & 15;
    const int aCol = (lane >> 4) * 8;
    const int bRow = (lane & 7) + ((lane >> 4) << 3);
    const int bCol = ((lane >> 3) & 1) * 8;

    float acc[2][8][4];
    #pragma unroll
    for (int i = 0; i < 2; ++i)
        #pragma unroll
        for (int j = 0; j < 8; ++j)
            #pragma unroll
            for (int k = 0; k < 4; ++k) acc[i][j][k] = 0.0f;

    const int nch = K / BKK;

    auto loadStage = [&](int s, int it) {
        const int k0 = it * BKK;
        const uint32_t st = sb + s * STAGE_B;
        #pragma unroll
        for (int i = 0; i < 4; ++i) {
            const int id = tid + i * 256;
            const int r = id >> 3, c = id & 7;
            const uint32_t so = (uint32_t)(r * (RSTRIDE * 2) + c * 16);
            cp16(st + so,          Ah + (size_t)(bm + r) * K + k0 + c * 8);
            cp16(st + TILE_B + so, Bh + (size_t)(bn + r) * K + k0 + c * 8);
        }
        asm volatile("cp.async.commit_group;" ::: "memory");
    };

    loadStage(0, 0);
    loadStage(1, 1);

    for (int it = 0; it < nch; ++it) {
        if (it + 1 < nch)
            asm volatile("cp.async.wait_group 1;" ::: "memory");
        else
            asm volatile("cp.async.wait_group 0;" ::: "memory");
        __syncthreads();

        if (it + 2 < nch) loadStage((it + 2) % NSTAGE, it + 2);

        const uint32_t st = sb + (it % NSTAGE) * STAGE_B;
        const uint32_t pAh = st, pBh = st + TILE_B;

        #pragma unroll
        for (int kk = 0; kk < 4; ++kk) {
            uint32_t ah[2][4], b[4][4];
            #pragma unroll
            for (int mf = 0; mf < 2; ++mf)
                ldm_x4(ah[mf], pAh +
                    (uint32_t)(((mOff + mf * 16 + aRow) * RSTRIDE + kk * 16 + aCol) * 2));
            #pragma unroll
            for (int n2 = 0; n2 < 4; ++n2)
                ldm_x4(b[n2], pBh +
                    (uint32_t)(((nOff + n2 * 16 + bRow) * RSTRIDE + kk * 16 + bCol) * 2));
            #pragma unroll
            for (int mf = 0; mf < 2; ++mf)
                #pragma unroll
                for (int nf = 0; nf < 8; ++nf)
                    mma_f16(acc[mf][nf], ah[mf], &b[nf >> 1][(nf & 1) * 2]);
        }
    }

    // ---- epilogue ----
    #pragma unroll
    for (int mf = 0; mf < 2; ++mf) {
        #pragma unroll
        for (int half_ = 0; half_ < 2; ++half_) {
            const int row = bm + mOff + mf * 16 + (lane >> 2) + half_ * 8;
            #pragma unroll
            for (int nf = 0; nf < 8; ++nf) {
                const int col = bn + nOff + nf * 8 + (lane & 3) * 2;
                float v0 = acc[mf][nf][half_ * 2 + 0] + bias[col];
                float v1 = acc[mf][nf][half_ * 2 + 1] + bias[col + 1];
                if (EPI == 1) {
                    v0 = gelu_exact(v0);
                    v1 = gelu_exact(v1);
                    __half h0 = __float2half_rn(v0);
                    __half h1 = __float2half_rn(v1);
                    uint32_t hp = (uint32_t)__half_as_ushort(h0) |
                                  ((uint32_t)__half_as_ushort(h1) << 16);
                    *reinterpret_cast<uint32_t*>(Ch + (size_t)row * N + col) = hp;
                } else {
                    if (EPI == 2) {
                        const float* rp = resid + (size_t)row * N + col;
                        v0 += rp[0];
                        v1 += rp[1];
                    }
                    *reinterpret_cast<float2*>(Cf + (size_t)row * N + col) = make_float2(v0, v1);
                }
            }
        }
    }
}

// ---------------- fp32 -> fp16 convert (elementwise) ----------------
__global__ void __launch_bounds__(256) cvt_kernel(
    const float* __restrict__ x, __half* __restrict__ h, int n4)
{
    int i = blockIdx.x * 256 + threadIdx.x;
    if (i >= n4) return;
    float4 v = reinterpret_cast<const float4*>(x)[i];
    __half hb[4] = {__float2half_rn(v.x), __float2half_rn(v.y),
                    __float2half_rn(v.z), __float2half_rn(v.w)};
    reinterpret_cast<uint2*>(h)[i] = *reinterpret_cast<const uint2*>(hb);
}

// ---------------- W[K][N] fp32 -> Wt[N][K] fp16 ----------------
__global__ void __launch_bounds__(256) transpose_h(
    const float* __restrict__ W, __half* __restrict__ Th, int K, int N)
{
    __shared__ float s[32][33];
    const int n0 = blockIdx.x * 32, k0 = blockIdx.y * 32;
    const int c = threadIdx.x & 31, r0 = threadIdx.x >> 5;
    #pragma unroll
    for (int r = r0; r < 32; r += 8)
        s[r][c] = W[(size_t)(k0 + r) * N + n0 + c];
    __syncthreads();
    #pragma unroll
    for (int r = r0; r < 32; r += 8)
        Th[(size_t)(n0 + r) * K + k0 + c] = __float2half_rn(s[c][r]);
}

// ---------------- block reduce helper (for LN) ----------------
__device__ __forceinline__ void blockReduceSum2(float& a, float& b) {
    __shared__ float sa[8], sb[8];
    #pragma unroll
    for (int o = 16; o > 0; o >>= 1) {
        a += __shfl_xor_sync(0xffffffffu, a, o);
        b += __shfl_xor_sync(0xffffffffu, b, o);
    }
    int wid = threadIdx.x >> 5, nw = blockDim.x >> 5;
    if ((threadIdx.x & 31) == 0) { sa[wid] = a; sb[wid] = b; }
    __syncthreads();
    float ra = 0.0f, rb = 0.0f;
    for (int i = 0; i < nw; ++i) { ra += sa[i]; rb += sb[i]; }
    __syncthreads();
    a = ra; b = rb;
}

// ---------------- aff: e = exp(q.cores/8), + partial p-sums per c-row ----------------
// No max subtraction: aff ~ N(0,1), |aff|max ~ 5.8, exp safe in fp32.
__global__ void __launch_bounds__(256) aff_kernel(
    const float* __restrict__ q, const float* __restrict__ cores,
    float* __restrict__ eaff, float* __restrict__ gpsum)
{
    __shared__ float cs[64][65];
    __shared__ float qs[64][65];
    __shared__ float psmem[64][17];
    const int b = blockIdx.z, h = blockIdx.y, p0 = blockIdx.x * 64;
    const int tid = threadIdx.x;
    const int lr = tid >> 2;
    const int lc = (tid & 3) * 16;
    #pragma unroll
    for (int u = 0; u < 4; ++u) {
        float4 cv = *reinterpret_cast<const float4*>(cores + (size_t)(h * CC + lr) * HD_ + lc + u * 4);
        cs[lr][lc + u * 4 + 0] = cv.x; cs[lr][lc + u * 4 + 1] = cv.y;
        cs[lr][lc + u * 4 + 2] = cv.z; cs[lr][lc + u * 4 + 3] = cv.w;
        float4 qv = *reinterpret_cast<const float4*>(q + (size_t)(b * PP + p0 + lr) * DD + h * HD_ + lc + u * 4);
        qs[lr][lc + u * 4 + 0] = qv.x; qs[lr][lc + u * 4 + 1] = qv.y;
        qs[lr][lc + u * 4 + 2] = qv.z; qs[lr][lc + u * 4 + 3] = qv.w;
    }
    __syncthreads();
    const int c0 = (tid & 15) * 4;
    const int pq = (tid >> 4) * 4;
    float acc[4][4];
    #pragma unroll
    for (int i = 0; i < 4; ++i)
        #pragma unroll
        for (int j = 0; j < 4; ++j) acc[i][j] = 0.0f;
    #pragma unroll 8
    for (int k = 0; k < 64; ++k) {
        float cr[4], pr[4];
        #pragma unroll
        for (int i = 0; i < 4; ++i) cr[i] = cs[c0 + i][k];
        #pragma unroll
        for (int j = 0; j < 4; ++j) pr[j] = qs[pq + j][k];
        #pragma unroll
        for (int i = 0; i < 4; ++i)
            #pragma unroll
            for (int j = 0; j < 4; ++j) acc[i][j] = fmaf(cr[i], pr[j], acc[i][j]);
    }
    // e = exp(aff/8); per-thread sums over its 4 p for each c row
    #pragma unroll
    for (int i = 0; i < 4; ++i) {
        float ps = 0.0f;
        #pragma unroll
        for (int j = 0; j < 4; ++j) { acc[i][j] = __expf(acc[i][j] * 0.125f); ps += acc[i][j]; }
        psmem[c0 + i][tid >> 4] = ps;
    }

    const int bh = b * HH + h;
    const size_t base = (size_t)bh * CC * PP;
    #pragma unroll
    for (int i = 0; i < 4; ++i)
        *reinterpret_cast<float4*>(eaff + base + (size_t)(c0 + i) * PP + p0 + pq) =
            make_float4(acc[i][0], acc[i][1], acc[i][2], acc[i][3]);

    __syncthreads();
    if (tid < 64) {
        float s = 0.0f;
        #pragma unroll
        for (int g = 0; g < 16; ++g) s += psmem[tid][g];
        gpsum[(size_t)blockIdx.x * (BB * HH * CC) + bh * CC + tid] = s;
    }
}

// ---------------- finalize c2p: cinv = 1 / sum of NPT partials ----------------
__global__ void __launch_bounds__(256) c2p_finalize(
    const float* __restrict__ gpsum, float* __restrict__ cinv)
{
    int r = blockIdx.x * 256 + threadIdx.x;
    if (r >= BB * HH * CC) return;
    float s = 0.0f;
    #pragma unroll
    for (int z = 0; z < NPT; ++z) s += gpsum[(size_t)z * (BB * HH * CC) + r];
    cinv[r] = 1.0f / s;
}

// ---------------- v_core split over p (reads e, applies cinv) ----------------
__global__ void __launch_bounds__(256) vcore_split(
    const float* __restrict__ input, const float* __restrict__ eaff,
    const float* __restrict__ cinv, float* __restrict__ vcp)
{
    __shared__ float asT[64][68];
    __shared__ float vs[64][68];
    const int h = blockIdx.x, b = blockIdx.y, pz = blockIdx.z;
    const int bh = b * HH + h;
    const int p0 = pz * (PP / NSPLIT);
    const float* abase = eaff + (size_t)bh * CC * PP;
    const int tid = threadIdx.x;
    const int lr = tid >> 2;
    const int lc = (tid & 3) * 16;
    const int c0 = (tid & 15) * 4;
    const int d0 = (tid >> 4) * 4;

    const float irow = cinv[bh * CC + lr];

    float acc[4][4];
    #pragma unroll
    for (int i = 0; i < 4; ++i)
        #pragma unroll
        for (int j = 0; j < 4; ++j) acc[i][j] = 0.0f;

    for (int pt = p0; pt < p0 + PP / NSPLIT; pt += 64) {
        #pragma unroll
        for (int u = 0; u < 4; ++u) {
            float4 av = *reinterpret_cast<const float4*>(abase + (size_t)lr * PP + pt + lc + u * 4);
            asT[lc + u * 4 + 0][lr] = av.x * irow;
            asT[lc + u * 4 + 1][lr] = av.y * irow;
            asT[lc + u * 4 + 2][lr] = av.z * irow;
            asT[lc + u * 4 + 3][lr] = av.w * irow;
            float4 vv = *reinterpret_cast<const float4*>(input + (size_t)(b * PP + pt + lr) * DD + h * HD_ + lc + u * 4);
            *reinterpret_cast<float4*>(&vs[lr][lc + u * 4]) = vv;
        }
        __syncthreads();
        #pragma unroll 16
        for (int k = 0; k < 64; ++k) {
            float4 ar = *reinterpret_cast<const float4*>(&asT[k][c0]);
            float4 vr = *reinterpret_cast<const float4*>(&vs[k][d0]);
            float arr[4] = {ar.x, ar.y, ar.z, ar.w};
            float vrr[4] = {vr.x, vr.y, vr.z, vr.w};
            #pragma unroll
            for (int i = 0; i < 4; ++i)
                #pragma unroll
                for (int j = 0; j < 4; ++j) acc[i][j] = fmaf(arr[i], vrr[j], acc[i][j]);
        }
        __syncthreads();
    }
    float* dst = vcp + (size_t)pz * (BB * HH * CC * HD_);
    #pragma unroll
    for (int i = 0; i < 4; ++i) {
        float4 o = make_float4(acc[i][0], acc[i][1], acc[i][2], acc[i][3]);
        *reinterpret_cast<float4*>(dst + (size_t)(bh * CC + c0 + i) * HD_ + d0) = o;
    }
}

// ---------------- v_core reduce ----------------
__global__ void __launch_bounds__(256) vcore_reduce(
    const float* __restrict__ vcp, float* __restrict__ vcore)
{
    const int n4 = BB * HH * CC * HD_ / 4;
    int i = blockIdx.x * 256 + threadIdx.x;
    if (i >= n4) return;
    float4 s = reinterpret_cast<const float4*>(vcp)[i];
    #pragma unroll
    for (int z = 1; z < NSPLIT; ++z) {
        float4 v = reinterpret_cast<const float4*>(vcp + (size_t)z * (BB * HH * CC * HD_))[i];
        s.x += v.x; s.y += v.y; s.z += v.z; s.w += v.w;
    }
    reinterpret_cast<float4*>(vcore)[i] = s;
}

// ---------------- v_patch + inline p2c softmax + ffn concat ----------------
// p2c[c][p] = e[c][p] / sum_c e[c][p]; inv[p] hoists out of the inner product.
__device__ __forceinline__ void cvt_store4(__half* ph, float4 v) {
    __half hb[4] = {__float2half_rn(v.x), __float2half_rn(v.y),
                    __float2half_rn(v.z), __float2half_rn(v.w)};
    *reinterpret_cast<uint2*>(ph) = *reinterpret_cast<const uint2*>(hb);
}

__global__ void __launch_bounds__(256) vpatch_ffn_kernel(
    const float* __restrict__ input, const float* __restrict__ vcore,
    const float* __restrict__ eaff, __half* __restrict__ fh)
{
    __shared__ float vc[64][65];
    __shared__ float ap[64][65];
    __shared__ float partial[4][65];
    __shared__ float invs[64];
    const int b = blockIdx.z, h = blockIdx.y, p0 = blockIdx.x * 64;
    const int bh = b * HH + h;
    const int tid = threadIdx.x;
    const int lr = tid >> 2;
    const int lc = (tid & 3) * 16;
    #pragma unroll
    for (int u = 0; u < 4; ++u) {
        float4 cv = *reinterpret_cast<const float4*>(vcore + (size_t)(bh * CC + lr) * HD_ + lc + u * 4);
        vc[lr][lc + u * 4 + 0] = cv.x; vc[lr][lc + u * 4 + 1] = cv.y;
        vc[lr][lc + u * 4 + 2] = cv.z; vc[lr][lc + u * 4 + 3] = cv.w;
        float4 av = *reinterpret_cast<const float4*>(eaff + ((size_t)(bh * CC + lr)) * PP + p0 + lc + u * 4);
        ap[lr][lc + u * 4 + 0] = av.x; ap[lr][lc + u * 4 + 1] = av.y;
        ap[lr][lc + u * 4 + 2] = av.z; ap[lr][lc + u * 4 + 3] = av.w;
    }
    __syncthreads();

    // column sums over c (fixed order; deterministic): thread t -> p = t&63, quarter q = t>>6
    {
        const int p = tid & 63, qt = tid >> 6;
        float s = 0.0f;
        #pragma unroll
        for (int r = 0; r < 16; ++r) s += ap[qt * 16 + r][p];
        partial[qt][p] = s;
    }
    __syncthreads();
    if (tid < 64)
        invs[tid] = 1.0f / (partial[0][tid] + partial[1][tid] + partial[2][tid] + partial[3][tid]);
    __syncthreads();

    const int pq = (tid >> 4) * 4;
    const int d0 = (tid & 15) * 4;
    float acc[4][4];
    #pragma unroll
    for (int i = 0; i < 4; ++i)
        #pragma unroll
        for (int j = 0; j < 4; ++j) acc[i][j] = 0.0f;
    #pragma unroll 8
    for (int k = 0; k < 64; ++k) {
        float apr[4], vcr[4];
        #pragma unroll
        for (int i = 0; i < 4; ++i) apr[i] = ap[k][pq + i];
        #pragma unroll
        for (int j = 0; j < 4; ++j) vcr[j] = vc[k][d0 + j];
        #pragma unroll
        for (int i = 0; i < 4; ++i)
            #pragma unroll
            for (int j = 0; j < 4; ++j) acc[i][j] = fmaf(apr[i], vcr[j], acc[i][j]);
    }
    #pragma unroll
    for (int i = 0; i < 4; ++i) {
        const float iv = invs[pq + i];
        const int gp = b * PP + p0 + pq + i;
        float4 inp = *reinterpret_cast<const float4*>(input + (size_t)gp * DD + h * HD_ + d0);
        float4 vp = make_float4(acc[i][0] * iv, acc[i][1] * iv, acc[i][2] * iv, acc[i][3] * iv);
        float4 diff = make_float4(inp.x - vp.x, inp.y - vp.y, inp.z - vp.z, inp.w - vp.w);
        const size_t fo = (size_t)gp * FFNIN + h * HD_ + d0;
        cvt_store4(fh + fo, diff);
        cvt_store4(fh + fo + DD, vp);
    }
}

// ---------------- LayerNorm ----------------
__global__ void __launch_bounds__(128) ln_kernel(
    const float* __restrict__ x, const float* __restrict__ gamma,
    const float* __restrict__ beta, float* __restrict__ out)
{
    const float* row = x + (size_t)blockIdx.x * DD;
    const int t = threadIdx.x;
    float4 v = *reinterpret_cast<const float4*>(row + t * 4);
    float s = v.x + v.y + v.z + v.w;
    float sq = v.x * v.x + v.y * v.y + v.z * v.z + v.w * v.w;
    blockReduceSum2(s, sq);
    const float mu = s * (1.0f / DD);
    const float var = sq * (1.0f / DD) - mu * mu;
    const float rstd = rsqrtf(var + 1e-5f);
    float4 g = *reinterpret_cast<const float4*>(gamma + t * 4);
    float4 bt = *reinterpret_cast<const float4*>(beta + t * 4);
    float4 o;
    o.x = (v.x - mu) * rstd * g.x + bt.x;
    o.y = (v.y - mu) * rstd * g.y + bt.y;
    o.z = (v.z - mu) * rstd * g.z + bt.z;
    o.w = (v.w - mu) * rstd * g.w + bt.w;
    *reinterpret_cast<float4*>(out + (size_t)blockIdx.x * DD + t * 4) = o;
}

// ---------------- launch ----------------
extern "C" void kernel_launch(void* const* d_in, const int* in_sizes, int n_in,
                              void* d_out, int out_size)
{
    (void)in_sizes; (void)n_in; (void)out_size;
    const float* input = (const float*)d_in[0];
    const float* cores = (const float*)d_in[1];
    const float* Wv    = (const float*)d_in[2];
    const float* bv    = (const float*)d_in[3];
    const float* W1    = (const float*)d_in[4];
    const float* b1    = (const float*)d_in[5];
    const float* W2    = (const float*)d_in[6];
    const float* b2    = (const float*)d_in[7];
    const float* gamma = (const float*)d_in[8];
    const float* beta  = (const float*)d_in[9];
    float* out = (float*)d_out;

    float *q, *eaff, *vcore, *vcp, *gpsum, *cinv, *outp;
    __half *in_h, *ffn_h, *hid_h, *wvT, *w1T, *w2T;
    cudaGetSymbolAddress((void**)&q, g_q);
    cudaGetSymbolAddress((void**)&eaff, g_eaff);
    cudaGetSymbolAddress((void**)&vcore, g_vcore);
    cudaGetSymbolAddress((void**)&vcp, g_vcp);
    cudaGetSymbolAddress((void**)&gpsum, g_gpsum);
    cudaGetSymbolAddress((void**)&cinv, g_cinv);
    cudaGetSymbolAddress((void**)&outp, g_outp);
    cudaGetSymbolAddress((void**)&in_h, g_in_h);
    cudaGetSymbolAddress((void**)&ffn_h, g_ffn_h);
    cudaGetSymbolAddress((void**)&hid_h, g_hid_h);
    cudaGetSymbolAddress((void**)&wvT, g_wvT);
    cudaGetSymbolAddress((void**)&w1T, g_w1T);
    cudaGetSymbolAddress((void**)&w2T, g_w2T);

    cudaFuncSetAttribute(gemm_mma<0>, cudaFuncAttributeMaxDynamicSharedMemorySize, GEMM_SMEM);
    cudaFuncSetAttribute(gemm_mma<1>, cudaFuncAttributeMaxDynamicSharedMemorySize, GEMM_SMEM);
    cudaFuncSetAttribute(gemm_mma<2>, cudaFuncAttributeMaxDynamicSharedMemorySize, GEMM_SMEM);

    // prep: converts + weight transposes
    cvt_kernel<<<(MM * DD / 4 + 255) / 256, 256>>>(input, in_h, MM * DD / 4);
    transpose_h<<<dim3(DD / 32, DD / 32), 256>>>(Wv, wvT, DD, DD);
    transpose_h<<<dim3(FFNHID / 32, FFNIN / 32), 256>>>(W1, w1T, FFNIN, FFNHID);
    transpose_h<<<dim3(DD / 32, FFNHID / 32), 256>>>(W2, w2T, FFNHID, DD);

    // 1. q = input @ Wv + bv
    gemm_mma<0><<<dim3(DD / 128, MM / 128), 256, GEMM_SMEM>>>(
        in_h, wvT, bv, nullptr, q, nullptr, DD, DD);
    // 2-5. e=exp(aff) (+partial p-sums), finalize cinv, split vcore, reduce, vpatch(+inline p2c)
    aff_kernel<<<dim3(NPT, HH, BB), 256>>>(q, cores, eaff, gpsum);
    c2p_finalize<<<(BB * HH * CC + 255) / 256, 256>>>(gpsum, cinv);
    vcore_split<<<dim3(HH, BB, NSPLIT), 256>>>(input, eaff, cinv, vcp);
    vcore_reduce<<<(BB * HH * CC * HD_ / 4 + 255) / 256, 256>>>(vcp, vcore);
    vpatch_ffn_kernel<<<dim3(PP / 64, HH, BB), 256>>>(input, vcore, eaff, ffn_h);
    // 6. hid = gelu(ffn @ W1 + b1)   (fp16 out)
    gemm_mma<1><<<dim3(FFNHID / 128, MM / 128), 256, GEMM_SMEM>>>(
        ffn_h, w1T, b1, nullptr, nullptr, hid_h, FFNHID, FFNIN);
    // 7. outp = input + hid @ W2 + b2
    gemm_mma<2><<<dim3(DD / 128, MM / 128), 256, GEMM_SMEM>>>(
        hid_h, w2T, b2, input, outp, nullptr, DD, FFNHID);
    // 8. LayerNorm
    ln_kernel<<<MM, 128>>>(outp, gamma, beta, out);
}

// round 14
// speedup vs baseline: 1.1804x; 1.0107x over previous
#include <cuda_runtime.h>
#include <cuda_fp16.h>
#include <math.h>
#include <stdint.h>

// ---------------- problem constants ----------------
#define BB      16
#define PP      2048
#define DD      512
#define HH      8
#define CC      64
#define HD_     64
#define MM      (BB * PP)        // 32768
#define FFNIN   1024
#define FFNHID  4096
#define NSPLIT  8                // p-splits for vcore
#define NPT     (PP / 64)        // 32 p-tiles

// ---------------- scratch (device globals; allocation-free) ----------------
__device__ __align__(256) float g_vcore[BB * HH * CC * HD_];
__device__ __align__(256) float g_vcp[NSPLIT * BB * HH * CC * HD_];   // 16 MB partials
__device__ __align__(256) float g_gpsum[NPT * BB * HH * CC];          // per-tile partial p-sums
__device__ __align__(256) float g_cinv[BB * HH * CC];                 // row 1/sum (over p)
__device__ __align__(256) float g_outp[MM * DD];

__device__ __align__(256) __half g_q_h[MM * DD];                      // q in fp16
__device__ __align__(256) __half g_eaff[BB * HH * CC * PP];           // exp(aff) in fp16
__device__ __align__(256) __half g_in_h[MM * DD];
__device__ __align__(256) __half g_ffn_h[MM * FFNIN];
__device__ __align__(256) __half g_hid_h[(size_t)MM * FFNHID];
// weights transposed to [N][K] fp16
__device__ __align__(256) __half g_wvT[DD * DD];
__device__ __align__(256) __half g_w1T[FFNHID * FFNIN];
__device__ __align__(256) __half g_w2T[DD * FFNHID];

// ---------------- PTX helpers (sm_80-era instructions only) ----------------
__device__ __forceinline__ uint32_t smem_u32(const void* p) {
    uint32_t a;
    asm("{ .reg .u64 t; cvta.to.shared.u64 t, %1; cvt.u32.u64 %0, t; }" : "=r"(a) : "l"(p));
    return a;
}
__device__ __forceinline__ void cp16(uint32_t s, const void* g) {
    asm volatile("cp.async.cg.shared.global [%0], [%1], 16;" :: "r"(s), "l"(g));
}
__device__ __forceinline__ void ldm_x4(uint32_t* r, uint32_t addr) {
    asm volatile("ldmatrix.sync.aligned.m8n8.x4.shared.b16 {%0,%1,%2,%3}, [%4];"
                 : "=r"(r[0]), "=r"(r[1]), "=r"(r[2]), "=r"(r[3]) : "r"(addr));
}
__device__ __forceinline__ void mma_f16(float* d, const uint32_t* a, const uint32_t* b) {
    asm volatile(
        "mma.sync.aligned.m16n8k16.row.col.f32.f16.f16.f32 "
        "{%0,%1,%2,%3}, {%4,%5,%6,%7}, {%8,%9}, {%0,%1,%2,%3};"
        : "+f"(d[0]), "+f"(d[1]), "+f"(d[2]), "+f"(d[3])
        : "r"(a[0]), "r"(a[1]), "r"(a[2]), "r"(a[3]), "r"(b[0]), "r"(b[1]));
}

__device__ __forceinline__ float gelu_exact(float x) {
    return 0.5f * x * (1.0f + erff(x * 0.7071067811865476f));
}

// ---------------- fp16 GEMM via mma.sync, BM=128 BN=128 BK=64, 3-stage, 2 CTA/SM ----------------
// EPI 0: Cf = D + bias                       (fp32 out)
// EPI 1: Ch = half(gelu(D + bias))           (fp16 out)
// EPI 2: Cf = D + bias + resid               (fp32 out)
// EPI 3: Ch = half(D + bias)                 (fp16 out)
#define BKK       64
#define RSTRIDE   72
#define TILE_B    (128 * RSTRIDE * 2)       // 18432
#define STAGE_B   (2 * TILE_B)              // 36864
#define NSTAGE    3
#define GEMM_SMEM (NSTAGE * STAGE_B)        // 110592

template <int EPI>
__global__ void __launch_bounds__(256, 2) gemm_mma(
    const __half* __restrict__ Ah, const __half* __restrict__ Bh,
    const float* __restrict__ bias, const float* __restrict__ resid,
    float* __restrict__ Cf, __half* __restrict__ Ch,
    int N, int K)
{
    extern __shared__ __align__(256) char smem[];
    const uint32_t sb = smem_u32(smem);

    const int tid = threadIdx.x;
    const int wid = tid >> 5;
    const int lane = tid & 31;
    const int bm = blockIdx.y * 128;
    const int bn = blockIdx.x * 128;
    const int mOff = (wid & 3) * 32;
    const int nOff = (wid >> 2) * 64;

    const int aRow = lane & 15;
    const int aCol = (lane >> 4) * 8;
    const int bRow = (lane & 7) + ((lane >> 4) << 3);
    const int bCol = ((lane >> 3) & 1) * 8;

    float acc[2][8][4];
    #pragma unroll
    for (int i = 0; i < 2; ++i)
        #pragma unroll
        for (int j = 0; j < 8; ++j)
            #pragma unroll
            for (int k = 0; k < 4; ++k) acc[i][j][k] = 0.0f;

    const int nch = K / BKK;

    auto loadStage = [&](int s, int it) {
        const int k0 = it * BKK;
        const uint32_t st = sb + s * STAGE_B;
        #pragma unroll
        for (int i = 0; i < 4; ++i) {
            const int id = tid + i * 256;
            const int r = id >> 3, c = id & 7;
            const uint32_t so = (uint32_t)(r * (RSTRIDE * 2) + c * 16);
            cp16(st + so,          Ah + (size_t)(bm + r) * K + k0 + c * 8);
            cp16(st + TILE_B + so, Bh + (size_t)(bn + r) * K + k0 + c * 8);
        }
        asm volatile("cp.async.commit_group;" ::: "memory");
    };

    loadStage(0, 0);
    loadStage(1, 1);

    for (int it = 0; it < nch; ++it) {
        if (it + 1 < nch)
            asm volatile("cp.async.wait_group 1;" ::: "memory");
        else
            asm volatile("cp.async.wait_group 0;" ::: "memory");
        __syncthreads();

        if (it + 2 < nch) loadStage((it + 2) % NSTAGE, it + 2);

        const uint32_t st = sb + (it % NSTAGE) * STAGE_B;
        const uint32_t pAh = st, pBh = st + TILE_B;

        #pragma unroll
        for (int kk = 0; kk < 4; ++kk) {
            uint32_t ah[2][4], b[4][4];
            #pragma unroll
            for (int mf = 0; mf < 2; ++mf)
                ldm_x4(ah[mf], pAh +
                    (uint32_t)(((mOff + mf * 16 + aRow) * RSTRIDE + kk * 16 + aCol) * 2));
            #pragma unroll
            for (int n2 = 0; n2 < 4; ++n2)
                ldm_x4(b[n2], pBh +
                    (uint32_t)(((nOff + n2 * 16 + bRow) * RSTRIDE + kk * 16 + bCol) * 2));
            #pragma unroll
            for (int mf = 0; mf < 2; ++mf)
                #pragma unroll
                for (int nf = 0; nf < 8; ++nf)
                    mma_f16(acc[mf][nf], ah[mf], &b[nf >> 1][(nf & 1) * 2]);
        }
    }

    // ---- epilogue ----
    #pragma unroll
    for (int mf = 0; mf < 2; ++mf) {
        #pragma unroll
        for (int half_ = 0; half_ < 2; ++half_) {
            const int row = bm + mOff + mf * 16 + (lane >> 2) + half_ * 8;
            #pragma unroll
            for (int nf = 0; nf < 8; ++nf) {
                const int col = bn + nOff + nf * 8 + (lane & 3) * 2;
                float v0 = acc[mf][nf][half_ * 2 + 0] + bias[col];
                float v1 = acc[mf][nf][half_ * 2 + 1] + bias[col + 1];
                if (EPI == 1 || EPI == 3) {
                    if (EPI == 1) { v0 = gelu_exact(v0); v1 = gelu_exact(v1); }
                    __half h0 = __float2half_rn(v0);
                    __half h1 = __float2half_rn(v1);
                    uint32_t hp = (uint32_t)__half_as_ushort(h0) |
                                  ((uint32_t)__half_as_ushort(h1) << 16);
                    *reinterpret_cast<uint32_t*>(Ch + (size_t)row * N + col) = hp;
                } else {
                    if (EPI == 2) {
                        const float* rp = resid + (size_t)row * N + col;
                        v0 += rp[0];
                        v1 += rp[1];
                    }
                    *reinterpret_cast<float2*>(Cf + (size_t)row * N + col) = make_float2(v0, v1);
                }
            }
        }
    }
}

// ---------------- fp32 -> fp16 convert (elementwise) ----------------
__global__ void __launch_bounds__(256) cvt_kernel(
    const float* __restrict__ x, __half* __restrict__ h, int n4)
{
    int i = blockIdx.x * 256 + threadIdx.x;
    if (i >= n4) return;
    float4 v = reinterpret_cast<const float4*>(x)[i];
    __half hb[4] = {__float2half_rn(v.x), __float2half_rn(v.y),
                    __float2half_rn(v.z), __float2half_rn(v.w)};
    reinterpret_cast<uint2*>(h)[i] = *reinterpret_cast<const uint2*>(hb);
}

// ---------------- W[K][N] fp32 -> Wt[N][K] fp16 ----------------
__global__ void __launch_bounds__(256) transpose_h(
    const float* __restrict__ W, __half* __restrict__ Th, int K, int N)
{
    __shared__ float s[32][33];
    const int n0 = blockIdx.x * 32, k0 = blockIdx.y * 32;
    const int c = threadIdx.x & 31, r0 = threadIdx.x >> 5;
    #pragma unroll
    for (int r = r0; r < 32; r += 8)
        s[r][c] = W[(size_t)(k0 + r) * N + n0 + c];
    __syncthreads();
    #pragma unroll
    for (int r = r0; r < 32; r += 8)
        Th[(size_t)(n0 + r) * K + k0 + c] = __float2half_rn(s[c][r]);
}

// ---------------- block reduce helper (for LN) ----------------
__device__ __forceinline__ void blockReduceSum2(float& a, float& b) {
    __shared__ float sa[8], sb[8];
    #pragma unroll
    for (int o = 16; o > 0; o >>= 1) {
        a += __shfl_xor_sync(0xffffffffu, a, o);
        b += __shfl_xor_sync(0xffffffffu, b, o);
    }
    int wid = threadIdx.x >> 5, nw = blockDim.x >> 5;
    if ((threadIdx.x & 31) == 0) { sa[wid] = a; sb[wid] = b; }
    __syncthreads();
    float ra = 0.0f, rb = 0.0f;
    for (int i = 0; i < nw; ++i) { ra += sa[i]; rb += sb[i]; }
    __syncthreads();
    a = ra; b = rb;
}

// ---------------- aff: e = exp(q.cores/8) fp16 out, + partial p-sums ----------------
// No max subtraction: aff ~ N(0,1), |aff|max ~ 5.8, exp safe.
__global__ void __launch_bounds__(256) aff_kernel(
    const __half* __restrict__ q, const float* __restrict__ cores,
    __half* __restrict__ eaff, float* __restrict__ gpsum)
{
    __shared__ float cs[64][65];
    __shared__ float qs[64][65];
    __shared__ float psmem[64][17];
    const int b = blockIdx.z, h = blockIdx.y, p0 = blockIdx.x * 64;
    const int tid = threadIdx.x;
    const int lr = tid >> 2;
    const int lc = (tid & 3) * 16;
    #pragma unroll
    for (int u = 0; u < 4; ++u) {
        float4 cv = *reinterpret_cast<const float4*>(cores + (size_t)(h * CC + lr) * HD_ + lc + u * 4);
        cs[lr][lc + u * 4 + 0] = cv.x; cs[lr][lc + u * 4 + 1] = cv.y;
        cs[lr][lc + u * 4 + 2] = cv.z; cs[lr][lc + u * 4 + 3] = cv.w;
        uint2 qraw = *reinterpret_cast<const uint2*>(q + (size_t)(b * PP + p0 + lr) * DD + h * HD_ + lc + u * 4);
        float2 q01 = __half22float2(*reinterpret_cast<const __half2*>(&qraw.x));
        float2 q23 = __half22float2(*reinterpret_cast<const __half2*>(&qraw.y));
        qs[lr][lc + u * 4 + 0] = q01.x; qs[lr][lc + u * 4 + 1] = q01.y;
        qs[lr][lc + u * 4 + 2] = q23.x; qs[lr][lc + u * 4 + 3] = q23.y;
    }
    __syncthreads();
    const int c0 = (tid & 15) * 4;
    const int pq = (tid >> 4) * 4;
    float acc[4][4];
    #pragma unroll
    for (int i = 0; i < 4; ++i)
        #pragma unroll
        for (int j = 0; j < 4; ++j) acc[i][j] = 0.0f;
    #pragma unroll 8
    for (int k = 0; k < 64; ++k) {
        float cr[4], pr[4];
        #pragma unroll
        for (int i = 0; i < 4; ++i) cr[i] = cs[c0 + i][k];
        #pragma unroll
        for (int j = 0; j < 4; ++j) pr[j] = qs[pq + j][k];
        #pragma unroll
        for (int i = 0; i < 4; ++i)
            #pragma unroll
            for (int j = 0; j < 4; ++j) acc[i][j] = fmaf(cr[i], pr[j], acc[i][j]);
    }
    #pragma unroll
    for (int i = 0; i < 4; ++i) {
        float ps = 0.0f;
        #pragma unroll
        for (int j = 0; j < 4; ++j) { acc[i][j] = __expf(acc[i][j] * 0.125f); ps += acc[i][j]; }
        psmem[c0 + i][tid >> 4] = ps;
    }

    const int bh = b * HH + h;
    const size_t base = (size_t)bh * CC * PP;
    #pragma unroll
    for (int i = 0; i < 4; ++i) {
        __half hb[4] = {__float2half_rn(acc[i][0]), __float2half_rn(acc[i][1]),
                        __float2half_rn(acc[i][2]), __float2half_rn(acc[i][3])};
        *reinterpret_cast<uint2*>(eaff + base + (size_t)(c0 + i) * PP + p0 + pq) =
            *reinterpret_cast<const uint2*>(hb);
    }

    __syncthreads();
    if (tid < 64) {
        float s = 0.0f;
        #pragma unroll
        for (int g = 0; g < 16; ++g) s += psmem[tid][g];
        gpsum[(size_t)blockIdx.x * (BB * HH * CC) + bh * CC + tid] = s;
    }
}

// ---------------- finalize c2p: cinv = 1 / sum of NPT partials ----------------
__global__ void __launch_bounds__(256) c2p_finalize(
    const float* __restrict__ gpsum, float* __restrict__ cinv)
{
    int r = blockIdx.x * 256 + threadIdx.x;
    if (r >= BB * HH * CC) return;
    float s = 0.0f;
    #pragma unroll
    for (int z = 0; z < NPT; ++z) s += gpsum[(size_t)z * (BB * HH * CC) + r];
    cinv[r] = 1.0f / s;
}

// ---------------- v_core split over p (reads e fp16, applies cinv) ----------------
__global__ void __launch_bounds__(256) vcore_split(
    const float* __restrict__ input, const __half* __restrict__ eaff,
    const float* __restrict__ cinv, float* __restrict__ vcp)
{
    __shared__ float asT[64][68];
    __shared__ float vs[64][68];
    const int h = blockIdx.x, b = blockIdx.y, pz = blockIdx.z;
    const int bh = b * HH + h;
    const int p0 = pz * (PP / NSPLIT);
    const __half* abase = eaff + (size_t)bh * CC * PP;
    const int tid = threadIdx.x;
    const int lr = tid >> 2;
    const int lc = (tid & 3) * 16;
    const int c0 = (tid & 15) * 4;
    const int d0 = (tid >> 4) * 4;

    const float irow = cinv[bh * CC + lr];

    float acc[4][4];
    #pragma unroll
    for (int i = 0; i < 4; ++i)
        #pragma unroll
        for (int j = 0; j < 4; ++j) acc[i][j] = 0.0f;

    for (int pt = p0; pt < p0 + PP / NSPLIT; pt += 64) {
        #pragma unroll
        for (int u = 0; u < 4; ++u) {
            uint2 araw = *reinterpret_cast<const uint2*>(abase + (size_t)lr * PP + pt + lc + u * 4);
            float2 a01 = __half22float2(*reinterpret_cast<const __half2*>(&araw.x));
            float2 a23 = __half22float2(*reinterpret_cast<const __half2*>(&araw.y));
            asT[lc + u * 4 + 0][lr] = a01.x * irow;
            asT[lc + u * 4 + 1][lr] = a01.y * irow;
            asT[lc + u * 4 + 2][lr] = a23.x * irow;
            asT[lc + u * 4 + 3][lr] = a23.y * irow;
            float4 vv = *reinterpret_cast<const float4*>(input + (size_t)(b * PP + pt + lr) * DD + h * HD_ + lc + u * 4);
            *reinterpret_cast<float4*>(&vs[lr][lc + u * 4]) = vv;
        }
        __syncthreads();
        #pragma unroll 16
        for (int k = 0; k < 64; ++k) {
            float4 ar = *reinterpret_cast<const float4*>(&asT[k][c0]);
            float4 vr = *reinterpret_cast<const float4*>(&vs[k][d0]);
            float arr[4] = {ar.x, ar.y, ar.z, ar.w};
            float vrr[4] = {vr.x, vr.y, vr.z, vr.w};
            #pragma unroll
            for (int i = 0; i < 4; ++i)
                #pragma unroll
                for (int j = 0; j < 4; ++j) acc[i][j] = fmaf(arr[i], vrr[j], acc[i][j]);
        }
        __syncthreads();
    }
    float* dst = vcp + (size_t)pz * (BB * HH * CC * HD_);
    #pragma unroll
    for (int i = 0; i < 4; ++i) {
        float4 o = make_float4(acc[i][0], acc[i][1], acc[i][2], acc[i][3]);
        *reinterpret_cast<float4*>(dst + (size_t)(bh * CC + c0 + i) * HD_ + d0) = o;
    }
}

// ---------------- v_core reduce ----------------
__global__ void __launch_bounds__(256) vcore_reduce(
    const float* __restrict__ vcp, float* __restrict__ vcore)
{
    const int n4 = BB * HH * CC * HD_ / 4;
    int i = blockIdx.x * 256 + threadIdx.x;
    if (i >= n4) return;
    float4 s = reinterpret_cast<const float4*>(vcp)[i];
    #pragma unroll
    for (int z = 1; z < NSPLIT; ++z) {
        float4 v = reinterpret_cast<const float4*>(vcp + (size_t)z * (BB * HH * CC * HD_))[i];
        s.x += v.x; s.y += v.y; s.z += v.z; s.w += v.w;
    }
    reinterpret_cast<float4*>(vcore)[i] = s;
}

// ---------------- v_patch + inline p2c softmax + ffn concat ----------------
__device__ __forceinline__ void cvt_store4(__half* ph, float4 v) {
    __half hb[4] = {__float2half_rn(v.x), __float2half_rn(v.y),
                    __float2half_rn(v.z), __float2half_rn(v.w)};
    *reinterpret_cast<uint2*>(ph) = *reinterpret_cast<const uint2*>(hb);
}

__global__ void __launch_bounds__(256) vpatch_ffn_kernel(
    const float* __restrict__ input, const float* __restrict__ vcore,
    const __half* __restrict__ eaff, __half* __restrict__ fh)
{
    __shared__ float vc[64][65];
    __shared__ float ap[64][65];
    __shared__ float partial[4][65];
    __shared__ float invs[64];
    const int b = blockIdx.z, h = blockIdx.y, p0 = blockIdx.x * 64;
    const int bh = b * HH + h;
    const int tid = threadIdx.x;
    const int lr = tid >> 2;
    const int lc = (tid & 3) * 16;
    #pragma unroll
    for (int u = 0; u < 4; ++u) {
        float4 cv = *reinterpret_cast<const float4*>(vcore + (size_t)(bh * CC + lr) * HD_ + lc + u * 4);
        vc[lr][lc + u * 4 + 0] = cv.x; vc[lr][lc + u * 4 + 1] = cv.y;
        vc[lr][lc + u * 4 + 2] = cv.z; vc[lr][lc + u * 4 + 3] = cv.w;
        uint2 araw = *reinterpret_cast<const uint2*>(eaff + ((size_t)(bh * CC + lr)) * PP + p0 + lc + u * 4);
        float2 a01 = __half22float2(*reinterpret_cast<const __half2*>(&araw.x));
        float2 a23 = __half22float2(*reinterpret_cast<const __half2*>(&araw.y));
        ap[lr][lc + u * 4 + 0] = a01.x; ap[lr][lc + u * 4 + 1] = a01.y;
        ap[lr][lc + u * 4 + 2] = a23.x; ap[lr][lc + u * 4 + 3] = a23.y;
    }
    __syncthreads();

    // column sums over c (fixed order; deterministic)
    {
        const int p = tid & 63, qt = tid >> 6;
        float s = 0.0f;
        #pragma unroll
        for (int r = 0; r < 16; ++r) s += ap[qt * 16 + r][p];
        partial[qt][p] = s;
    }
    __syncthreads();
    if (tid < 64)
        invs[tid] = 1.0f / (partial[0][tid] + partial[1][tid] + partial[2][tid] + partial[3][tid]);
    __syncthreads();

    const int pq = (tid >> 4) * 4;
    const int d0 = (tid & 15) * 4;
    float acc[4][4];
    #pragma unroll
    for (int i = 0; i < 4; ++i)
        #pragma unroll
        for (int j = 0; j < 4; ++j) acc[i][j] = 0.0f;
    #pragma unroll 8
    for (int k = 0; k < 64; ++k) {
        float apr[4], vcr[4];
        #pragma unroll
        for (int i = 0; i < 4; ++i) apr[i] = ap[k][pq + i];
        #pragma unroll
        for (int j = 0; j < 4; ++j) vcr[j] = vc[k][d0 + j];
        #pragma unroll
        for (int i = 0; i < 4; ++i)
            #pragma unroll
            for (int j = 0; j < 4; ++j) acc[i][j] = fmaf(apr[i], vcr[j], acc[i][j]);
    }
    #pragma unroll
    for (int i = 0; i < 4; ++i) {
        const float iv = invs[pq + i];
        const int gp = b * PP + p0 + pq + i;
        float4 inp = *reinterpret_cast<const float4*>(input + (size_t)gp * DD + h * HD_ + d0);
        float4 vp = make_float4(acc[i][0] * iv, acc[i][1] * iv, acc[i][2] * iv, acc[i][3] * iv);
        float4 diff = make_float4(inp.x - vp.x, inp.y - vp.y, inp.z - vp.z, inp.w - vp.w);
        const size_t fo = (size_t)gp * FFNIN + h * HD_ + d0;
        cvt_store4(fh + fo, diff);
        cvt_store4(fh + fo + DD, vp);
    }
}

// ---------------- LayerNorm ----------------
__global__ void __launch_bounds__(128) ln_kernel(
    const float* __restrict__ x, const float* __restrict__ gamma,
    const float* __restrict__ beta, float* __restrict__ out)
{
    const float* row = x + (size_t)blockIdx.x * DD;
    const int t = threadIdx.x;
    float4 v = *reinterpret_cast<const float4*>(row + t * 4);
    float s = v.x + v.y + v.z + v.w;
    float sq = v.x * v.x + v.y * v.y + v.z * v.z + v.w * v.w;
    blockReduceSum2(s, sq);
    const float mu = s * (1.0f / DD);
    const float var = sq * (1.0f / DD) - mu * mu;
    const float rstd = rsqrtf(var + 1e-5f);
    float4 g = *reinterpret_cast<const float4*>(gamma + t * 4);
    float4 bt = *reinterpret_cast<const float4*>(beta + t * 4);
    float4 o;
    o.x = (v.x - mu) * rstd * g.x + bt.x;
    o.y = (v.y - mu) * rstd * g.y + bt.y;
    o.z = (v.z - mu) * rstd * g.z + bt.z;
    o.w = (v.w - mu) * rstd * g.w + bt.w;
    *reinterpret_cast<float4*>(out + (size_t)blockIdx.x * DD + t * 4) = o;
}

// ---------------- launch ----------------
extern "C" void kernel_launch(void* const* d_in, const int* in_sizes, int n_in,
                              void* d_out, int out_size)
{
    (void)in_sizes; (void)n_in; (void)out_size;
    const float* input = (const float*)d_in[0];
    const float* cores = (const float*)d_in[1];
    const float* Wv    = (const float*)d_in[2];
    const float* bv    = (const float*)d_in[3];
    const float* W1    = (const float*)d_in[4];
    const float* b1    = (const float*)d_in[5];
    const float* W2    = (const float*)d_in[6];
    const float* b2    = (const float*)d_in[7];
    const float* gamma = (const float*)d_in[8];
    const float* beta  = (const float*)d_in[9];
    float* out = (float*)d_out;

    float *vcore, *vcp, *gpsum, *cinv, *outp;
    __half *q_h, *eaff, *in_h, *ffn_h, *hid_h, *wvT, *w1T, *w2T;
    cudaGetSymbolAddress((void**)&vcore, g_vcore);
    cudaGetSymbolAddress((void**)&vcp, g_vcp);
    cudaGetSymbolAddress((void**)&gpsum, g_gpsum);
    cudaGetSymbolAddress((void**)&cinv, g_cinv);
    cudaGetSymbolAddress((void**)&outp, g_outp);
    cudaGetSymbolAddress((void**)&q_h, g_q_h);
    cudaGetSymbolAddress((void**)&eaff, g_eaff);
    cudaGetSymbolAddress((void**)&in_h, g_in_h);
    cudaGetSymbolAddress((void**)&ffn_h, g_ffn_h);
    cudaGetSymbolAddress((void**)&hid_h, g_hid_h);
    cudaGetSymbolAddress((void**)&wvT, g_wvT);
    cudaGetSymbolAddress((void**)&w1T, g_w1T);
    cudaGetSymbolAddress((void**)&w2T, g_w2T);

    cudaFuncSetAttribute(gemm_mma<1>, cudaFuncAttributeMaxDynamicSharedMemorySize, GEMM_SMEM);
    cudaFuncSetAttribute(gemm_mma<2>, cudaFuncAttributeMaxDynamicSharedMemorySize, GEMM_SMEM);
    cudaFuncSetAttribute(gemm_mma<3>, cudaFuncAttributeMaxDynamicSharedMemorySize, GEMM_SMEM);

    // prep: converts + weight transposes
    cvt_kernel<<<(MM * DD / 4 + 255) / 256, 256>>>(input, in_h, MM * DD / 4);
    transpose_h<<<dim3(DD / 32, DD / 32), 256>>>(Wv, wvT, DD, DD);
    transpose_h<<<dim3(FFNHID / 32, FFNIN / 32), 256>>>(W1, w1T, FFNIN, FFNHID);
    transpose_h<<<dim3(DD / 32, FFNHID / 32), 256>>>(W2, w2T, FFNHID, DD);

    // 1. q = input @ Wv + bv  (fp16 out)
    gemm_mma<3><<<dim3(DD / 128, MM / 128), 256, GEMM_SMEM>>>(
        in_h, wvT, bv, nullptr, nullptr, q_h, DD, DD);
    // 2-5. e=exp(aff) fp16 (+partial p-sums), cinv, split vcore, reduce, vpatch(+inline p2c)
    aff_kernel<<<dim3(NPT, HH, BB), 256>>>(q_h, cores, eaff, gpsum);
    c2p_finalize<<<(BB * HH * CC + 255) / 256, 256>>>(gpsum, cinv);
    vcore_split<<<dim3(HH, BB, NSPLIT), 256>>>(input, eaff, cinv, vcp);
    vcore_reduce<<<(BB * HH * CC * HD_ / 4 + 255) / 256, 256>>>(vcp, vcore);
    vpatch_ffn_kernel<<<dim3(PP / 64, HH, BB), 256>>>(input, vcore, eaff, ffn_h);
    // 6. hid = gelu(ffn @ W1 + b1)   (fp16 out)
    gemm_mma<1><<<dim3(FFNHID / 128, MM / 128), 256, GEMM_SMEM>>>(
        ffn_h, w1T, b1, nullptr, nullptr, hid_h, FFNHID, FFNIN);
    // 7. outp = input + hid @ W2 + b2
    gemm_mma<2><<<dim3(DD / 128, MM / 128), 256, GEMM_SMEM>>>(
        hid_h, w2T, b2, input, outp, nullptr, DD, FFNHID);
    // 8. LayerNorm
    ln_kernel<<<MM, 128>>>(outp, gamma, beta, out);
}

// round 15
// speedup vs baseline: 1.1812x; 1.0007x over previous
#include <cuda_runtime.h>
#include <cuda_fp16.h>
#include <math.h>
#include <stdint.h>

// ---------------- problem constants ----------------
#define BB      16
#define PP      2048
#define DD      512
#define HH      8
#define CC      64
#define HD_     64
#define MM      (BB * PP)        // 32768
#define FFNIN   1024
#define FFNHID  4096
#define NSPLIT  8                // p-splits for vcore
#define NPT     (PP / 64)        // 32 p-tiles

// ---------------- scratch (device globals; allocation-free) ----------------
__device__ __align__(256) float g_vcore[BB * HH * CC * HD_];
__device__ __align__(256) float g_vcp[NSPLIT * BB * HH * CC * HD_];   // 16 MB partials
__device__ __align__(256) float g_gpsum[NPT * BB * HH * CC];          // per-tile partial p-sums
__device__ __align__(256) float g_outp[MM * DD];

__device__ __align__(256) __half g_q_h[MM * DD];                      // q in fp16
__device__ __align__(256) __half g_eaff[BB * HH * CC * PP];           // exp(aff) in fp16
__device__ __align__(256) __half g_in_h[MM * DD];
__device__ __align__(256) __half g_ffn_h[MM * FFNIN];
__device__ __align__(256) __half g_hid_h[(size_t)MM * FFNHID];
// weights transposed to [N][K] fp16
__device__ __align__(256) __half g_wvT[DD * DD];
__device__ __align__(256) __half g_w1T[FFNHID * FFNIN];
__device__ __align__(256) __half g_w2T[DD * FFNHID];

// ---------------- PTX helpers (sm_80-era instructions only) ----------------
__device__ __forceinline__ uint32_t smem_u32(const void* p) {
    uint32_t a;
    asm("{ .reg .u64 t; cvta.to.shared.u64 t, %1; cvt.u32.u64 %0, t; }" : "=r"(a) : "l"(p));
    return a;
}
__device__ __forceinline__ void cp16(uint32_t s, const void* g) {
    asm volatile("cp.async.cg.shared.global [%0], [%1], 16;" :: "r"(s), "l"(g));
}
__device__ __forceinline__ void ldm_x4(uint32_t* r, uint32_t addr) {
    asm volatile("ldmatrix.sync.aligned.m8n8.x4.shared.b16 {%0,%1,%2,%3}, [%4];"
                 : "=r"(r[0]), "=r"(r[1]), "=r"(r[2]), "=r"(r[3]) : "r"(addr));
}
__device__ __forceinline__ void mma_f16(float* d, const uint32_t* a, const uint32_t* b) {
    asm volatile(
        "mma.sync.aligned.m16n8k16.row.col.f32.f16.f16.f32 "
        "{%0,%1,%2,%3}, {%4,%5,%6,%7}, {%8,%9}, {%0,%1,%2,%3};"
        : "+f"(d[0]), "+f"(d[1]), "+f"(d[2]), "+f"(d[3])
        : "r"(a[0]), "r"(a[1]), "r"(a[2]), "r"(a[3]), "r"(b[0]), "r"(b[1]));
}

__device__ __forceinline__ float gelu_exact(float x) {
    return 0.5f * x * (1.0f + erff(x * 0.7071067811865476f));
}

// ---------------- fp16 GEMM via mma.sync, BM=128 BN=128 BK=64, 3-stage, 2 CTA/SM ----------------
// EPI 0: Cf = D + bias                       (fp32 out)
// EPI 1: Ch = half(gelu(D + bias))           (fp16 out)
// EPI 2: Cf = D + bias + resid               (fp32 out)
// EPI 3: Ch = half(D + bias)                 (fp16 out)
#define BKK       64
#define RSTRIDE   72
#define TILE_B    (128 * RSTRIDE * 2)       // 18432
#define STAGE_B   (2 * TILE_B)              // 36864
#define NSTAGE    3
#define GEMM_SMEM (NSTAGE * STAGE_B)        // 110592

template <int EPI>
__global__ void __launch_bounds__(256, 2) gemm_mma(
    const __half* __restrict__ Ah, const __half* __restrict__ Bh,
    const float* __restrict__ bias, const float* __restrict__ resid,
    float* __restrict__ Cf, __half* __restrict__ Ch,
    int N, int K)
{
    extern __shared__ __align__(256) char smem[];
    const uint32_t sb = smem_u32(smem);

    const int tid = threadIdx.x;
    const int wid = tid >> 5;
    const int lane = tid & 31;
    const int bm = blockIdx.y * 128;
    const int bn = blockIdx.x * 128;
    const int mOff = (wid & 3) * 32;
    const int nOff = (wid >> 2) * 64;

    const int aRow = lane & 15;
    const int aCol = (lane >> 4) * 8;
    const int bRow = (lane & 7) + ((lane >> 4) << 3);
    const int bCol = ((lane >> 3) & 1) * 8;

    float acc[2][8][4];
    #pragma unroll
    for (int i = 0; i < 2; ++i)
        #pragma unroll
        for (int j = 0; j < 8; ++j)
            #pragma unroll
            for (int k = 0; k < 4; ++k) acc[i][j][k] = 0.0f;

    const int nch = K / BKK;

    auto loadStage = [&](int s, int it) {
        const int k0 = it * BKK;
        const uint32_t st = sb + s * STAGE_B;
        #pragma unroll
        for (int i = 0; i < 4; ++i) {
            const int id = tid + i * 256;
            const int r = id >> 3, c = id & 7;
            const uint32_t so = (uint32_t)(r * (RSTRIDE * 2) + c * 16);
            cp16(st + so,          Ah + (size_t)(bm + r) * K + k0 + c * 8);
            cp16(st + TILE_B + so, Bh + (size_t)(bn + r) * K + k0 + c * 8);
        }
        asm volatile("cp.async.commit_group;" ::: "memory");
    };

    loadStage(0, 0);
    loadStage(1, 1);

    for (int it = 0; it < nch; ++it) {
        if (it + 1 < nch)
            asm volatile("cp.async.wait_group 1;" ::: "memory");
        else
            asm volatile("cp.async.wait_group 0;" ::: "memory");
        __syncthreads();

        if (it + 2 < nch) loadStage((it + 2) % NSTAGE, it + 2);

        const uint32_t st = sb + (it % NSTAGE) * STAGE_B;
        const uint32_t pAh = st, pBh = st + TILE_B;

        #pragma unroll
        for (int kk = 0; kk < 4; ++kk) {
            uint32_t ah[2][4], b[4][4];
            #pragma unroll
            for (int mf = 0; mf < 2; ++mf)
                ldm_x4(ah[mf], pAh +
                    (uint32_t)(((mOff + mf * 16 + aRow) * RSTRIDE + kk * 16 + aCol) * 2));
            #pragma unroll
            for (int n2 = 0; n2 < 4; ++n2)
                ldm_x4(b[n2], pBh +
                    (uint32_t)(((nOff + n2 * 16 + bRow) * RSTRIDE + kk * 16 + bCol) * 2));
            #pragma unroll
            for (int mf = 0; mf < 2; ++mf)
                #pragma unroll
                for (int nf = 0; nf < 8; ++nf)
                    mma_f16(acc[mf][nf], ah[mf], &b[nf >> 1][(nf & 1) * 2]);
        }
    }

    // ---- epilogue ----
    #pragma unroll
    for (int mf = 0; mf < 2; ++mf) {
        #pragma unroll
        for (int half_ = 0; half_ < 2; ++half_) {
            const int row = bm + mOff + mf * 16 + (lane >> 2) + half_ * 8;
            #pragma unroll
            for (int nf = 0; nf < 8; ++nf) {
                const int col = bn + nOff + nf * 8 + (lane & 3) * 2;
                float v0 = acc[mf][nf][half_ * 2 + 0] + bias[col];
                float v1 = acc[mf][nf][half_ * 2 + 1] + bias[col + 1];
                if (EPI == 1 || EPI == 3) {
                    if (EPI == 1) { v0 = gelu_exact(v0); v1 = gelu_exact(v1); }
                    __half h0 = __float2half_rn(v0);
                    __half h1 = __float2half_rn(v1);
                    uint32_t hp = (uint32_t)__half_as_ushort(h0) |
                                  ((uint32_t)__half_as_ushort(h1) << 16);
                    *reinterpret_cast<uint32_t*>(Ch + (size_t)row * N + col) = hp;
                } else {
                    if (EPI == 2) {
                        const float* rp = resid + (size_t)row * N + col;
                        v0 += rp[0];
                        v1 += rp[1];
                    }
                    *reinterpret_cast<float2*>(Cf + (size_t)row * N + col) = make_float2(v0, v1);
                }
            }
        }
    }
}

// ---------------- merged prep: cvt(input->fp16) + 3 weight transposes ----------------
#define NCVT_BLK   (MM * DD / 4 / 256)                 // 16384
#define NWV_BLK    ((DD / 32) * (DD / 32))             // 256
#define NW1_BLK    ((FFNHID / 32) * (FFNIN / 32))      // 4096
#define NW2_BLK    ((DD / 32) * (FFNHID / 32))         // 2048

__device__ __forceinline__ void transpose_tile(
    const float* __restrict__ W, __half* __restrict__ Th,
    int K, int N, int bx, int by, float (*s)[33])
{
    const int n0 = bx * 32, k0 = by * 32;
    const int c = threadIdx.x & 31, r0 = threadIdx.x >> 5;
    #pragma unroll
    for (int r = r0; r < 32; r += 8)
        s[r][c] = W[(size_t)(k0 + r) * N + n0 + c];
    __syncthreads();
    #pragma unroll
    for (int r = r0; r < 32; r += 8)
        Th[(size_t)(n0 + r) * K + k0 + c] = __float2half_rn(s[c][r]);
}

__global__ void __launch_bounds__(256) prep_all(
    const float* __restrict__ input, __half* __restrict__ in_h,
    const float* __restrict__ Wv, __half* __restrict__ wvT,
    const float* __restrict__ W1, __half* __restrict__ w1T,
    const float* __restrict__ W2, __half* __restrict__ w2T)
{
    __shared__ float s[32][33];
    int blk = blockIdx.x;
    if (blk < NCVT_BLK) {
        int i = blk * 256 + threadIdx.x;
        float4 v = reinterpret_cast<const float4*>(input)[i];
        __half hb[4] = {__float2half_rn(v.x), __float2half_rn(v.y),
                        __float2half_rn(v.z), __float2half_rn(v.w)};
        reinterpret_cast<uint2*>(in_h)[i] = *reinterpret_cast<const uint2*>(hb);
        return;
    }
    blk -= NCVT_BLK;
    if (blk < NWV_BLK) {
        transpose_tile(Wv, wvT, DD, DD, blk % (DD / 32), blk / (DD / 32), s);
        return;
    }
    blk -= NWV_BLK;
    if (blk < NW1_BLK) {
        transpose_tile(W1, w1T, FFNIN, FFNHID, blk % (FFNHID / 32), blk / (FFNHID / 32), s);
        return;
    }
    blk -= NW1_BLK;
    transpose_tile(W2, w2T, FFNHID, DD, blk % (DD / 32), blk / (DD / 32), s);
}

// ---------------- block reduce helper (for LN) ----------------
__device__ __forceinline__ void blockReduceSum2(float& a, float& b) {
    __shared__ float sa[8], sb[8];
    #pragma unroll
    for (int o = 16; o > 0; o >>= 1) {
        a += __shfl_xor_sync(0xffffffffu, a, o);
        b += __shfl_xor_sync(0xffffffffu, b, o);
    }
    int wid = threadIdx.x >> 5, nw = blockDim.x >> 5;
    if ((threadIdx.x & 31) == 0) { sa[wid] = a; sb[wid] = b; }
    __syncthreads();
    float ra = 0.0f, rb = 0.0f;
    for (int i = 0; i < nw; ++i) { ra += sa[i]; rb += sb[i]; }
    __syncthreads();
    a = ra; b = rb;
}

// ---------------- aff: e = exp(q.cores/8) fp16 out, + partial p-sums ----------------
__global__ void __launch_bounds__(256) aff_kernel(
    const __half* __restrict__ q, const float* __restrict__ cores,
    __half* __restrict__ eaff, float* __restrict__ gpsum)
{
    __shared__ float cs[64][65];
    __shared__ float qs[64][65];
    __shared__ float psmem[64][17];
    const int b = blockIdx.z, h = blockIdx.y, p0 = blockIdx.x * 64;
    const int tid = threadIdx.x;
    const int lr = tid >> 2;
    const int lc = (tid & 3) * 16;
    #pragma unroll
    for (int u = 0; u < 4; ++u) {
        float4 cv = *reinterpret_cast<const float4*>(cores + (size_t)(h * CC + lr) * HD_ + lc + u * 4);
        cs[lr][lc + u * 4 + 0] = cv.x; cs[lr][lc + u * 4 + 1] = cv.y;
        cs[lr][lc + u * 4 + 2] = cv.z; cs[lr][lc + u * 4 + 3] = cv.w;
        uint2 qraw = *reinterpret_cast<const uint2*>(q + (size_t)(b * PP + p0 + lr) * DD + h * HD_ + lc + u * 4);
        float2 q01 = __half22float2(*reinterpret_cast<const __half2*>(&qraw.x));
        float2 q23 = __half22float2(*reinterpret_cast<const __half2*>(&qraw.y));
        qs[lr][lc + u * 4 + 0] = q01.x; qs[lr][lc + u * 4 + 1] = q01.y;
        qs[lr][lc + u * 4 + 2] = q23.x; qs[lr][lc + u * 4 + 3] = q23.y;
    }
    __syncthreads();
    const int c0 = (tid & 15) * 4;
    const int pq = (tid >> 4) * 4;
    float acc[4][4];
    #pragma unroll
    for (int i = 0; i < 4; ++i)
        #pragma unroll
        for (int j = 0; j < 4; ++j) acc[i][j] = 0.0f;
    #pragma unroll 8
    for (int k = 0; k < 64; ++k) {
        float cr[4], pr[4];
        #pragma unroll
        for (int i = 0; i < 4; ++i) cr[i] = cs[c0 + i][k];
        #pragma unroll
        for (int j = 0; j < 4; ++j) pr[j] = qs[pq + j][k];
        #pragma unroll
        for (int i = 0; i < 4; ++i)
            #pragma unroll
            for (int j = 0; j < 4; ++j) acc[i][j] = fmaf(cr[i], pr[j], acc[i][j]);
    }
    #pragma unroll
    for (int i = 0; i < 4; ++i) {
        float ps = 0.0f;
        #pragma unroll
        for (int j = 0; j < 4; ++j) { acc[i][j] = __expf(acc[i][j] * 0.125f); ps += acc[i][j]; }
        psmem[c0 + i][tid >> 4] = ps;
    }

    const int bh = b * HH + h;
    const size_t base = (size_t)bh * CC * PP;
    #pragma unroll
    for (int i = 0; i < 4; ++i) {
        __half hb[4] = {__float2half_rn(acc[i][0]), __float2half_rn(acc[i][1]),
                        __float2half_rn(acc[i][2]), __float2half_rn(acc[i][3])};
        *reinterpret_cast<uint2*>(eaff + base + (size_t)(c0 + i) * PP + p0 + pq) =
            *reinterpret_cast<const uint2*>(hb);
    }

    __syncthreads();
    if (tid < 64) {
        float s = 0.0f;
        #pragma unroll
        for (int g = 0; g < 16; ++g) s += psmem[tid][g];
        gpsum[(size_t)blockIdx.x * (BB * HH * CC) + bh * CC + tid] = s;
    }
}

// ---------------- v_core split over p (reads e fp16, computes cinv inline) ----------------
__global__ void __launch_bounds__(256) vcore_split(
    const float* __restrict__ input, const __half* __restrict__ eaff,
    const float* __restrict__ gpsum, float* __restrict__ vcp)
{
    __shared__ float asT[64][68];
    __shared__ float vs[64][68];
    const int h = blockIdx.x, b = blockIdx.y, pz = blockIdx.z;
    const int bh = b * HH + h;
    const int p0 = pz * (PP / NSPLIT);
    const __half* abase = eaff + (size_t)bh * CC * PP;
    const int tid = threadIdx.x;
    const int lr = tid >> 2;
    const int lc = (tid & 3) * 16;
    const int c0 = (tid & 15) * 4;
    const int d0 = (tid >> 4) * 4;

    // cinv for row lr: fixed-order sum of NPT partials (same order as old c2p_finalize)
    float rs = 0.0f;
    #pragma unroll
    for (int z = 0; z < NPT; ++z) rs += gpsum[(size_t)z * (BB * HH * CC) + bh * CC + lr];
    const float irow = 1.0f / rs;

    float acc[4][4];
    #pragma unroll
    for (int i = 0; i < 4; ++i)
        #pragma unroll
        for (int j = 0; j < 4; ++j) acc[i][j] = 0.0f;

    for (int pt = p0; pt < p0 + PP / NSPLIT; pt += 64) {
        #pragma unroll
        for (int u = 0; u < 4; ++u) {
            uint2 araw = *reinterpret_cast<const uint2*>(abase + (size_t)lr * PP + pt + lc + u * 4);
            float2 a01 = __half22float2(*reinterpret_cast<const __half2*>(&araw.x));
            float2 a23 = __half22float2(*reinterpret_cast<const __half2*>(&araw.y));
            asT[lc + u * 4 + 0][lr] = a01.x * irow;
            asT[lc + u * 4 + 1][lr] = a01.y * irow;
            asT[lc + u * 4 + 2][lr] = a23.x * irow;
            asT[lc + u * 4 + 3][lr] = a23.y * irow;
            float4 vv = *reinterpret_cast<const float4*>(input + (size_t)(b * PP + pt + lr) * DD + h * HD_ + lc + u * 4);
            *reinterpret_cast<float4*>(&vs[lr][lc + u * 4]) = vv;
        }
        __syncthreads();
        #pragma unroll 16
        for (int k = 0; k < 64; ++k) {
            float4 ar = *reinterpret_cast<const float4*>(&asT[k][c0]);
            float4 vr = *reinterpret_cast<const float4*>(&vs[k][d0]);
            float arr[4] = {ar.x, ar.y, ar.z, ar.w};
            float vrr[4] = {vr.x, vr.y, vr.z, vr.w};
            #pragma unroll
            for (int i = 0; i < 4; ++i)
                #pragma unroll
                for (int j = 0; j < 4; ++j) acc[i][j] = fmaf(arr[i], vrr[j], acc[i][j]);
        }
        __syncthreads();
    }
    float* dst = vcp + (size_t)pz * (BB * HH * CC * HD_);
    #pragma unroll
    for (int i = 0; i < 4; ++i) {
        float4 o = make_float4(acc[i][0], acc[i][1], acc[i][2], acc[i][3]);
        *reinterpret_cast<float4*>(dst + (size_t)(bh * CC + c0 + i) * HD_ + d0) = o;
    }
}

// ---------------- v_core reduce ----------------
__global__ void __launch_bounds__(256) vcore_reduce(
    const float* __restrict__ vcp, float* __restrict__ vcore)
{
    const int n4 = BB * HH * CC * HD_ / 4;
    int i = blockIdx.x * 256 + threadIdx.x;
    if (i >= n4) return;
    float4 s = reinterpret_cast<const float4*>(vcp)[i];
    #pragma unroll
    for (int z = 1; z < NSPLIT; ++z) {
        float4 v = reinterpret_cast<const float4*>(vcp + (size_t)z * (BB * HH * CC * HD_))[i];
        s.x += v.x; s.y += v.y; s.z += v.z; s.w += v.w;
    }
    reinterpret_cast<float4*>(vcore)[i] = s;
}

// ---------------- v_patch + inline p2c softmax + ffn concat ----------------
__device__ __forceinline__ void cvt_store4(__half* ph, float4 v) {
    __half hb[4] = {__float2half_rn(v.x), __float2half_rn(v.y),
                    __float2half_rn(v.z), __float2half_rn(v.w)};
    *reinterpret_cast<uint2*>(ph) = *reinterpret_cast<const uint2*>(hb);
}

__global__ void __launch_bounds__(256) vpatch_ffn_kernel(
    const float* __restrict__ input, const float* __restrict__ vcore,
    const __half* __restrict__ eaff, __half* __restrict__ fh)
{
    __shared__ float vc[64][65];
    __shared__ float ap[64][65];
    __shared__ float partial[4][65];
    __shared__ float invs[64];
    const int b = blockIdx.z, h = blockIdx.y, p0 = blockIdx.x * 64;
    const int bh = b * HH + h;
    const int tid = threadIdx.x;
    const int lr = tid >> 2;
    const int lc = (tid & 3) * 16;
    #pragma unroll
    for (int u = 0; u < 4; ++u) {
        float4 cv = *reinterpret_cast<const float4*>(vcore + (size_t)(bh * CC + lr) * HD_ + lc + u * 4);
        vc[lr][lc + u * 4 + 0] = cv.x; vc[lr][lc + u * 4 + 1] = cv.y;
        vc[lr][lc + u * 4 + 2] = cv.z; vc[lr][lc + u * 4 + 3] = cv.w;
        uint2 araw = *reinterpret_cast<const uint2*>(eaff + ((size_t)(bh * CC + lr)) * PP + p0 + lc + u * 4);
        float2 a01 = __half22float2(*reinterpret_cast<const __half2*>(&araw.x));
        float2 a23 = __half22float2(*reinterpret_cast<const __half2*>(&araw.y));
        ap[lr][lc + u * 4 + 0] = a01.x; ap[lr][lc + u * 4 + 1] = a01.y;
        ap[lr][lc + u * 4 + 2] = a23.x; ap[lr][lc + u * 4 + 3] = a23.y;
    }
    __syncthreads();

    // column sums over c (fixed order; deterministic)
    {
        const int p = tid & 63, qt = tid >> 6;
        float s = 0.0f;
        #pragma unroll
        for (int r = 0; r < 16; ++r) s += ap[qt * 16 + r][p];
        partial[qt][p] = s;
    }
    __syncthreads();
    if (tid < 64)
        invs[tid] = 1.0f / (partial[0][tid] + partial[1][tid] + partial[2][tid] + partial[3][tid]);
    __syncthreads();

    const int pq = (tid >> 4) * 4;
    const int d0 = (tid & 15) * 4;
    float acc[4][4];
    #pragma unroll
    for (int i = 0; i < 4; ++i)
        #pragma unroll
        for (int j = 0; j < 4; ++j) acc[i][j] = 0.0f;
    #pragma unroll 8
    for (int k = 0; k < 64; ++k) {
        float apr[4], vcr[4];
        #pragma unroll
        for (int i = 0; i < 4; ++i) apr[i] = ap[k][pq + i];
        #pragma unroll
        for (int j = 0; j < 4; ++j) vcr[j] = vc[k][d0 + j];
        #pragma unroll
        for (int i = 0; i < 4; ++i)
            #pragma unroll
            for (int j = 0; j < 4; ++j) acc[i][j] = fmaf(apr[i], vcr[j], acc[i][j]);
    }
    #pragma unroll
    for (int i = 0; i < 4; ++i) {
        const float iv = invs[pq + i];
        const int gp = b * PP + p0 + pq + i;
        float4 inp = *reinterpret_cast<const float4*>(input + (size_t)gp * DD + h * HD_ + d0);
        float4 vp = make_float4(acc[i][0] * iv, acc[i][1] * iv, acc[i][2] * iv, acc[i][3] * iv);
        float4 diff = make_float4(inp.x - vp.x, inp.y - vp.y, inp.z - vp.z, inp.w - vp.w);
        const size_t fo = (size_t)gp * FFNIN + h * HD_ + d0;
        cvt_store4(fh + fo, diff);
        cvt_store4(fh + fo + DD, vp);
    }
}

// ---------------- LayerNorm ----------------
__global__ void __launch_bounds__(128) ln_kernel(
    const float* __restrict__ x, const float* __restrict__ gamma,
    const float* __restrict__ beta, float* __restrict__ out)
{
    const float* row = x + (size_t)blockIdx.x * DD;
    const int t = threadIdx.x;
    float4 v = *reinterpret_cast<const float4*>(row + t * 4);
    float s = v.x + v.y + v.z + v.w;
    float sq = v.x * v.x + v.y * v.y + v.z * v.z + v.w * v.w;
    blockReduceSum2(s, sq);
    const float mu = s * (1.0f / DD);
    const float var = sq * (1.0f / DD) - mu * mu;
    const float rstd = rsqrtf(var + 1e-5f);
    float4 g = *reinterpret_cast<const float4*>(gamma + t * 4);
    float4 bt = *reinterpret_cast<const float4*>(beta + t * 4);
    float4 o;
    o.x = (v.x - mu) * rstd * g.x + bt.x;
    o.y = (v.y - mu) * rstd * g.y + bt.y;
    o.z = (v.z - mu) * rstd * g.z + bt.z;
    o.w = (v.w - mu) * rstd * g.w + bt.w;
    *reinterpret_cast<float4*>(out + (size_t)blockIdx.x * DD + t * 4) = o;
}

// ---------------- launch ----------------
extern "C" void kernel_launch(void* const* d_in, const int* in_sizes, int n_in,
                              void* d_out, int out_size)
{
    (void)in_sizes; (void)n_in; (void)out_size;
    const float* input = (const float*)d_in[0];
    const float* cores = (const float*)d_in[1];
    const float* Wv    = (const float*)d_in[2];
    const float* bv    = (const float*)d_in[3];
    const float* W1    = (const float*)d_in[4];
    const float* b1    = (const float*)d_in[5];
    const float* W2    = (const float*)d_in[6];
    const float* b2    = (const float*)d_in[7];
    const float* gamma = (const float*)d_in[8];
    const float* beta  = (const float*)d_in[9];
    float* out = (float*)d_out;

    float *vcore, *vcp, *gpsum, *outp;
    __half *q_h, *eaff, *in_h, *ffn_h, *hid_h, *wvT, *w1T, *w2T;
    cudaGetSymbolAddress((void**)&vcore, g_vcore);
    cudaGetSymbolAddress((void**)&vcp, g_vcp);
    cudaGetSymbolAddress((void**)&gpsum, g_gpsum);
    cudaGetSymbolAddress((void**)&outp, g_outp);
    cudaGetSymbolAddress((void**)&q_h, g_q_h);
    cudaGetSymbolAddress((void**)&eaff, g_eaff);
    cudaGetSymbolAddress((void**)&in_h, g_in_h);
    cudaGetSymbolAddress((void**)&ffn_h, g_ffn_h);
    cudaGetSymbolAddress((void**)&hid_h, g_hid_h);
    cudaGetSymbolAddress((void**)&wvT, g_wvT);
    cudaGetSymbolAddress((void**)&w1T, g_w1T);
    cudaGetSymbolAddress((void**)&w2T, g_w2T);

    cudaFuncSetAttribute(gemm_mma<1>, cudaFuncAttributeMaxDynamicSharedMemorySize, GEMM_SMEM);
    cudaFuncSetAttribute(gemm_mma<2>, cudaFuncAttributeMaxDynamicSharedMemorySize, GEMM_SMEM);
    cudaFuncSetAttribute(gemm_mma<3>, cudaFuncAttributeMaxDynamicSharedMemorySize, GEMM_SMEM);

    // 0. merged prep: input->fp16 + 3 weight transposes (one launch)
    prep_all<<<NCVT_BLK + NWV_BLK + NW1_BLK + NW2_BLK, 256>>>(
        input, in_h, Wv, wvT, W1, w1T, W2, w2T);

    // 1. q = input @ Wv + bv  (fp16 out)
    gemm_mma<3><<<dim3(DD / 128, MM / 128), 256, GEMM_SMEM>>>(
        in_h, wvT, bv, nullptr, nullptr, q_h, DD, DD);
    // 2-5. e=exp(aff) fp16 (+partial p-sums), split vcore (inline cinv), reduce, vpatch(+inline p2c)
    aff_kernel<<<dim3(NPT, HH, BB), 256>>>(q_h, cores, eaff, gpsum);
    vcore_split<<<dim3(HH, BB, NSPLIT), 256>>>(input, eaff, gpsum, vcp);
    vcore_reduce<<<(BB * HH * CC * HD_ / 4 + 255) / 256, 256>>>(vcp, vcore);
    vpatch_ffn_kernel<<<dim3(PP / 64, HH, BB), 256>>>(input, vcore, eaff, ffn_h);
    // 6. hid = gelu(ffn @ W1 + b1)   (fp16 out)
    gemm_mma<1><<<dim3(FFNHID / 128, MM / 128), 256, GEMM_SMEM>>>(
        ffn_h, w1T, b1, nullptr, nullptr, hid_h, FFNHID, FFNIN);
    // 7. outp = input + hid @ W2 + b2
    gemm_mma<2><<<dim3(DD / 128, MM / 128), 256, GEMM_SMEM>>>(
        hid_h, w2T, b2, input, outp, nullptr, DD, FFNHID);
    // 8. LayerNorm
    ln_kernel<<<MM, 128>>>(outp, gamma, beta, out);
}

// round 17
// speedup vs baseline: 1.3063x; 1.1058x over previous
#include <cuda_runtime.h>
#include <cuda_fp16.h>
#include <math.h>
#include <stdint.h>

// ---------------- problem constants ----------------
#define BB      16
#define PP      2048
#define DD      512
#define HH      8
#define CC      64
#define HD_     64
#define MM      (BB * PP)        // 32768
#define FFNIN   1024
#define FFNHID  4096
#define NSPLIT  8                // p-splits for vcore
#define NPT     (PP / 64)        // 32 p-tiles

// ---------------- scratch (device globals; allocation-free) ----------------
__device__ __align__(256) float g_vcore[BB * HH * CC * HD_];
__device__ __align__(256) float g_vcp[NSPLIT * BB * HH * CC * HD_];   // 16 MB partials
__device__ __align__(256) float g_gpsum[NPT * BB * HH * CC];          // per-tile partial p-sums
__device__ __align__(256) float g_outp[MM * DD];

__device__ __align__(256) __half g_q_h[MM * DD];                      // q in fp16
__device__ __align__(256) __half g_eaff[BB * HH * CC * PP];           // exp(aff) in fp16
__device__ __align__(256) __half g_in_h[MM * DD];
__device__ __align__(256) __half g_ffn_h[MM * FFNIN];
__device__ __align__(256) __half g_hid_h[(size_t)MM * FFNHID];
// weights transposed to [N][K] fp16
__device__ __align__(256) __half g_wvT[DD * DD];
__device__ __align__(256) __half g_w1T[FFNHID * FFNIN];
__device__ __align__(256) __half g_w2T[DD * FFNHID];

// ---------------- PTX helpers (sm_80-era instructions only) ----------------
__device__ __forceinline__ uint32_t smem_u32(const void* p) {
    uint32_t a;
    asm("{ .reg .u64 t; cvta.to.shared.u64 t, %1; cvt.u32.u64 %0, t; }" : "=r"(a) : "l"(p));
    return a;
}
__device__ __forceinline__ void cp16(uint32_t s, const void* g) {
    asm volatile("cp.async.cg.shared.global [%0], [%1], 16;" :: "r"(s), "l"(g));
}
__device__ __forceinline__ void ldm_x4(uint32_t* r, uint32_t addr) {
    asm volatile("ldmatrix.sync.aligned.m8n8.x4.shared.b16 {%0,%1,%2,%3}, [%4];"
                 : "=r"(r[0]), "=r"(r[1]), "=r"(r[2]), "=r"(r[3]) : "r"(addr));
}
__device__ __forceinline__ void mma_f16(float* d, const uint32_t* a, const uint32_t* b) {
    asm volatile(
        "mma.sync.aligned.m16n8k16.row.col.f32.f16.f16.f32 "
        "{%0,%1,%2,%3}, {%4,%5,%6,%7}, {%8,%9}, {%0,%1,%2,%3};"
        : "+f"(d[0]), "+f"(d[1]), "+f"(d[2]), "+f"(d[3])
        : "r"(a[0]), "r"(a[1]), "r"(a[2]), "r"(a[3]), "r"(b[0]), "r"(b[1]));
}

__device__ __forceinline__ float gelu_exact(float x) {
    return 0.5f * x * (1.0f + erff(x * 0.7071067811865476f));
}

// ---------------- fp16 GEMM via mma.sync, BM=128 BN=128 BK=64 ----------------
// smem: XOR-swizzled 16B chunks (chunk' = chunk ^ (row & 7)), rows of 128 B,
// conflict-free for both cp.async fills and ldmatrix reads.
// EPI 0: Cf = D + bias                       (fp32 out)
// EPI 1: Ch = half(gelu(D + bias))           (fp16 out)
// EPI 2: Cf = D + bias + resid               (fp32 out)
// EPI 3: Ch = half(D + bias)                 (fp16 out)
#define BKK       64
#define ROW_B     128                       // 64 fp16 = 128 bytes per row
#define TILE_B    (128 * ROW_B)             // 16384
#define STAGE_B   (2 * TILE_B)              // 32768
#define NSTAGE    3
#define GEMM_SMEM (NSTAGE * STAGE_B)        // 98304 (x2 CTAs = 192 KB/SM)

template <int EPI>
__global__ void __launch_bounds__(256, 2) gemm_mma(
    const __half* __restrict__ Ah, const __half* __restrict__ Bh,
    const float* __restrict__ bias, const float* __restrict__ resid,
    float* __restrict__ Cf, __half* __restrict__ Ch,
    int N, int K)
{
    extern __shared__ __align__(256) char smem[];
    const uint32_t sb = smem_u32(smem);

    const int tid = threadIdx.x;
    const int wid = tid >> 5;
    const int lane = tid & 31;
    const int bm = blockIdx.y * 128;
    const int bn = blockIdx.x * 128;
    const int mOff = (wid & 3) * 32;
    const int nOff = (wid >> 2) * 64;

    // ldmatrix per-lane row / column-half selectors
    const int aRow = lane & 15;
    const int aHalf = lane >> 4;            // 0/1: which 16B chunk within the k16 pair
    const int bRow = (lane & 7) + ((lane >> 4) << 3);
    const int bHalf = (lane >> 3) & 1;

    float acc[2][8][4];
    #pragma unroll
    for (int i = 0; i < 2; ++i)
        #pragma unroll
        for (int j = 0; j < 8; ++j)
            #pragma unroll
            for (int k = 0; k < 4; ++k) acc[i][j][k] = 0.0f;

    const int nch = K / BKK;

    // stage loader: 4 chunks of 16B per thread per matrix; swizzled dest
    auto loadStage = [&](int s, int it) {
        const int k0 = it * BKK;
        const uint32_t st = sb + s * STAGE_B;
        #pragma unroll
        for (int i = 0; i < 4; ++i) {
            const int id = tid + i * 256;
            const int r = id >> 3, c = id & 7;
            const uint32_t so = (uint32_t)(r * ROW_B + ((c ^ (r & 7)) * 16));
            cp16(st + so,          Ah + (size_t)(bm + r) * K + k0 + c * 8);
            cp16(st + TILE_B + so, Bh + (size_t)(bn + r) * K + k0 + c * 8);
        }
        asm volatile("cp.async.commit_group;" ::: "memory");
    };

    loadStage(0, 0);
    loadStage(1, 1);

    for (int it = 0; it < nch; ++it) {
        if (it + 1 < nch)
            asm volatile("cp.async.wait_group 1;" ::: "memory");
        else
            asm volatile("cp.async.wait_group 0;" ::: "memory");
        __syncthreads();

        if (it + 2 < nch) loadStage((it + 2) % NSTAGE, it + 2);

        const uint32_t st = sb + (it % NSTAGE) * STAGE_B;
        const uint32_t pAh = st, pBh = st + TILE_B;

        #pragma unroll
        for (int kk = 0; kk < 4; ++kk) {
            uint32_t ah[2][4], b[4][4];
            #pragma unroll
            for (int mf = 0; mf < 2; ++mf) {
                const int row = mOff + mf * 16 + aRow;
                const uint32_t chunk = (uint32_t)((kk * 2 + aHalf) ^ (row & 7));
                ldm_x4(ah[mf], pAh + (uint32_t)(row * ROW_B) + chunk * 16);
            }
            #pragma unroll
            for (int n2 = 0; n2 < 4; ++n2) {
                const int row = nOff + n2 * 16 + bRow;
                const uint32_t chunk = (uint32_t)((kk * 2 + bHalf) ^ (row & 7));
                ldm_x4(b[n2], pBh + (uint32_t)(row * ROW_B) + chunk * 16);
            }
            #pragma unroll
            for (int mf = 0; mf < 2; ++mf)
                #pragma unroll
                for (int nf = 0; nf < 8; ++nf)
                    mma_f16(acc[mf][nf], ah[mf], &b[nf >> 1][(nf & 1) * 2]);
        }
    }

    // ---- epilogue ----
    #pragma unroll
    for (int mf = 0; mf < 2; ++mf) {
        #pragma unroll
        for (int half_ = 0; half_ < 2; ++half_) {
            const int row = bm + mOff + mf * 16 + (lane >> 2) + half_ * 8;
            #pragma unroll
            for (int nf = 0; nf < 8; ++nf) {
                const int col = bn + nOff + nf * 8 + (lane & 3) * 2;
                float v0 = acc[mf][nf][half_ * 2 + 0] + bias[col];
                float v1 = acc[mf][nf][half_ * 2 + 1] + bias[col + 1];
                if (EPI == 1 || EPI == 3) {
                    if (EPI == 1) { v0 = gelu_exact(v0); v1 = gelu_exact(v1); }
                    __half h0 = __float2half_rn(v0);
                    __half h1 = __float2half_rn(v1);
                    uint32_t hp = (uint32_t)__half_as_ushort(h0) |
                                  ((uint32_t)__half_as_ushort(h1) << 16);
                    *reinterpret_cast<uint32_t*>(Ch + (size_t)row * N + col) = hp;
                } else {
                    if (EPI == 2) {
                        const float* rp = resid + (size_t)row * N + col;
                        v0 += rp[0];
                        v1 += rp[1];
                    }
                    *reinterpret_cast<float2*>(Cf + (size_t)row * N + col) = make_float2(v0, v1);
                }
            }
        }
    }
}

// ---------------- merged prep: cvt(input->fp16) + 3 weight transposes ----------------
#define NCVT_BLK   (MM * DD / 4 / 256)                 // 16384
#define NWV_BLK    ((DD / 32) * (DD / 32))             // 256
#define NW1_BLK    ((FFNHID / 32) * (FFNIN / 32))      // 4096
#define NW2_BLK    ((DD / 32) * (FFNHID / 32))         // 2048

__device__ __forceinline__ void transpose_tile(
    const float* __restrict__ W, __half* __restrict__ Th,
    int K, int N, int bx, int by, float (*s)[33])
{
    const int n0 = bx * 32, k0 = by * 32;
    const int c = threadIdx.x & 31, r0 = threadIdx.x >> 5;
    #pragma unroll
    for (int r = r0; r < 32; r += 8)
        s[r][c] = W[(size_t)(k0 + r) * N + n0 + c];
    __syncthreads();
    #pragma unroll
    for (int r = r0; r < 32; r += 8)
        Th[(size_t)(n0 + r) * K + k0 + c] = __float2half_rn(s[c][r]);
}

__global__ void __launch_bounds__(256) prep_all(
    const float* __restrict__ input, __half* __restrict__ in_h,
    const float* __restrict__ Wv, __half* __restrict__ wvT,
    const float* __restrict__ W1, __half* __restrict__ w1T,
    const float* __restrict__ W2, __half* __restrict__ w2T)
{
    __shared__ float s[32][33];
    int blk = blockIdx.x;
    if (blk < NCVT_BLK) {
        int i = blk * 256 + threadIdx.x;
        float4 v = reinterpret_cast<const float4*>(input)[i];
        __half hb[4] = {__float2half_rn(v.x), __float2half_rn(v.y),
                        __float2half_rn(v.z), __float2half_rn(v.w)};
        reinterpret_cast<uint2*>(in_h)[i] = *reinterpret_cast<const uint2*>(hb);
        return;
    }
    blk -= NCVT_BLK;
    if (blk < NWV_BLK) {
        transpose_tile(Wv, wvT, DD, DD, blk % (DD / 32), blk / (DD / 32), s);
        return;
    }
    blk -= NWV_BLK;
    if (blk < NW1_BLK) {
        transpose_tile(W1, w1T, FFNIN, FFNHID, blk % (FFNHID / 32), blk / (FFNHID / 32), s);
        return;
    }
    blk -= NW1_BLK;
    transpose_tile(W2, w2T, FFNHID, DD, blk % (DD / 32), blk / (DD / 32), s);
}

// ---------------- block reduce helper (for LN) ----------------
__device__ __forceinline__ void blockReduceSum2(float& a, float& b) {
    __shared__ float sa[8], sb[8];
    #pragma unroll
    for (int o = 16; o > 0; o >>= 1) {
        a += __shfl_xor_sync(0xffffffffu, a, o);
        b += __shfl_xor_sync(0xffffffffu, b, o);
    }
    int wid = threadIdx.x >> 5, nw = blockDim.x >> 5;
    if ((threadIdx.x & 31) == 0) { sa[wid] = a; sb[wid] = b; }
    __syncthreads();
    float ra = 0.0f, rb = 0.0f;
    for (int i = 0; i < nw; ++i) { ra += sa[i]; rb += sb[i]; }
    __syncthreads();
    a = ra; b = rb;
}

// ---------------- aff: e = exp(q.cores/8) fp16 out, + partial p-sums ----------------
__global__ void __launch_bounds__(256) aff_kernel(
    const __half* __restrict__ q, const float* __restrict__ cores,
    __half* __restrict__ eaff, float* __restrict__ gpsum)
{
    __shared__ float cs[64][65];
    __shared__ float qs[64][65];
    __shared__ float psmem[64][17];
    const int b = blockIdx.z, h = blockIdx.y, p0 = blockIdx.x * 64;
    const int tid = threadIdx.x;
    const int lr = tid >> 2;
    const int lc = (tid & 3) * 16;
    #pragma unroll
    for (int u = 0; u < 4; ++u) {
        float4 cv = *reinterpret_cast<const float4*>(cores + (size_t)(h * CC + lr) * HD_ + lc + u * 4);
        cs[lr][lc + u * 4 + 0] = cv.x; cs[lr][lc + u * 4 + 1] = cv.y;
        cs[lr][lc + u * 4 + 2] = cv.z; cs[lr][lc + u * 4 + 3] = cv.w;
        uint2 qraw = *reinterpret_cast<const uint2*>(q + (size_t)(b * PP + p0 + lr) * DD + h * HD_ + lc + u * 4);
        float2 q01 = __half22float2(*reinterpret_cast<const __half2*>(&qraw.x));
        float2 q23 = __half22float2(*reinterpret_cast<const __half2*>(&qraw.y));
        qs[lr][lc + u * 4 + 0] = q01.x; qs[lr][lc + u * 4 + 1] = q01.y;
        qs[lr][lc + u * 4 + 2] = q23.x; qs[lr][lc + u * 4 + 3] = q23.y;
    }
    __syncthreads();
    const int c0 = (tid & 15) * 4;
    const int pq = (tid >> 4) * 4;
    float acc[4][4];
    #pragma unroll
    for (int i = 0; i < 4; ++i)
        #pragma unroll
        for (int j = 0; j < 4; ++j) acc[i][j] = 0.0f;
    #pragma unroll 8
    for (int k = 0; k < 64; ++k) {
        float cr[4], pr[4];
        #pragma unroll
        for (int i = 0; i < 4; ++i) cr[i] = cs[c0 + i][k];
        #pragma unroll
        for (int j = 0; j < 4; ++j) pr[j] = qs[pq + j][k];
        #pragma unroll
        for (int i = 0; i < 4; ++i)
            #pragma unroll
            for (int j = 0; j < 4; ++j) acc[i][j] = fmaf(cr[i], pr[j], acc[i][j]);
    }
    #pragma unroll
    for (int i = 0; i < 4; ++i) {
        float ps = 0.0f;
        #pragma unroll
        for (int j = 0; j < 4; ++j) { acc[i][j] = __expf(acc[i][j] * 0.125f); ps += acc[i][j]; }
        psmem[c0 + i][tid >> 4] = ps;
    }

    const int bh = b * HH + h;
    const size_t base = (size_t)bh * CC * PP;
    #pragma unroll
    for (int i = 0; i < 4; ++i) {
        __half hb[4] = {__float2half_rn(acc[i][0]), __float2half_rn(acc[i][1]),
                        __float2half_rn(acc[i][2]), __float2half_rn(acc[i][3])};
        *reinterpret_cast<uint2*>(eaff + base + (size_t)(c0 + i) * PP + p0 + pq) =
            *reinterpret_cast<const uint2*>(hb);
    }

    __syncthreads();
    if (tid < 64) {
        float s = 0.0f;
        #pragma unroll
        for (int g = 0; g < 16; ++g) s += psmem[tid][g];
        gpsum[(size_t)blockIdx.x * (BB * HH * CC) + bh * CC + tid] = s;
    }
}

// ---------------- v_core split over p (reads e fp16, computes cinv inline) ----------------
__global__ void __launch_bounds__(256) vcore_split(
    const float* __restrict__ input, const __half* __restrict__ eaff,
    const float* __restrict__ gpsum, float* __restrict__ vcp)
{
    __shared__ float asT[64][68];
    __shared__ float vs[64][68];
    const int h = blockIdx.x, b = blockIdx.y, pz = blockIdx.z;
    const int bh = b * HH + h;
    const int p0 = pz * (PP / NSPLIT);
    const __half* abase = eaff + (size_t)bh * CC * PP;
    const int tid = threadIdx.x;
    const int lr = tid >> 2;
    const int lc = (tid & 3) * 16;
    const int c0 = (tid & 15) * 4;
    const int d0 = (tid >> 4) * 4;

    // cinv for row lr: fixed-order sum of NPT partials
    float rs = 0.0f;
    #pragma unroll
    for (int z = 0; z < NPT; ++z) rs += gpsum[(size_t)z * (BB * HH * CC) + bh * CC + lr];
    const float irow = 1.0f / rs;

    float acc[4][4];
    #pragma unroll
    for (int i = 0; i < 4; ++i)
        #pragma unroll
        for (int j = 0; j < 4; ++j) acc[i][j] = 0.0f;

    for (int pt = p0; pt < p0 + PP / NSPLIT; pt += 64) {
        #pragma unroll
        for (int u = 0; u < 4; ++u) {
            uint2 araw = *reinterpret_cast<const uint2*>(abase + (size_t)lr * PP + pt + lc + u * 4);
            float2 a01 = __half22float2(*reinterpret_cast<const __half2*>(&araw.x));
            float2 a23 = __half22float2(*reinterpret_cast<const __half2*>(&araw.y));
            asT[lc + u * 4 + 0][lr] = a01.x * irow;
            asT[lc + u * 4 + 1][lr] = a01.y * irow;
            asT[lc + u * 4 + 2][lr] = a23.x * irow;
            asT[lc + u * 4 + 3][lr] = a23.y * irow;
            float4 vv = *reinterpret_cast<const float4*>(input + (size_t)(b * PP + pt + lr) * DD + h * HD_ + lc + u * 4);
            *reinterpret_cast<float4*>(&vs[lr][lc + u * 4]) = vv;
        }
        __syncthreads();
        #pragma unroll 16
        for (int k = 0; k < 64; ++k) {
            float4 ar = *reinterpret_cast<const float4*>(&asT[k][c0]);
            float4 vr = *reinterpret_cast<const float4*>(&vs[k][d0]);
            float arr[4] = {ar.x, ar.y, ar.z, ar.w};
            float vrr[4] = {vr.x, vr.y, vr.z, vr.w};
            #pragma unroll
            for (int i = 0; i < 4; ++i)
                #pragma unroll
                for (int j = 0; j < 4; ++j) acc[i][j] = fmaf(arr[i], vrr[j], acc[i][j]);
        }
        __syncthreads();
    }
    float* dst = vcp + (size_t)pz * (BB * HH * CC * HD_);
    #pragma unroll
    for (int i = 0; i < 4; ++i) {
        float4 o = make_float4(acc[i][0], acc[i][1], acc[i][2], acc[i][3]);
        *reinterpret_cast<float4*>(dst + (size_t)(bh * CC + c0 + i) * HD_ + d0) = o;
    }
}

// ---------------- v_core reduce ----------------
__global__ void __launch_bounds__(256) vcore_reduce(
    const float* __restrict__ vcp, float* __restrict__ vcore)
{
    const int n4 = BB * HH * CC * HD_ / 4;
    int i = blockIdx.x * 256 + threadIdx.x;
    if (i >= n4) return;
    float4 s = reinterpret_cast<const float4*>(vcp)[i];
    #pragma unroll
    for (int z = 1; z < NSPLIT; ++z) {
        float4 v = reinterpret_cast<const float4*>(vcp + (size_t)z * (BB * HH * CC * HD_))[i];
        s.x += v.x; s.y += v.y; s.z += v.z; s.w += v.w;
    }
    reinterpret_cast<float4*>(vcore)[i] = s;
}

// ---------------- v_patch + inline p2c softmax + ffn concat ----------------
__device__ __forceinline__ void cvt_store4(__half* ph, float4 v) {
    __half hb[4] = {__float2half_rn(v.x), __float2half_rn(v.y),
                    __float2half_rn(v.z), __float2half_rn(v.w)};
    *reinterpret_cast<uint2*>(ph) = *reinterpret_cast<const uint2*>(hb);
}

__global__ void __launch_bounds__(256) vpatch_ffn_kernel(
    const float* __restrict__ input, const float* __restrict__ vcore,
    const __half* __restrict__ eaff, __half* __restrict__ fh)
{
    __shared__ float vc[64][65];
    __shared__ float ap[64][65];
    __shared__ float partial[4][65];
    __shared__ float invs[64];
    const int b = blockIdx.z, h = blockIdx.y, p0 = blockIdx.x * 64;
    const int bh = b * HH + h;
    const int tid = threadIdx.x;
    const int lr = tid >> 2;
    const int lc = (tid & 3) * 16;
    #pragma unroll
    for (int u = 0; u < 4; ++u) {
        float4 cv = *reinterpret_cast<const float4*>(vcore + (size_t)(bh * CC + lr) * HD_ + lc + u * 4);
        vc[lr][lc + u * 4 + 0] = cv.x; vc[lr][lc + u * 4 + 1] = cv.y;
        vc[lr][lc + u * 4 + 2] = cv.z; vc[lr][lc + u * 4 + 3] = cv.w;
        uint2 araw = *reinterpret_cast<const uint2*>(eaff + ((size_t)(bh * CC + lr)) * PP + p0 + lc + u * 4);
        float2 a01 = __half22float2(*reinterpret_cast<const __half2*>(&araw.x));
        float2 a23 = __half22float2(*reinterpret_cast<const __half2*>(&araw.y));
        ap[lr][lc + u * 4 + 0] = a01.x; ap[lr][lc + u * 4 + 1] = a01.y;
        ap[lr][lc + u * 4 + 2] = a23.x; ap[lr][lc + u * 4 + 3] = a23.y;
    }
    __syncthreads();

    // column sums over c (fixed order; deterministic)
    {
        const int p = tid & 63, qt = tid >> 6;
        float s = 0.0f;
        #pragma unroll
        for (int r = 0; r < 16; ++r) s += ap[qt * 16 + r][p];
        partial[qt][p] = s;
    }
    __syncthreads();
    if (tid < 64)
        invs[tid] = 1.0f / (partial[0][tid] + partial[1][tid] + partial[2][tid] + partial[3][tid]);
    __syncthreads();

    const int pq = (tid >> 4) * 4;
    const int d0 = (tid & 15) * 4;
    float acc[4][4];
    #pragma unroll
    for (int i = 0; i < 4; ++i)
        #pragma unroll
        for (int j = 0; j < 4; ++j) acc[i][j] = 0.0f;
    #pragma unroll 8
    for (int k = 0; k < 64; ++k) {
        float apr[4], vcr[4];
        #pragma unroll
        for (int i = 0; i < 4; ++i) apr[i] = ap[k][pq + i];
        #pragma unroll
        for (int j = 0; j < 4; ++j) vcr[j] = vc[k][d0 + j];
        #pragma unroll
        for (int i = 0; i < 4; ++i)
            #pragma unroll
            for (int j = 0; j < 4; ++j) acc[i][j] = fmaf(apr[i], vcr[j], acc[i][j]);
    }
    #pragma unroll
    for (int i = 0; i < 4; ++i) {
        const float iv = invs[pq + i];
        const int gp = b * PP + p0 + pq + i;
        float4 inp = *reinterpret_cast<const float4*>(input + (size_t)gp * DD + h * HD_ + d0);
        float4 vp = make_float4(acc[i][0] * iv, acc[i][1] * iv, acc[i][2] * iv, acc[i][3] * iv);
        float4 diff = make_float4(inp.x - vp.x, inp.y - vp.y, inp.z - vp.z, inp.w - vp.w);
        const size_t fo = (size_t)gp * FFNIN + h * HD_ + d0;
        cvt_store4(fh + fo, diff);
        cvt_store4(fh + fo + DD, vp);
    }
}

// ---------------- LayerNorm ----------------
__global__ void __launch_bounds__(128) ln_kernel(
    const float* __restrict__ x, const float* __restrict__ gamma,
    const float* __restrict__ beta, float* __restrict__ out)
{
    const float* row = x + (size_t)blockIdx.x * DD;
    const int t = threadIdx.x;
    float4 v = *reinterpret_cast<const float4*>(row + t * 4);
    float s = v.x + v.y + v.z + v.w;
    float sq = v.x * v.x + v.y * v.y + v.z * v.z + v.w * v.w;
    blockReduceSum2(s, sq);
    const float mu = s * (1.0f / DD);
    const float var = sq * (1.0f / DD) - mu * mu;
    const float rstd = rsqrtf(var + 1e-5f);
    float4 g = *reinterpret_cast<const float4*>(gamma + t * 4);
    float4 bt = *reinterpret_cast<const float4*>(beta + t * 4);
    float4 o;
    o.x = (v.x - mu) * rstd * g.x + bt.x;
    o.y = (v.y - mu) * rstd * g.y + bt.y;
    o.z = (v.z - mu) * rstd * g.z + bt.z;
    o.w = (v.w - mu) * rstd * g.w + bt.w;
    *reinterpret_cast<float4*>(out + (size_t)blockIdx.x * DD + t * 4) = o;
}

// ---------------- launch ----------------
extern "C" void kernel_launch(void* const* d_in, const int* in_sizes, int n_in,
                              void* d_out, int out_size)
{
    (void)in_sizes; (void)n_in; (void)out_size;
    const float* input = (const float*)d_in[0];
    const float* cores = (const float*)d_in[1];
    const float* Wv    = (const float*)d_in[2];
    const float* bv    = (const float*)d_in[3];
    const float* W1    = (const float*)d_in[4];
    const float* b1    = (const float*)d_in[5];
    const float* W2    = (const float*)d_in[6];
    const float* b2    = (const float*)d_in[7];
    const float* gamma = (const float*)d_in[8];
    const float* beta  = (const float*)d_in[9];
    float* out = (float*)d_out;

    float *vcore, *vcp, *gpsum, *outp;
    __half *q_h, *eaff, *in_h, *ffn_h, *hid_h, *wvT, *w1T, *w2T;
    cudaGetSymbolAddress((void**)&vcore, g_vcore);
    cudaGetSymbolAddress((void**)&vcp, g_vcp);
    cudaGetSymbolAddress((void**)&gpsum, g_gpsum);
    cudaGetSymbolAddress((void**)&outp, g_outp);
    cudaGetSymbolAddress((void**)&q_h, g_q_h);
    cudaGetSymbolAddress((void**)&eaff, g_eaff);
    cudaGetSymbolAddress((void**)&in_h, g_in_h);
    cudaGetSymbolAddress((void**)&ffn_h, g_ffn_h);
    cudaGetSymbolAddress((void**)&hid_h, g_hid_h);
    cudaGetSymbolAddress((void**)&wvT, g_wvT);
    cudaGetSymbolAddress((void**)&w1T, g_w1T);
    cudaGetSymbolAddress((void**)&w2T, g_w2T);

    cudaFuncSetAttribute(gemm_mma<1>, cudaFuncAttributeMaxDynamicSharedMemorySize, GEMM_SMEM);
    cudaFuncSetAttribute(gemm_mma<2>, cudaFuncAttributeMaxDynamicSharedMemorySize, GEMM_SMEM);
    cudaFuncSetAttribute(gemm_mma<3>, cudaFuncAttributeMaxDynamicSharedMemorySize, GEMM_SMEM);

    // 0. merged prep: input->fp16 + 3 weight transposes (one launch)
    prep_all<<<NCVT_BLK + NWV_BLK + NW1_BLK + NW2_BLK, 256>>>(
        input, in_h, Wv, wvT, W1, w1T, W2, w2T);

    // 1. q = input @ Wv + bv  (fp16 out)
    gemm_mma<3><<<dim3(DD / 128, MM / 128), 256, GEMM_SMEM>>>(
        in_h, wvT, bv, nullptr, nullptr, q_h, DD, DD);
    // 2-5. e=exp(aff) fp16 (+partial p-sums), split vcore (inline cinv), reduce, vpatch(+inline p2c)
    aff_kernel<<<dim3(NPT, HH, BB), 256>>>(q_h, cores, eaff, gpsum);
    vcore_split<<<dim3(HH, BB, NSPLIT), 256>>>(input, eaff, gpsum, vcp);
    vcore_reduce<<<(BB * HH * CC * HD_ / 4 + 255) / 256, 256>>>(vcp, vcore);
    vpatch_ffn_kernel<<<dim3(PP / 64, HH, BB), 256>>>(input, vcore, eaff, ffn_h);
    // 6. hid = gelu(ffn @ W1 + b1)   (fp16 out)
    gemm_mma<1><<<dim3(FFNHID / 128, MM / 128), 256, GEMM_SMEM>>>(
        ffn_h, w1T, b1, nullptr, nullptr, hid_h, FFNHID, FFNIN);
    // 7. outp = input + hid @ W2 + b2
    gemm_mma<2><<<dim3(DD / 128, MM / 128), 256, GEMM_SMEM>>>(
        hid_h, w2T, b2, input, outp, nullptr, DD, FFNHID);
    // 8. LayerNorm
    ln_kernel<<<MM, 128>>>(outp, gamma, beta, out);
}